// round 1
// baseline (speedup 1.0000x reference)
#include <cuda_runtime.h>
#include <math.h>

#define Bc 32
#define Tc 128
#define Mc 1290
#define Cc 512
#define Hc 8
#define Dh 64
#define NBLK 4
#define TOPK 8
#define QT 16

static __device__ float d_inp[Bc*Tc*Cc];
static __device__ float d_mem[(size_t)Bc*Mc*Cc];
static __device__ float d_qb [(size_t)Bc*Mc*Cc];
static __device__ float d_kb [(size_t)Bc*Mc*Cc];
static __device__ float d_vb [(size_t)Bc*Mc*Cc];
static __device__ float d_ao [(size_t)Bc*Mc*Cc];
static __device__ float d_h1 [(size_t)Bc*Mc*Cc];
static __device__ float d_h2 [(size_t)Bc*Mc*Cc];
static __device__ float d_t0 [(size_t)Bc*Mc*Cc];
static __device__ float d_gt [(size_t)Bc*Mc*2*Cc];
static __device__ float d_rm [Bc*Cc];
static __device__ float d_gi [Bc*2*Cc];

#define F_INF __int_as_float(0x7f800000)

// ---------------- GEMM: out[N,NO] = A[N,K] @ W[K,NO] + bias (+relu) ----------------
__global__ __launch_bounds__(256) void gemm_kernel(
    const float* __restrict__ A, const float* __restrict__ W,
    const float* __restrict__ bias, float* __restrict__ out,
    int N, int K, int NO, int relu)
{
    __shared__ float As[16][64];
    __shared__ float Bs[16][64];
    int t  = threadIdx.x;
    int tx = t & 15, ty = t >> 4;
    int row0 = blockIdx.y * 64;
    int col0 = blockIdx.x * 64;
    float acc[4][4] = {};
    for (int k0 = 0; k0 < K; k0 += 16) {
        {
            int r = t >> 2;            // 0..63
            int c4 = (t & 3) * 4;      // 0,4,8,12
            float4 av = make_float4(0.f,0.f,0.f,0.f);
            if (row0 + r < N)
                av = *reinterpret_cast<const float4*>(A + (size_t)(row0 + r) * K + k0 + c4);
            As[c4+0][r] = av.x; As[c4+1][r] = av.y; As[c4+2][r] = av.z; As[c4+3][r] = av.w;
        }
        {
            int r  = t >> 4;           // 0..15 (k)
            int c4 = (t & 15) * 4;
            float4 bv = *reinterpret_cast<const float4*>(W + (size_t)(k0 + r) * NO + col0 + c4);
            *reinterpret_cast<float4*>(&Bs[r][c4]) = bv;
        }
        __syncthreads();
        #pragma unroll
        for (int kk = 0; kk < 16; kk++) {
            float4 a4 = *reinterpret_cast<const float4*>(&As[kk][ty*4]);
            float4 b4 = *reinterpret_cast<const float4*>(&Bs[kk][tx*4]);
            float a[4] = {a4.x,a4.y,a4.z,a4.w};
            float b[4] = {b4.x,b4.y,b4.z,b4.w};
            #pragma unroll
            for (int i=0;i<4;i++)
                #pragma unroll
                for (int j=0;j<4;j++) acc[i][j] += a[i]*b[j];
        }
        __syncthreads();
    }
    float4 bb = *reinterpret_cast<const float4*>(bias + col0 + tx*4);
    #pragma unroll
    for (int i=0;i<4;i++) {
        int r = row0 + ty*4 + i;
        if (r >= N) continue;
        float4 o4;
        o4.x = acc[i][0] + bb.x; o4.y = acc[i][1] + bb.y;
        o4.z = acc[i][2] + bb.z; o4.w = acc[i][3] + bb.w;
        if (relu) {
            o4.x = fmaxf(o4.x,0.f); o4.y = fmaxf(o4.y,0.f);
            o4.z = fmaxf(o4.z,0.f); o4.w = fmaxf(o4.w,0.f);
        }
        *reinterpret_cast<float4*>(out + (size_t)r * NO + col0 + tx*4) = o4;
    }
}

// ---------------- block reductions (128 threads) ----------------
__device__ __forceinline__ float warpMax(float v){
    #pragma unroll
    for (int o=16;o;o>>=1) v = fmaxf(v, __shfl_xor_sync(0xffffffffu, v, o));
    return v;
}
__device__ __forceinline__ float warpSum(float v){
    #pragma unroll
    for (int o=16;o;o>>=1) v += __shfl_xor_sync(0xffffffffu, v, o);
    return v;
}
__device__ __forceinline__ float blockMax128(float v, float* red){
    v = warpMax(v);
    int w = threadIdx.x >> 5;
    if ((threadIdx.x & 31) == 0) red[w] = v;
    __syncthreads();
    float r = fmaxf(fmaxf(red[0],red[1]), fmaxf(red[2],red[3]));
    __syncthreads();
    return r;
}
__device__ __forceinline__ float blockSum128(float v, float* red){
    v = warpSum(v);
    int w = threadIdx.x >> 5;
    if ((threadIdx.x & 31) == 0) red[w] = v;
    __syncthreads();
    float r = red[0]+red[1]+red[2]+red[3];
    __syncthreads();
    return r;
}

// ---------------- top-k attention (block loop): q[B,M,C], k/v[B,T,C] -> o[B,M,C] ----------------
#define SMEM_TOPK ((64*128 + 128*64 + 64 + 128 + 32)*4)
__global__ __launch_bounds__(128) void attn_topk_kernel(
    const float* __restrict__ q, const float* __restrict__ k,
    const float* __restrict__ v, float* __restrict__ o)
{
    extern __shared__ float sm[];
    float* Kt  = sm;              // [64][128] transposed
    float* Vs  = Kt + 64*128;     // [128][64]
    float* sq  = Vs + 128*64;     // [64]
    float* sc  = sq + 64;         // [128]
    float* red = sc + 128;        // [32]

    int tid = threadIdx.x;
    int bh = blockIdx.x, b = bh / Hc, h = bh % Hc;

    for (int idx = tid; idx < 128*16; idx += 128) {
        int t = idx >> 4, j = idx & 15;
        size_t row = ((size_t)b*Tc + t)*Cc + h*64 + j*4;
        float4 kv = *reinterpret_cast<const float4*>(k + row);
        float4 vv = *reinterpret_cast<const float4*>(v + row);
        Kt[(j*4+0)*128 + t] = kv.x;
        Kt[(j*4+1)*128 + t] = kv.y;
        Kt[(j*4+2)*128 + t] = kv.z;
        Kt[(j*4+3)*128 + t] = kv.w;
        *reinterpret_cast<float4*>(&Vs[t*64 + j*4]) = vv;
    }
    __syncthreads();

    const float scale = 0.125f;
    int q0 = blockIdx.y * 129;
    int qend = min(q0 + 129, Mc);
    for (int qi = q0; qi < qend; qi++) {
        if (tid < 16) {
            float4 qv = *reinterpret_cast<const float4*>(q + ((size_t)b*Mc + qi)*Cc + h*64 + tid*4);
            *reinterpret_cast<float4*>(&sq[tid*4]) = qv;
        }
        __syncthreads();
        float sv = 0.f;
        #pragma unroll 8
        for (int d=0; d<64; d++) sv += sq[d]*Kt[d*128 + tid];
        sv *= scale;
        // iterative max -> 8th-largest threshold (values assumed distinct)
        float thr = F_INF, gmax = 0.f;
        #pragma unroll
        for (int it=0; it<TOPK; it++) {
            float cand = (sv < thr) ? sv : -F_INF;
            float mx = blockMax128(cand, red);
            if (it == 0) gmax = mx;
            thr = mx;
        }
        // softmax over ALL keys; mask (no renorm) per reference
        float e = expf(sv - gmax);
        float denom = blockSum128(e, red);
        sc[tid] = (sv >= thr) ? e / denom : 0.f;
        __syncthreads();
        if (tid < 64) {
            float acc = 0.f;
            #pragma unroll 8
            for (int t=0;t<128;t++) acc += sc[t]*Vs[t*64 + tid];
            o[((size_t)b*Mc + qi)*Cc + h*64 + tid] = acc;
        }
        __syncthreads();
    }
}

// ---------------- hx attention: q[B,T,C], k/v[B,M,C] -> o[B,T,C], online softmax ----------------
#define SMEM_HX ((64*128 + 128*64 + QT*64 + QT*128 + QT*64 + QT + QT + 32)*4)
__global__ __launch_bounds__(128) void attn_hx_kernel(
    const float* __restrict__ q, const float* __restrict__ k,
    const float* __restrict__ v, float* __restrict__ o)
{
    extern __shared__ float sm[];
    float* Kt   = sm;               // [64][128]
    float* Vs   = Kt + 64*128;      // [128][64]
    float* sq   = Vs + 128*64;      // [QT][64]
    float* sc   = sq + QT*64;       // [QT][128]
    float* oa   = sc + QT*128;      // [QT][64]
    float* smm  = oa + QT*64;       // [QT]
    float* sden = smm + QT;         // [QT]
    float* red  = sden + QT;        // [32]

    int tid = threadIdx.x;
    int bh = blockIdx.x, b = bh / Hc, h = bh % Hc;
    int q0 = blockIdx.y * QT;

    for (int idx = tid; idx < QT*16; idx += 128) {
        int qi = idx >> 4, j = idx & 15;
        float4 qv = *reinterpret_cast<const float4*>(q + ((size_t)b*Tc + q0 + qi)*Cc + h*64 + j*4);
        *reinterpret_cast<float4*>(&sq[qi*64 + j*4]) = qv;
    }
    for (int idx = tid; idx < QT*64; idx += 128) oa[idx] = 0.f;
    if (tid < QT) { smm[tid] = -F_INF; sden[tid] = 0.f; }
    __syncthreads();

    const float scale = 0.125f;
    for (int c0 = 0; c0 < Mc; c0 += 128) {
        int nk = min(128, Mc - c0);
        for (int idx = tid; idx < 128*16; idx += 128) {
            int t = idx >> 4, j = idx & 15;
            float4 kv = make_float4(0.f,0.f,0.f,0.f), vv = kv;
            if (t < nk) {
                size_t row = ((size_t)b*Mc + c0 + t)*Cc + h*64 + j*4;
                kv = *reinterpret_cast<const float4*>(k + row);
                vv = *reinterpret_cast<const float4*>(v + row);
            }
            Kt[(j*4+0)*128 + t] = kv.x;
            Kt[(j*4+1)*128 + t] = kv.y;
            Kt[(j*4+2)*128 + t] = kv.z;
            Kt[(j*4+3)*128 + t] = kv.w;
            *reinterpret_cast<float4*>(&Vs[t*64 + j*4]) = vv;
        }
        __syncthreads();

        float s[QT];
        #pragma unroll
        for (int qi=0; qi<QT; qi++) s[qi] = 0.f;
        #pragma unroll 4
        for (int d=0; d<64; d++) {
            float kd = Kt[d*128 + tid];
            #pragma unroll
            for (int qi=0; qi<QT; qi++) s[qi] += sq[qi*64 + d]*kd;
        }

        for (int qi=0; qi<QT; qi++) {
            float sv = (tid < nk) ? s[qi]*scale : -F_INF;
            float mold = smm[qi];
            float mc = blockMax128(sv, red);
            float newm = fmaxf(mold, mc);
            float e = (tid < nk) ? expf(sv - newm) : 0.f;
            float ssum = blockSum128(e, red);
            sc[qi*128 + tid] = e;
            float f = expf(mold - newm);
            if (tid == 0) { sden[qi] = sden[qi]*f + ssum; smm[qi] = newm; }
            __syncthreads();
            if (tid < 64) {
                float acc = oa[qi*64 + tid]*f;
                #pragma unroll 8
                for (int t=0;t<128;t++) acc += sc[qi*128 + t]*Vs[t*64 + tid];
                oa[qi*64 + tid] = acc;
            }
            __syncthreads();
        }
    }
    for (int idx = tid; idx < QT*64; idx += 128) {
        int qi = idx >> 6, d = idx & 63;
        o[((size_t)b*Tc + q0 + qi)*Cc + h*64 + d] = oa[qi*64 + d] / sden[qi];
    }
}

// ---------------- add + layernorm: out = LN(x + r)*g + b, row len 512, warp/row ----------------
__global__ __launch_bounds__(256) void add_ln_kernel(
    const float* __restrict__ x, const float* __restrict__ r,
    const float* __restrict__ g, const float* __restrict__ bb,
    float* __restrict__ out, int nrows)
{
    int warp = (blockIdx.x * blockDim.x + threadIdx.x) >> 5;
    int lane = threadIdx.x & 31;
    if (warp >= nrows) return;
    const float* xr = x + (size_t)warp * Cc;
    const float* rr = r + (size_t)warp * Cc;
    float vals[16];
    float s = 0.f;
    #pragma unroll
    for (int i=0;i<16;i++) { float vv = xr[lane + i*32] + rr[lane + i*32]; vals[i] = vv; s += vv; }
    #pragma unroll
    for (int o2=16;o2;o2>>=1) s += __shfl_xor_sync(0xffffffffu, s, o2);
    float mu = s * (1.f/512.f);
    float vs = 0.f;
    #pragma unroll
    for (int i=0;i<16;i++){ float d = vals[i]-mu; vs += d*d; }
    #pragma unroll
    for (int o2=16;o2;o2>>=1) vs += __shfl_xor_sync(0xffffffffu, vs, o2);
    float rstd = rsqrtf(vs*(1.f/512.f) + 1e-5f);
    float* outr = out + (size_t)warp * Cc;
    #pragma unroll
    for (int i=0;i<16;i++){ int cc = lane + i*32; outr[cc] = (vals[i]-mu)*rstd*g[cc] + bb[cc]; }
}

// ---------------- misc elementwise ----------------
__global__ void repmean_kernel(const float* __restrict__ inp, const float* __restrict__ rep_w,
                               float* __restrict__ out)
{
    int b = blockIdx.x, c = threadIdx.x;
    const float* base = inp + (size_t)b*Tc*Cc + c;
    float rw = rep_w[c];
    float s = 0.f;
    for (int t=0;t<Tc;t++) s += fmaxf(rw * base[(size_t)t*Cc], 0.f);
    out[b*Cc + c] = s * (1.f/Tc);
}

__global__ void tanh_kernel(const float* __restrict__ in, float* __restrict__ o, size_t n)
{
    size_t i = (size_t)blockIdx.x*blockDim.x + threadIdx.x;
    size_t st = (size_t)gridDim.x*blockDim.x;
    for (; i < n; i += st) o[i] = tanhf(in[i]);
}

__global__ void gate_kernel(const float* __restrict__ gates, const float* __restrict__ gi,
                            const float* __restrict__ mem_final, const float* __restrict__ mem0,
                            const float* __restrict__ ib, const float* __restrict__ fb,
                            float* __restrict__ nm)
{
    size_t n = (size_t)Bc*Mc*Cc;
    size_t i = (size_t)blockIdx.x*blockDim.x + threadIdx.x;
    size_t st = (size_t)gridDim.x*blockDim.x;
    float ibv = ib[0], fbv = fb[0];
    for (; i < n; i += st) {
        int c = (int)(i % Cc);
        size_t bm = i / Cc;
        int b = (int)(bm / Mc);
        float gI = gates[bm*2*Cc + c]      + gi[b*2*Cc + c]      + ibv;
        float gF = gates[bm*2*Cc + Cc + c] + gi[b*2*Cc + Cc + c] + fbv;
        float igv = 1.f/(1.f + expf(-gI));
        float fgv = 1.f/(1.f + expf(-gF));
        nm[i] = igv * tanhf(mem_final[i]) + fgv * mem0[i];
    }
}

// ---------------- launch ----------------
extern "C" void kernel_launch(void* const* d_in, const int* in_sizes, int n_in,
                              void* d_out, int out_size)
{
    const float* ipts   = (const float*)d_in[0];
    const float* memory = (const float*)d_in[1];
    const float* Wq=(const float*)d_in[2],  *bq=(const float*)d_in[3];
    const float* Wk=(const float*)d_in[4],  *bk=(const float*)d_in[5];
    const float* Wv=(const float*)d_in[6],  *bv=(const float*)d_in[7];
    const float* Wm=(const float*)d_in[8],  *bm=(const float*)d_in[9];
    const float* g1=(const float*)d_in[10], *b1=(const float*)d_in[11];
    const float* g2=(const float*)d_in[12], *b2=(const float*)d_in[13];
    const float* Wp=(const float*)d_in[14], *bp=(const float*)d_in[15];
    const float* rep_w=(const float*)d_in[16];
    const float* Wig=(const float*)d_in[17], *big=(const float*)d_in[18];
    const float* Wmg=(const float*)d_in[19], *bmg=(const float*)d_in[20];
    const float* fb=(const float*)d_in[21], *ib=(const float*)d_in[22];

    float* out_nm = (float*)d_out;
    float* out_hx = out_nm + (size_t)Bc*Mc*Cc;

    float *inp,*mem,*qb,*kb,*vb,*ao,*h1,*h2,*t0,*gt,*rm,*gi;
    cudaGetSymbolAddress((void**)&inp, d_inp);
    cudaGetSymbolAddress((void**)&mem, d_mem);
    cudaGetSymbolAddress((void**)&qb,  d_qb);
    cudaGetSymbolAddress((void**)&kb,  d_kb);
    cudaGetSymbolAddress((void**)&vb,  d_vb);
    cudaGetSymbolAddress((void**)&ao,  d_ao);
    cudaGetSymbolAddress((void**)&h1,  d_h1);
    cudaGetSymbolAddress((void**)&h2,  d_h2);
    cudaGetSymbolAddress((void**)&t0,  d_t0);
    cudaGetSymbolAddress((void**)&gt,  d_gt);
    cudaGetSymbolAddress((void**)&rm,  d_rm);
    cudaGetSymbolAddress((void**)&gi,  d_gi);

    cudaFuncSetAttribute(attn_topk_kernel, cudaFuncAttributeMaxDynamicSharedMemorySize, SMEM_TOPK);
    cudaFuncSetAttribute(attn_hx_kernel,   cudaFuncAttributeMaxDynamicSharedMemorySize, SMEM_HX);

    auto gemm = [&](const float* A, const float* W, const float* bias, float* o,
                    int N, int K, int NO, int relu){
        gemm_kernel<<<dim3(NO/64, (N+63)/64), 256>>>(A, W, bias, o, N, K, NO, relu);
    };

    // inp = ipts @ Wp + bp ; k,v from inp are LOOP-INVARIANT (computed once)
    gemm(ipts, Wp, bp, inp, Bc*Tc, Cc, Cc, 0);
    gemm(inp,  Wk, bk, kb,  Bc*Tc, Cc, Cc, 0);
    gemm(inp,  Wv, bv, vb,  Bc*Tc, Cc, Cc, 0);
    cudaMemcpyAsync(mem, memory, sizeof(float)*(size_t)Bc*Mc*Cc, cudaMemcpyDeviceToDevice);

    for (int blk = 0; blk < NBLK; blk++) {
        gemm(mem, Wq, bq, qb, Bc*Mc, Cc, Cc, 0);
        attn_topk_kernel<<<dim3(Bc*Hc, 10), 128, SMEM_TOPK>>>(qb, kb, vb, ao);
        add_ln_kernel<<<(Bc*Mc + 7)/8, 256>>>(mem, ao, g1, b1, mem, Bc*Mc);
        gemm(mem, Wm, bm, h1, Bc*Mc, Cc, Cc, 1);
        gemm(h1,  Wm, bm, h2, Bc*Mc, Cc, Cc, 1);
        add_ln_kernel<<<(Bc*Mc + 7)/8, 256>>>(mem, h2, g2, b2, mem, Bc*Mc);
    }

    // gates
    repmean_kernel<<<Bc, Cc>>>(inp, rep_w, rm);
    gemm(rm, Wig, big, gi, Bc, Cc, 2*Cc, 0);
    tanh_kernel<<<2048, 256>>>(memory, t0, (size_t)Bc*Mc*Cc);
    gemm(t0, Wmg, bmg, gt, Bc*Mc, Cc, 2*Cc, 0);
    gate_kernel<<<2048, 256>>>(gt, gi, mem, memory, ib, fb, out_nm);

    // hx = attention(q from inp, k/v from next_memory), no topk
    gemm(inp,    Wq, bq, qb, Bc*Tc, Cc, Cc, 0);
    gemm(out_nm, Wk, bk, kb, Bc*Mc, Cc, Cc, 0);
    gemm(out_nm, Wv, bv, vb, Bc*Mc, Cc, Cc, 0);
    attn_hx_kernel<<<dim3(Bc*Hc, Tc/QT), 128, SMEM_HX>>>(qb, kb, vb, out_hx);
}

// round 2
// speedup vs baseline: 1.8236x; 1.8236x over previous
#include <cuda_runtime.h>
#include <math.h>

#define Bc 32
#define Tc 128
#define Mc 1290
#define Cc 512
#define Hc 8
#define NBLK 4
#define TOPK 8

static __device__ float d_inp[Bc*Tc*Cc];
static __device__ float d_mem[(size_t)Bc*Mc*Cc];
static __device__ float d_qb [(size_t)Bc*Mc*Cc];
static __device__ float d_kb [(size_t)Bc*Mc*Cc];
static __device__ float d_vb [(size_t)Bc*Mc*Cc];
static __device__ float d_ao [(size_t)Bc*Mc*Cc];
static __device__ float d_h1 [(size_t)Bc*Mc*Cc];
static __device__ float d_h2 [(size_t)Bc*Mc*Cc];
static __device__ float d_t0 [(size_t)Bc*Mc*Cc];
static __device__ float d_gt [(size_t)Bc*Mc*2*Cc];
static __device__ float d_rm [Bc*Cc];
static __device__ float d_gi [Bc*2*Cc];

#define F_INF __int_as_float(0x7f800000)

// ============ GEMM: 128x128 tile, 256 thr, 8x8/thread (split 4+4) ============
__global__ __launch_bounds__(256) void gemm_kernel(
    const float* __restrict__ A, const float* __restrict__ W,
    const float* __restrict__ bias, float* __restrict__ out,
    int N, int K, int NO, int relu)
{
    __shared__ float As[16][128];
    __shared__ float Bs[16][128];
    int t  = threadIdx.x;
    int tx = t & 15, ty = t >> 4;
    int row0 = blockIdx.y * 128;
    int col0 = blockIdx.x * 128;
    float acc[2][2][4][4] = {};

    int arow = t >> 2;          // 0..63 (+64)
    int akc  = (t & 3) * 4;     // k sub
    int bk   = t >> 5;          // 0..7 (+8)
    int bcol = (t & 31) * 4;

    for (int k0 = 0; k0 < K; k0 += 16) {
        #pragma unroll
        for (int i = 0; i < 2; i++) {
            int r = arow + i*64;
            float4 av = make_float4(0.f,0.f,0.f,0.f);
            if (row0 + r < N)
                av = *reinterpret_cast<const float4*>(A + (size_t)(row0+r)*K + k0 + akc);
            As[akc+0][r] = av.x; As[akc+1][r] = av.y;
            As[akc+2][r] = av.z; As[akc+3][r] = av.w;
        }
        #pragma unroll
        for (int i = 0; i < 2; i++) {
            int kk = bk + i*8;
            float4 bv = *reinterpret_cast<const float4*>(W + (size_t)(k0+kk)*NO + col0 + bcol);
            *reinterpret_cast<float4*>(&Bs[kk][bcol]) = bv;
        }
        __syncthreads();
        #pragma unroll
        for (int kk = 0; kk < 16; kk++) {
            float a[2][4], b[2][4];
            *reinterpret_cast<float4*>(a[0]) = *reinterpret_cast<const float4*>(&As[kk][ty*4]);
            *reinterpret_cast<float4*>(a[1]) = *reinterpret_cast<const float4*>(&As[kk][64 + ty*4]);
            *reinterpret_cast<float4*>(b[0]) = *reinterpret_cast<const float4*>(&Bs[kk][tx*4]);
            *reinterpret_cast<float4*>(b[1]) = *reinterpret_cast<const float4*>(&Bs[kk][64 + tx*4]);
            #pragma unroll
            for (int ia=0; ia<2; ia++)
            #pragma unroll
            for (int ib=0; ib<2; ib++)
            #pragma unroll
            for (int i=0; i<4; i++)
            #pragma unroll
            for (int j=0; j<4; j++)
                acc[ia][ib][i][j] += a[ia][i] * b[ib][j];
        }
        __syncthreads();
    }

    float4 bb[2];
    bb[0] = *reinterpret_cast<const float4*>(bias + col0 + tx*4);
    bb[1] = *reinterpret_cast<const float4*>(bias + col0 + 64 + tx*4);
    #pragma unroll
    for (int ia=0; ia<2; ia++)
    #pragma unroll
    for (int i=0; i<4; i++) {
        int r = row0 + ia*64 + ty*4 + i;
        if (r >= N) continue;
        #pragma unroll
        for (int ib=0; ib<2; ib++) {
            float4 o4;
            o4.x = acc[ia][ib][i][0] + bb[ib].x;
            o4.y = acc[ia][ib][i][1] + bb[ib].y;
            o4.z = acc[ia][ib][i][2] + bb[ib].z;
            o4.w = acc[ia][ib][i][3] + bb[ib].w;
            if (relu) {
                o4.x = fmaxf(o4.x,0.f); o4.y = fmaxf(o4.y,0.f);
                o4.z = fmaxf(o4.z,0.f); o4.w = fmaxf(o4.w,0.f);
            }
            *reinterpret_cast<float4*>(out + (size_t)r*NO + col0 + ib*64 + tx*4) = o4;
        }
    }
}

// ============ warp reductions ============
__device__ __forceinline__ float warpMax(float v){
    #pragma unroll
    for (int o=16;o;o>>=1) v = fmaxf(v, __shfl_xor_sync(0xffffffffu, v, o));
    return v;
}
__device__ __forceinline__ float warpSum(float v){
    #pragma unroll
    for (int o=16;o;o>>=1) v += __shfl_xor_sync(0xffffffffu, v, o);
    return v;
}

// ============ top-k attention: warp-per-query ============
// q[B,M,C], k/v[B,T,C] -> o[B,M,C].  Block: 256 thr (8 warps), K/V tiles in smem.
#define Q_BLOCKS 6
#define SMEM_TOPK ((64*128 + 128*64 + 8*64)*4)
__global__ __launch_bounds__(256) void attn_topk_kernel(
    const float* __restrict__ q, const float* __restrict__ k,
    const float* __restrict__ v, float* __restrict__ o)
{
    extern __shared__ float sm[];
    float* Kt = sm;             // [64][128]  Kt[d][key]
    float* Vs = Kt + 64*128;    // [128][64]
    float* sq = Vs + 128*64;    // [8][64]

    int tid = threadIdx.x;
    int warp = tid >> 5, lane = tid & 31;
    int bh = blockIdx.x, b = bh / Hc, h = bh % Hc;

    for (int idx = tid; idx < 128*16; idx += 256) {
        int t = idx >> 4, j = idx & 15;
        size_t row = ((size_t)b*Tc + t)*Cc + h*64 + j*4;
        float4 kv = *reinterpret_cast<const float4*>(k + row);
        float4 vv = *reinterpret_cast<const float4*>(v + row);
        Kt[(j*4+0)*128 + t] = kv.x;
        Kt[(j*4+1)*128 + t] = kv.y;
        Kt[(j*4+2)*128 + t] = kv.z;
        Kt[(j*4+3)*128 + t] = kv.w;
        *reinterpret_cast<float4*>(&Vs[t*64 + j*4]) = vv;
    }
    __syncthreads();

    const int nq = (Mc + Q_BLOCKS - 1) / Q_BLOCKS;   // 215
    int q0 = blockIdx.y * nq;
    int qend = min(q0 + nq, Mc);

    for (int qi = q0 + warp; qi < qend; qi += 8) {
        if (lane < 16) {
            float4 qv = *reinterpret_cast<const float4*>(q + ((size_t)b*Mc + qi)*Cc + h*64 + lane*4);
            *reinterpret_cast<float4*>(&sq[warp*64 + lane*4]) = qv;
        }
        __syncwarp();
        float s[4] = {0.f,0.f,0.f,0.f};
        #pragma unroll
        for (int d0 = 0; d0 < 64; d0 += 4) {
            float4 qd = *reinterpret_cast<const float4*>(&sq[warp*64 + d0]);
            float qa[4] = {qd.x, qd.y, qd.z, qd.w};
            #pragma unroll
            for (int dd = 0; dd < 4; dd++) {
                float4 kk4 = *reinterpret_cast<const float4*>(&Kt[(d0+dd)*128 + lane*4]);
                s[0] += qa[dd]*kk4.x; s[1] += qa[dd]*kk4.y;
                s[2] += qa[dd]*kk4.z; s[3] += qa[dd]*kk4.w;
            }
        }
        #pragma unroll
        for (int j=0;j<4;j++) s[j] *= 0.125f;

        // top-8 threshold via iterative warp max
        float thr = F_INF, gmax = 0.f;
        #pragma unroll
        for (int it = 0; it < TOPK; it++) {
            float c = -F_INF;
            #pragma unroll
            for (int j=0;j<4;j++) c = fmaxf(c, (s[j] < thr) ? s[j] : -F_INF);
            float mx = warpMax(c);
            if (it == 0) gmax = mx;
            thr = mx;
        }
        // softmax over all 128 keys, then mask (no renorm)
        float e[4], le = 0.f;
        #pragma unroll
        for (int j=0;j<4;j++){ e[j] = __expf(s[j] - gmax); le += e[j]; }
        float inv = 1.f / warpSum(le);
        float p[4];
        #pragma unroll
        for (int j=0;j<4;j++) p[j] = (s[j] >= thr) ? e[j]*inv : 0.f;

        // sparse AV: only ~8 nonzero probs
        float2 acc = make_float2(0.f, 0.f);
        int d0 = lane*2;
        #pragma unroll
        for (int j=0;j<4;j++) {
            unsigned msk = __ballot_sync(0xffffffffu, p[j] != 0.f);
            while (msk) {
                int src = __ffs(msk) - 1;
                msk &= msk - 1;
                float pv = __shfl_sync(0xffffffffu, p[j], src);
                int key = src*4 + j;
                float2 vv = *reinterpret_cast<const float2*>(&Vs[key*64 + d0]);
                acc.x += pv*vv.x; acc.y += pv*vv.y;
            }
        }
        *reinterpret_cast<float2*>(o + ((size_t)b*Mc + qi)*Cc + h*64 + d0) = acc;
    }
}

// ============ hx attention: warp-per-query online softmax ============
// q[B,T,C], k/v[B,M,C] -> o[B,T,C]. Block 256 thr, 32 queries (4/warp).
#define SMEM_HX ((64*128 + 128*64 + 32*64 + 8*4*128)*4)
__global__ __launch_bounds__(256) void attn_hx_kernel(
    const float* __restrict__ q, const float* __restrict__ k,
    const float* __restrict__ v, float* __restrict__ o)
{
    extern __shared__ float sm[];
    float* Kt = sm;              // [64][128]
    float* Vs = Kt + 64*128;     // [128][64]
    float* sq = Vs + 128*64;     // [32][64]
    float* ps = sq + 32*64;      // [8 warps][4 q][128]

    int tid = threadIdx.x;
    int warp = tid >> 5, lane = tid & 31;
    int bh = blockIdx.x, b = bh / Hc, h = bh % Hc;
    int q0 = blockIdx.y * 32;

    // load 32 query rows
    for (int idx = tid; idx < 32*16; idx += 256) {
        int qi = idx >> 4, j = idx & 15;
        float4 qv = *reinterpret_cast<const float4*>(q + ((size_t)b*Tc + q0 + qi)*Cc + h*64 + j*4);
        *reinterpret_cast<float4*>(&sq[qi*64 + j*4]) = qv;
    }

    float m[4], den[4];
    float2 acc[4];
    #pragma unroll
    for (int i=0;i<4;i++){ m[i] = -F_INF; den[i] = 0.f; acc[i] = make_float2(0.f,0.f); }
    int d0 = lane*2;

    for (int c0 = 0; c0 < Mc; c0 += 128) {
        int nk = min(128, Mc - c0);
        __syncthreads();
        for (int idx = tid; idx < 128*16; idx += 256) {
            int t = idx >> 4, j = idx & 15;
            float4 kv = make_float4(0.f,0.f,0.f,0.f), vv = kv;
            if (t < nk) {
                size_t row = ((size_t)b*Mc + c0 + t)*Cc + h*64 + j*4;
                kv = *reinterpret_cast<const float4*>(k + row);
                vv = *reinterpret_cast<const float4*>(v + row);
            }
            Kt[(j*4+0)*128 + t] = kv.x;
            Kt[(j*4+1)*128 + t] = kv.y;
            Kt[(j*4+2)*128 + t] = kv.z;
            Kt[(j*4+3)*128 + t] = kv.w;
            *reinterpret_cast<float4*>(&Vs[t*64 + j*4]) = vv;
        }
        __syncthreads();

        #pragma unroll
        for (int i=0;i<4;i++) {
            int qrow = warp*4 + i;
            float s[4] = {0.f,0.f,0.f,0.f};
            #pragma unroll
            for (int dd0 = 0; dd0 < 64; dd0 += 4) {
                float4 qd = *reinterpret_cast<const float4*>(&sq[qrow*64 + dd0]);
                float qa[4] = {qd.x, qd.y, qd.z, qd.w};
                #pragma unroll
                for (int dd = 0; dd < 4; dd++) {
                    float4 kk4 = *reinterpret_cast<const float4*>(&Kt[(dd0+dd)*128 + lane*4]);
                    s[0] += qa[dd]*kk4.x; s[1] += qa[dd]*kk4.y;
                    s[2] += qa[dd]*kk4.z; s[3] += qa[dd]*kk4.w;
                }
            }
            float lm = -F_INF;
            #pragma unroll
            for (int j=0;j<4;j++) {
                s[j] = (lane*4 + j < nk) ? s[j]*0.125f : -F_INF;
                lm = fmaxf(lm, s[j]);
            }
            float tmax = warpMax(lm);
            float newm = fmaxf(m[i], tmax);
            float f = __expf(m[i] - newm);
            float e[4], le = 0.f;
            #pragma unroll
            for (int j=0;j<4;j++){ e[j] = __expf(s[j] - newm); le += e[j]; }
            den[i] = den[i]*f + warpSum(le);
            m[i] = newm;
            acc[i].x *= f; acc[i].y *= f;
            // probs to smem (warp-private), dense AV
            *reinterpret_cast<float4*>(&ps[(warp*4 + i)*128 + lane*4]) =
                make_float4(e[0], e[1], e[2], e[3]);
            __syncwarp();
            float ax = acc[i].x, ay = acc[i].y;
            #pragma unroll 4
            for (int kk = 0; kk < 128; kk++) {
                float pv = ps[(warp*4 + i)*128 + kk];
                float2 vv = *reinterpret_cast<const float2*>(&Vs[kk*64 + d0]);
                ax += pv*vv.x; ay += pv*vv.y;
            }
            acc[i].x = ax; acc[i].y = ay;
        }
    }
    #pragma unroll
    for (int i=0;i<4;i++) {
        int qi = q0 + warp*4 + i;
        float invd = 1.f / den[i];
        float2 ov = make_float2(acc[i].x*invd, acc[i].y*invd);
        *reinterpret_cast<float2*>(o + ((size_t)b*Tc + qi)*Cc + h*64 + d0) = ov;
    }
}

// ============ add + layernorm ============
__global__ __launch_bounds__(256) void add_ln_kernel(
    const float* __restrict__ x, const float* __restrict__ r,
    const float* __restrict__ g, const float* __restrict__ bb,
    float* __restrict__ out, int nrows)
{
    int warp = (blockIdx.x * blockDim.x + threadIdx.x) >> 5;
    int lane = threadIdx.x & 31;
    if (warp >= nrows) return;
    const float* xr = x + (size_t)warp * Cc;
    const float* rr = r + (size_t)warp * Cc;
    float vals[16];
    float s = 0.f;
    #pragma unroll
    for (int i=0;i<16;i++) { float vv = xr[lane + i*32] + rr[lane + i*32]; vals[i] = vv; s += vv; }
    #pragma unroll
    for (int o2=16;o2;o2>>=1) s += __shfl_xor_sync(0xffffffffu, s, o2);
    float mu = s * (1.f/512.f);
    float vs = 0.f;
    #pragma unroll
    for (int i=0;i<16;i++){ float d = vals[i]-mu; vs += d*d; }
    #pragma unroll
    for (int o2=16;o2;o2>>=1) vs += __shfl_xor_sync(0xffffffffu, vs, o2);
    float rstd = rsqrtf(vs*(1.f/512.f) + 1e-5f);
    float* outr = out + (size_t)warp * Cc;
    #pragma unroll
    for (int i=0;i<16;i++){ int cc = lane + i*32; outr[cc] = (vals[i]-mu)*rstd*g[cc] + bb[cc]; }
}

// ============ misc elementwise ============
__global__ void repmean_kernel(const float* __restrict__ inp, const float* __restrict__ rep_w,
                               float* __restrict__ out)
{
    int b = blockIdx.x, c = threadIdx.x;
    const float* base = inp + (size_t)b*Tc*Cc + c;
    float rw = rep_w[c];
    float s = 0.f;
    for (int t=0;t<Tc;t++) s += fmaxf(rw * base[(size_t)t*Cc], 0.f);
    out[b*Cc + c] = s * (1.f/Tc);
}

__global__ void tanh_kernel(const float* __restrict__ in, float* __restrict__ o, size_t n)
{
    size_t i = (size_t)blockIdx.x*blockDim.x + threadIdx.x;
    size_t st = (size_t)gridDim.x*blockDim.x;
    for (; i < n; i += st) o[i] = tanhf(in[i]);
}

__global__ void gate_kernel(const float* __restrict__ gates, const float* __restrict__ gi,
                            const float* __restrict__ mem_final, const float* __restrict__ mem0,
                            const float* __restrict__ ib, const float* __restrict__ fb,
                            float* __restrict__ nm)
{
    size_t n = (size_t)Bc*Mc*Cc;
    size_t i = (size_t)blockIdx.x*blockDim.x + threadIdx.x;
    size_t st = (size_t)gridDim.x*blockDim.x;
    float ibv = ib[0], fbv = fb[0];
    for (; i < n; i += st) {
        int c = (int)(i % Cc);
        size_t bm = i / Cc;
        int b = (int)(bm / Mc);
        float gI = gates[bm*2*Cc + c]      + gi[b*2*Cc + c]      + ibv;
        float gF = gates[bm*2*Cc + Cc + c] + gi[b*2*Cc + Cc + c] + fbv;
        float igv = 1.f/(1.f + __expf(-gI));
        float fgv = 1.f/(1.f + __expf(-gF));
        nm[i] = igv * tanhf(mem_final[i]) + fgv * mem0[i];
    }
}

// ============ launch ============
extern "C" void kernel_launch(void* const* d_in, const int* in_sizes, int n_in,
                              void* d_out, int out_size)
{
    const float* ipts   = (const float*)d_in[0];
    const float* memory = (const float*)d_in[1];
    const float* Wq=(const float*)d_in[2],  *bq=(const float*)d_in[3];
    const float* Wk=(const float*)d_in[4],  *bk=(const float*)d_in[5];
    const float* Wv=(const float*)d_in[6],  *bv=(const float*)d_in[7];
    const float* Wm=(const float*)d_in[8],  *bm=(const float*)d_in[9];
    const float* g1=(const float*)d_in[10], *b1=(const float*)d_in[11];
    const float* g2=(const float*)d_in[12], *b2=(const float*)d_in[13];
    const float* Wp=(const float*)d_in[14], *bp=(const float*)d_in[15];
    const float* rep_w=(const float*)d_in[16];
    const float* Wig=(const float*)d_in[17], *big=(const float*)d_in[18];
    const float* Wmg=(const float*)d_in[19], *bmg=(const float*)d_in[20];
    const float* fb=(const float*)d_in[21], *ib=(const float*)d_in[22];

    float* out_nm = (float*)d_out;
    float* out_hx = out_nm + (size_t)Bc*Mc*Cc;

    float *inp,*mem,*qb,*kb,*vb,*ao,*h1,*h2,*t0,*gt,*rm,*gi;
    cudaGetSymbolAddress((void**)&inp, d_inp);
    cudaGetSymbolAddress((void**)&mem, d_mem);
    cudaGetSymbolAddress((void**)&qb,  d_qb);
    cudaGetSymbolAddress((void**)&kb,  d_kb);
    cudaGetSymbolAddress((void**)&vb,  d_vb);
    cudaGetSymbolAddress((void**)&ao,  d_ao);
    cudaGetSymbolAddress((void**)&h1,  d_h1);
    cudaGetSymbolAddress((void**)&h2,  d_h2);
    cudaGetSymbolAddress((void**)&t0,  d_t0);
    cudaGetSymbolAddress((void**)&gt,  d_gt);
    cudaGetSymbolAddress((void**)&rm,  d_rm);
    cudaGetSymbolAddress((void**)&gi,  d_gi);

    cudaFuncSetAttribute(attn_topk_kernel, cudaFuncAttributeMaxDynamicSharedMemorySize, SMEM_TOPK);
    cudaFuncSetAttribute(attn_hx_kernel,   cudaFuncAttributeMaxDynamicSharedMemorySize, SMEM_HX);

    auto gemm = [&](const float* A, const float* W, const float* bias, float* o,
                    int N, int K, int NO, int relu){
        gemm_kernel<<<dim3(NO/128, (N+127)/128), 256>>>(A, W, bias, o, N, K, NO, relu);
    };

    // inp = ipts @ Wp + bp ; k,v from inp are LOOP-INVARIANT
    gemm(ipts, Wp, bp, inp, Bc*Tc, Cc, Cc, 0);
    gemm(inp,  Wk, bk, kb,  Bc*Tc, Cc, Cc, 0);
    gemm(inp,  Wv, bv, vb,  Bc*Tc, Cc, Cc, 0);
    cudaMemcpyAsync(mem, memory, sizeof(float)*(size_t)Bc*Mc*Cc, cudaMemcpyDeviceToDevice);

    for (int blk = 0; blk < NBLK; blk++) {
        gemm(mem, Wq, bq, qb, Bc*Mc, Cc, Cc, 0);
        attn_topk_kernel<<<dim3(Bc*Hc, Q_BLOCKS), 256, SMEM_TOPK>>>(qb, kb, vb, ao);
        add_ln_kernel<<<(Bc*Mc + 7)/8, 256>>>(mem, ao, g1, b1, mem, Bc*Mc);
        gemm(mem, Wm, bm, h1, Bc*Mc, Cc, Cc, 1);
        gemm(h1,  Wm, bm, h2, Bc*Mc, Cc, Cc, 1);
        add_ln_kernel<<<(Bc*Mc + 7)/8, 256>>>(mem, h2, g2, b2, mem, Bc*Mc);
    }

    // gates
    repmean_kernel<<<Bc, Cc>>>(inp, rep_w, rm);
    gemm(rm, Wig, big, gi, Bc, Cc, 2*Cc, 0);
    tanh_kernel<<<2048, 256>>>(memory, t0, (size_t)Bc*Mc*Cc);
    gemm(t0, Wmg, bmg, gt, Bc*Mc, Cc, 2*Cc, 0);
    gate_kernel<<<2048, 256>>>(gt, gi, mem, memory, ib, fb, out_nm);

    // hx = attention(q from inp, k/v from next_memory), no topk
    gemm(inp,    Wq, bq, qb, Bc*Tc, Cc, Cc, 0);
    gemm(out_nm, Wk, bk, kb, Bc*Mc, Cc, Cc, 0);
    gemm(out_nm, Wv, bv, vb, Bc*Mc, Cc, Cc, 0);
    attn_hx_kernel<<<dim3(Bc*Hc, Tc/32), 256, SMEM_HX>>>(qb, kb, vb, out_hx);
}

// round 4
// speedup vs baseline: 2.1676x; 1.1886x over previous
#include <cuda_runtime.h>
#include <math.h>
#include <stdint.h>

#define Bc 32
#define Tc 128
#define Mc 1290
#define Cc 512
#define Hc 8
#define NBLK 4
#define TOPK 8

static __device__ float d_inp[Bc*Tc*Cc];
static __device__ float d_mem[(size_t)Bc*Mc*Cc];
static __device__ float d_qb [(size_t)Bc*Mc*Cc];
static __device__ float d_kb [(size_t)Bc*Mc*Cc];
static __device__ float d_vb [(size_t)Bc*Mc*Cc];
static __device__ float d_ao [(size_t)Bc*Mc*Cc];
static __device__ float d_h1 [(size_t)Bc*Mc*Cc];
static __device__ float d_h2 [(size_t)Bc*Mc*Cc];
static __device__ float d_gt [(size_t)Bc*Mc*2*Cc];
static __device__ float d_rm [Bc*Cc];
static __device__ float d_gi [Bc*2*Cc];
// transposed weights (K-major rows per output column)
static __device__ float d_WqT[Cc*Cc];
static __device__ float d_WkT[Cc*Cc];
static __device__ float d_WvT[Cc*Cc];
static __device__ float d_WmT[Cc*Cc];
static __device__ float d_WpT[Cc*Cc];
static __device__ float d_WmgT[Cc*2*Cc];

#define F_INF __int_as_float(0x7f800000)

__device__ __forceinline__ float to_tf32(float x){
    float r;
    asm("cvt.rna.tf32.f32 %0, %1;" : "=f"(r) : "f"(x));
    return r;
}
__device__ __forceinline__ void mma_tf32(float* d, const uint32_t* a, const uint32_t* b){
    asm volatile("mma.sync.aligned.m16n8k8.row.col.f32.tf32.tf32.f32 "
        "{%0,%1,%2,%3}, {%4,%5,%6,%7}, {%8,%9}, {%0,%1,%2,%3};"
        : "+f"(d[0]), "+f"(d[1]), "+f"(d[2]), "+f"(d[3])
        : "r"(a[0]), "r"(a[1]), "r"(a[2]), "r"(a[3]), "r"(b[0]), "r"(b[1]));
}

// ============ tf32 mma.sync GEMM: out[N,NO] = A[N,512] @ WT[NO,512]^T + bias ============
// block 128x128, K-chunk 32, 256 thr = 8 warps (4m x 2n), warp tile 32x64.
// SMEM holds fragment-permuted A (LDS.128/frag) and B (LDS.64/frag).
#define TGK 32
#define TG_SMEM ((4096 + 4096)*4)
__global__ __launch_bounds__(256) void tf32_gemm_kernel(
    const float* __restrict__ A, const float* __restrict__ WT,
    const float* __restrict__ bias, float* __restrict__ out,
    int Nrows, int K, int NO, int relu, int dotanh)
{
    extern __shared__ float sm[];
    float* As = sm;           // 4096: atom (mi*4+ki)*128 + lane*4 + j
    float* Bs = sm + 4096;    // 4096: atom (ki*16+ni)*64 + lane*2 + j

    int tid = threadIdx.x;
    int wid = tid >> 5, lane = tid & 31;
    int wm = wid & 3, wn = wid >> 2;
    int row0 = blockIdx.y * 128;
    int col0 = blockIdx.x * 128;

    float acc[2][8][4];
    #pragma unroll
    for (int i=0;i<2;i++)
        #pragma unroll
        for (int j=0;j<8;j++)
            #pragma unroll
            for (int l=0;l<4;l++) acc[i][j][l] = 0.f;

    int srow = tid >> 1;            // 0..127
    int skb  = (tid & 1) * 16;      // 0 or 16

    for (int k0 = 0; k0 < K; k0 += TGK) {
        __syncthreads();
        // ---- stage A (rows may be OOB -> skip; those accum rows never stored) ----
        {
            int grow = row0 + srow;
            if (grow < Nrows) {
                int mi = srow >> 4, rr = srow & 15;
                #pragma unroll
                for (int jj = 0; jj < 4; jj++) {
                    float4 v = *reinterpret_cast<const float4*>(A + (size_t)grow*K + k0 + skb + jj*4);
                    if (dotanh) { v.x=tanhf(v.x); v.y=tanhf(v.y); v.z=tanhf(v.z); v.w=tanhf(v.w); }
                    float e[4] = {to_tf32(v.x), to_tf32(v.y), to_tf32(v.z), to_tf32(v.w)};
                    #pragma unroll
                    for (int q = 0; q < 4; q++) {
                        int c = skb + jj*4 + q;
                        int ki = c >> 3, cc = c & 7;
                        int fj = (rr >= 8 ? 1 : 0) + (cc >= 4 ? 2 : 0);
                        int fl = (rr & 7)*4 + (cc & 3);
                        As[(mi*4 + ki)*128 + fl*4 + fj] = e[q];
                    }
                }
            }
        }
        // ---- stage B ----
        {
            int n = srow;
            int ni = n >> 3, nn = n & 7;
            #pragma unroll
            for (int jj = 0; jj < 4; jj++) {
                float4 v = *reinterpret_cast<const float4*>(WT + (size_t)(col0 + n)*K + k0 + skb + jj*4);
                float e[4] = {to_tf32(v.x), to_tf32(v.y), to_tf32(v.z), to_tf32(v.w)};
                #pragma unroll
                for (int q = 0; q < 4; q++) {
                    int c = skb + jj*4 + q;
                    int ki = c >> 3, cc = c & 7;
                    int fj = (cc >= 4 ? 1 : 0);
                    int fl = nn*4 + (cc & 3);
                    Bs[(ki*16 + ni)*64 + fl*2 + fj] = e[q];
                }
            }
        }
        __syncthreads();
        // ---- compute: 4 k-steps of 8 ----
        #pragma unroll
        for (int ki = 0; ki < 4; ki++) {
            uint32_t af[2][4];
            #pragma unroll
            for (int ma = 0; ma < 2; ma++)
                *reinterpret_cast<float4*>(af[ma]) =
                    *reinterpret_cast<const float4*>(&As[((wm*2 + ma)*4 + ki)*128 + lane*4]);
            uint32_t bf[8][2];
            #pragma unroll
            for (int na = 0; na < 8; na++)
                *reinterpret_cast<float2*>(bf[na]) =
                    *reinterpret_cast<const float2*>(&Bs[(ki*16 + wn*8 + na)*64 + lane*2]);
            #pragma unroll
            for (int ma = 0; ma < 2; ma++)
                #pragma unroll
                for (int na = 0; na < 8; na++)
                    mma_tf32(acc[ma][na], af[ma], bf[na]);
        }
    }

    // ---- epilogue ----
    int lr = lane >> 2, lc = lane & 3;
    #pragma unroll
    for (int ma = 0; ma < 2; ma++) {
        int r1 = row0 + wm*32 + ma*16 + lr;
        int r2 = r1 + 8;
        #pragma unroll
        for (int na = 0; na < 8; na++) {
            int col = col0 + wn*64 + na*8 + lc*2;
            float bx = bias[col], by = bias[col+1];
            float2 o1 = make_float2(acc[ma][na][0] + bx, acc[ma][na][1] + by);
            float2 o2 = make_float2(acc[ma][na][2] + bx, acc[ma][na][3] + by);
            if (relu) {
                o1.x = fmaxf(o1.x,0.f); o1.y = fmaxf(o1.y,0.f);
                o2.x = fmaxf(o2.x,0.f); o2.y = fmaxf(o2.y,0.f);
            }
            if (r1 < Nrows) *reinterpret_cast<float2*>(out + (size_t)r1*NO + col) = o1;
            if (r2 < Nrows) *reinterpret_cast<float2*>(out + (size_t)r2*NO + col) = o2;
        }
    }
}

// ============ transpose: in[R][C] -> out[C][R] ============
__global__ __launch_bounds__(256) void transpose_kernel(
    const float* __restrict__ in, float* __restrict__ out, int R, int C)
{
    __shared__ float t[32][33];
    int c0 = blockIdx.x*32, r0 = blockIdx.y*32;
    int x = threadIdx.x & 31, y = threadIdx.x >> 5;
    #pragma unroll
    for (int i = 0; i < 4; i++)
        t[y + i*8][x] = in[(size_t)(r0 + y + i*8)*C + c0 + x];
    __syncthreads();
    #pragma unroll
    for (int i = 0; i < 4; i++)
        out[(size_t)(c0 + y + i*8)*R + r0 + x] = t[x][y + i*8];
}

// ============ SIMT GEMM (tiny shapes) ============
__global__ __launch_bounds__(256) void gemm_kernel(
    const float* __restrict__ A, const float* __restrict__ W,
    const float* __restrict__ bias, float* __restrict__ out,
    int N, int K, int NO, int relu)
{
    __shared__ float As[16][64];
    __shared__ float Bs[16][64];
    int t  = threadIdx.x;
    int tx = t & 15, ty = t >> 4;
    int row0 = blockIdx.y * 64;
    int col0 = blockIdx.x * 64;
    float acc[4][4] = {};
    for (int k0 = 0; k0 < K; k0 += 16) {
        {
            int r = t >> 2;
            int c4 = (t & 3) * 4;
            float4 av = make_float4(0.f,0.f,0.f,0.f);
            if (row0 + r < N)
                av = *reinterpret_cast<const float4*>(A + (size_t)(row0 + r) * K + k0 + c4);
            As[c4+0][r] = av.x; As[c4+1][r] = av.y; As[c4+2][r] = av.z; As[c4+3][r] = av.w;
        }
        {
            int r  = t >> 4;
            int c4 = (t & 15) * 4;
            float4 bv = *reinterpret_cast<const float4*>(W + (size_t)(k0 + r) * NO + col0 + c4);
            *reinterpret_cast<float4*>(&Bs[r][c4]) = bv;
        }
        __syncthreads();
        #pragma unroll
        for (int kk = 0; kk < 16; kk++) {
            float4 a4 = *reinterpret_cast<const float4*>(&As[kk][ty*4]);
            float4 b4 = *reinterpret_cast<const float4*>(&Bs[kk][tx*4]);
            float a[4] = {a4.x,a4.y,a4.z,a4.w};
            float b[4] = {b4.x,b4.y,b4.z,b4.w};
            #pragma unroll
            for (int i=0;i<4;i++)
                #pragma unroll
                for (int j=0;j<4;j++) acc[i][j] += a[i]*b[j];
        }
        __syncthreads();
    }
    float4 bb = *reinterpret_cast<const float4*>(bias + col0 + tx*4);
    #pragma unroll
    for (int i=0;i<4;i++) {
        int r = row0 + ty*4 + i;
        if (r >= N) continue;
        float4 o4;
        o4.x = acc[i][0] + bb.x; o4.y = acc[i][1] + bb.y;
        o4.z = acc[i][2] + bb.z; o4.w = acc[i][3] + bb.w;
        if (relu) {
            o4.x = fmaxf(o4.x,0.f); o4.y = fmaxf(o4.y,0.f);
            o4.z = fmaxf(o4.z,0.f); o4.w = fmaxf(o4.w,0.f);
        }
        *reinterpret_cast<float4*>(out + (size_t)r * NO + col0 + tx*4) = o4;
    }
}

// ============ warp reductions ============
__device__ __forceinline__ float warpMax(float v){
    #pragma unroll
    for (int o=16;o;o>>=1) v = fmaxf(v, __shfl_xor_sync(0xffffffffu, v, o));
    return v;
}
__device__ __forceinline__ float warpSum(float v){
    #pragma unroll
    for (int o=16;o;o>>=1) v += __shfl_xor_sync(0xffffffffu, v, o);
    return v;
}

// ============ top-k attention: warp-per-query ============
#define Q_BLOCKS 6
#define SMEM_TOPK ((64*128 + 128*64 + 8*64)*4)
__global__ __launch_bounds__(256) void attn_topk_kernel(
    const float* __restrict__ q, const float* __restrict__ k,
    const float* __restrict__ v, float* __restrict__ o)
{
    extern __shared__ float sm[];
    float* Kt = sm;
    float* Vs = Kt + 64*128;
    float* sq = Vs + 128*64;

    int tid = threadIdx.x;
    int warp = tid >> 5, lane = tid & 31;
    int bh = blockIdx.x, b = bh / Hc, h = bh % Hc;

    for (int idx = tid; idx < 128*16; idx += 256) {
        int t = idx >> 4, j = idx & 15;
        size_t row = ((size_t)b*Tc + t)*Cc + h*64 + j*4;
        float4 kv = *reinterpret_cast<const float4*>(k + row);
        float4 vv = *reinterpret_cast<const float4*>(v + row);
        Kt[(j*4+0)*128 + t] = kv.x;
        Kt[(j*4+1)*128 + t] = kv.y;
        Kt[(j*4+2)*128 + t] = kv.z;
        Kt[(j*4+3)*128 + t] = kv.w;
        *reinterpret_cast<float4*>(&Vs[t*64 + j*4]) = vv;
    }
    __syncthreads();

    const int nq = (Mc + Q_BLOCKS - 1) / Q_BLOCKS;
    int q0 = blockIdx.y * nq;
    int qend = min(q0 + nq, Mc);

    for (int qi = q0 + warp; qi < qend; qi += 8) {
        if (lane < 16) {
            float4 qv = *reinterpret_cast<const float4*>(q + ((size_t)b*Mc + qi)*Cc + h*64 + lane*4);
            *reinterpret_cast<float4*>(&sq[warp*64 + lane*4]) = qv;
        }
        __syncwarp();
        float s[4] = {0.f,0.f,0.f,0.f};
        #pragma unroll
        for (int d0 = 0; d0 < 64; d0 += 4) {
            float4 qd = *reinterpret_cast<const float4*>(&sq[warp*64 + d0]);
            float qa[4] = {qd.x, qd.y, qd.z, qd.w};
            #pragma unroll
            for (int dd = 0; dd < 4; dd++) {
                float4 kk4 = *reinterpret_cast<const float4*>(&Kt[(d0+dd)*128 + lane*4]);
                s[0] += qa[dd]*kk4.x; s[1] += qa[dd]*kk4.y;
                s[2] += qa[dd]*kk4.z; s[3] += qa[dd]*kk4.w;
            }
        }
        #pragma unroll
        for (int j=0;j<4;j++) s[j] *= 0.125f;

        float thr = F_INF, gmax = 0.f;
        #pragma unroll
        for (int it = 0; it < TOPK; it++) {
            float c = -F_INF;
            #pragma unroll
            for (int j=0;j<4;j++) c = fmaxf(c, (s[j] < thr) ? s[j] : -F_INF);
            float mx = warpMax(c);
            if (it == 0) gmax = mx;
            thr = mx;
        }
        float e[4], le = 0.f;
        #pragma unroll
        for (int j=0;j<4;j++){ e[j] = __expf(s[j] - gmax); le += e[j]; }
        float inv = 1.f / warpSum(le);
        float p[4];
        #pragma unroll
        for (int j=0;j<4;j++) p[j] = (s[j] >= thr) ? e[j]*inv : 0.f;

        float2 acc = make_float2(0.f, 0.f);
        int d0 = lane*2;
        #pragma unroll
        for (int j=0;j<4;j++) {
            unsigned msk = __ballot_sync(0xffffffffu, p[j] != 0.f);
            while (msk) {
                int src = __ffs(msk) - 1;
                msk &= msk - 1;
                float pv = __shfl_sync(0xffffffffu, p[j], src);
                int key = src*4 + j;
                float2 vv = *reinterpret_cast<const float2*>(&Vs[key*64 + d0]);
                acc.x += pv*vv.x; acc.y += pv*vv.y;
            }
        }
        *reinterpret_cast<float2*>(o + ((size_t)b*Mc + qi)*Cc + h*64 + d0) = acc;
    }
}

// ============ hx attention ============
#define SMEM_HX ((64*128 + 128*64 + 32*64 + 8*4*128)*4)
__global__ __launch_bounds__(256) void attn_hx_kernel(
    const float* __restrict__ q, const float* __restrict__ k,
    const float* __restrict__ v, float* __restrict__ o)
{
    extern __shared__ float sm[];
    float* Kt = sm;
    float* Vs = Kt + 64*128;
    float* sq = Vs + 128*64;
    float* ps = sq + 32*64;

    int tid = threadIdx.x;
    int warp = tid >> 5, lane = tid & 31;
    int bh = blockIdx.x, b = bh / Hc, h = bh % Hc;
    int q0 = blockIdx.y * 32;

    for (int idx = tid; idx < 32*16; idx += 256) {
        int qi = idx >> 4, j = idx & 15;
        float4 qv = *reinterpret_cast<const float4*>(q + ((size_t)b*Tc + q0 + qi)*Cc + h*64 + j*4);
        *reinterpret_cast<float4*>(&sq[qi*64 + j*4]) = qv;
    }

    float m[4], den[4];
    float2 acc[4];
    #pragma unroll
    for (int i=0;i<4;i++){ m[i] = -F_INF; den[i] = 0.f; acc[i] = make_float2(0.f,0.f); }
    int d0 = lane*2;

    for (int c0 = 0; c0 < Mc; c0 += 128) {
        int nk = min(128, Mc - c0);
        __syncthreads();
        for (int idx = tid; idx < 128*16; idx += 256) {
            int t = idx >> 4, j = idx & 15;
            float4 kv = make_float4(0.f,0.f,0.f,0.f), vv = kv;
            if (t < nk) {
                size_t row = ((size_t)b*Mc + c0 + t)*Cc + h*64 + j*4;
                kv = *reinterpret_cast<const float4*>(k + row);
                vv = *reinterpret_cast<const float4*>(v + row);
            }
            Kt[(j*4+0)*128 + t] = kv.x;
            Kt[(j*4+1)*128 + t] = kv.y;
            Kt[(j*4+2)*128 + t] = kv.z;
            Kt[(j*4+3)*128 + t] = kv.w;
            *reinterpret_cast<float4*>(&Vs[t*64 + j*4]) = vv;
        }
        __syncthreads();

        #pragma unroll
        for (int i=0;i<4;i++) {
            int qrow = warp*4 + i;
            float s[4] = {0.f,0.f,0.f,0.f};
            #pragma unroll
            for (int dd0 = 0; dd0 < 64; dd0 += 4) {
                float4 qd = *reinterpret_cast<const float4*>(&sq[qrow*64 + dd0]);
                float qa[4] = {qd.x, qd.y, qd.z, qd.w};
                #pragma unroll
                for (int dd = 0; dd < 4; dd++) {
                    float4 kk4 = *reinterpret_cast<const float4*>(&Kt[(dd0+dd)*128 + lane*4]);
                    s[0] += qa[dd]*kk4.x; s[1] += qa[dd]*kk4.y;
                    s[2] += qa[dd]*kk4.z; s[3] += qa[dd]*kk4.w;
                }
            }
            float lm = -F_INF;
            #pragma unroll
            for (int j=0;j<4;j++) {
                s[j] = (lane*4 + j < nk) ? s[j]*0.125f : -F_INF;
                lm = fmaxf(lm, s[j]);
            }
            float tmax = warpMax(lm);
            float newm = fmaxf(m[i], tmax);
            float f = __expf(m[i] - newm);
            float e[4], le = 0.f;
            #pragma unroll
            for (int j=0;j<4;j++){ e[j] = __expf(s[j] - newm); le += e[j]; }
            den[i] = den[i]*f + warpSum(le);
            m[i] = newm;
            acc[i].x *= f; acc[i].y *= f;
            *reinterpret_cast<float4*>(&ps[(warp*4 + i)*128 + lane*4]) =
                make_float4(e[0], e[1], e[2], e[3]);
            __syncwarp();
            float ax = acc[i].x, ay = acc[i].y;
            #pragma unroll 4
            for (int kk = 0; kk < 128; kk++) {
                float pv = ps[(warp*4 + i)*128 + kk];
                float2 vv = *reinterpret_cast<const float2*>(&Vs[kk*64 + d0]);
                ax += pv*vv.x; ay += pv*vv.y;
            }
            acc[i].x = ax; acc[i].y = ay;
        }
    }
    #pragma unroll
    for (int i=0;i<4;i++) {
        int qi = q0 + warp*4 + i;
        float invd = 1.f / den[i];
        float2 ov = make_float2(acc[i].x*invd, acc[i].y*invd);
        *reinterpret_cast<float2*>(o + ((size_t)b*Tc + qi)*Cc + h*64 + d0) = ov;
    }
}

// ============ add + layernorm ============
__global__ __launch_bounds__(256) void add_ln_kernel(
    const float* __restrict__ x, const float* __restrict__ r,
    const float* __restrict__ g, const float* __restrict__ bb,
    float* __restrict__ out, int nrows)
{
    int warp = (blockIdx.x * blockDim.x + threadIdx.x) >> 5;
    int lane = threadIdx.x & 31;
    if (warp >= nrows) return;
    const float* xr = x + (size_t)warp * Cc;
    const float* rr = r + (size_t)warp * Cc;
    float vals[16];
    float s = 0.f;
    #pragma unroll
    for (int i=0;i<16;i++) { float vv = xr[lane + i*32] + rr[lane + i*32]; vals[i] = vv; s += vv; }
    #pragma unroll
    for (int o2=16;o2;o2>>=1) s += __shfl_xor_sync(0xffffffffu, s, o2);
    float mu = s * (1.f/512.f);
    float vs = 0.f;
    #pragma unroll
    for (int i=0;i<16;i++){ float d = vals[i]-mu; vs += d*d; }
    #pragma unroll
    for (int o2=16;o2;o2>>=1) vs += __shfl_xor_sync(0xffffffffu, vs, o2);
    float rstd = rsqrtf(vs*(1.f/512.f) + 1e-5f);
    float* outr = out + (size_t)warp * Cc;
    #pragma unroll
    for (int i=0;i<16;i++){ int cc = lane + i*32; outr[cc] = (vals[i]-mu)*rstd*g[cc] + bb[cc]; }
}

// ============ misc elementwise ============
__global__ void repmean_kernel(const float* __restrict__ inp, const float* __restrict__ rep_w,
                               float* __restrict__ out)
{
    int b = blockIdx.x, c = threadIdx.x;
    const float* base = inp + (size_t)b*Tc*Cc + c;
    float rw = rep_w[c];
    float s = 0.f;
    for (int t=0;t<Tc;t++) s += fmaxf(rw * base[(size_t)t*Cc], 0.f);
    out[b*Cc + c] = s * (1.f/Tc);
}

__global__ void gate_kernel(const float* __restrict__ gates, const float* __restrict__ gi,
                            const float* __restrict__ mem_final, const float* __restrict__ mem0,
                            const float* __restrict__ ib, const float* __restrict__ fb,
                            float* __restrict__ nm)
{
    size_t n = (size_t)Bc*Mc*Cc;
    size_t i = (size_t)blockIdx.x*blockDim.x + threadIdx.x;
    size_t st = (size_t)gridDim.x*blockDim.x;
    float ibv = ib[0], fbv = fb[0];
    for (; i < n; i += st) {
        int c = (int)(i % Cc);
        size_t bm = i / Cc;
        int b = (int)(bm / Mc);
        float gI = gates[bm*2*Cc + c]      + gi[b*2*Cc + c]      + ibv;
        float gF = gates[bm*2*Cc + Cc + c] + gi[b*2*Cc + Cc + c] + fbv;
        float igv = 1.f/(1.f + __expf(-gI));
        float fgv = 1.f/(1.f + __expf(-gF));
        nm[i] = igv * tanhf(mem_final[i]) + fgv * mem0[i];
    }
}

// ============ launch ============
extern "C" void kernel_launch(void* const* d_in, const int* in_sizes, int n_in,
                              void* d_out, int out_size)
{
    const float* ipts   = (const float*)d_in[0];
    const float* memory = (const float*)d_in[1];
    const float* Wq=(const float*)d_in[2],  *bq=(const float*)d_in[3];
    const float* Wk=(const float*)d_in[4],  *bk=(const float*)d_in[5];
    const float* Wv=(const float*)d_in[6],  *bv=(const float*)d_in[7];
    const float* Wm=(const float*)d_in[8],  *bm=(const float*)d_in[9];
    const float* g1=(const float*)d_in[10], *b1=(const float*)d_in[11];
    const float* g2=(const float*)d_in[12], *b2=(const float*)d_in[13];
    const float* Wp=(const float*)d_in[14], *bp=(const float*)d_in[15];
    const float* rep_w=(const float*)d_in[16];
    const float* Wig=(const float*)d_in[17], *big=(const float*)d_in[18];
    const float* Wmg=(const float*)d_in[19], *bmg=(const float*)d_in[20];
    const float* fb=(const float*)d_in[21], *ib=(const float*)d_in[22];

    float* out_nm = (float*)d_out;
    float* out_hx = out_nm + (size_t)Bc*Mc*Cc;

    float *inp,*mem,*qb,*kb,*vb,*ao,*h1,*h2,*gt,*rm,*gi;
    float *WqT,*WkT,*WvT,*WmT,*WpT,*WmgT;
    cudaGetSymbolAddress((void**)&inp, d_inp);
    cudaGetSymbolAddress((void**)&mem, d_mem);
    cudaGetSymbolAddress((void**)&qb,  d_qb);
    cudaGetSymbolAddress((void**)&kb,  d_kb);
    cudaGetSymbolAddress((void**)&vb,  d_vb);
    cudaGetSymbolAddress((void**)&ao,  d_ao);
    cudaGetSymbolAddress((void**)&h1,  d_h1);
    cudaGetSymbolAddress((void**)&h2,  d_h2);
    cudaGetSymbolAddress((void**)&gt,  d_gt);
    cudaGetSymbolAddress((void**)&rm,  d_rm);
    cudaGetSymbolAddress((void**)&gi,  d_gi);
    cudaGetSymbolAddress((void**)&WqT, d_WqT);
    cudaGetSymbolAddress((void**)&WkT, d_WkT);
    cudaGetSymbolAddress((void**)&WvT, d_WvT);
    cudaGetSymbolAddress((void**)&WmT, d_WmT);
    cudaGetSymbolAddress((void**)&WpT, d_WpT);
    cudaGetSymbolAddress((void**)&WmgT, d_WmgT);

    cudaFuncSetAttribute(attn_topk_kernel, cudaFuncAttributeMaxDynamicSharedMemorySize, SMEM_TOPK);
    cudaFuncSetAttribute(attn_hx_kernel,   cudaFuncAttributeMaxDynamicSharedMemorySize, SMEM_HX);
    cudaFuncSetAttribute(tf32_gemm_kernel, cudaFuncAttributeMaxDynamicSharedMemorySize, TG_SMEM);

    // transpose weights (K-major rows per output column)
    transpose_kernel<<<dim3(16,16), 256>>>(Wq, WqT, Cc, Cc);
    transpose_kernel<<<dim3(16,16), 256>>>(Wk, WkT, Cc, Cc);
    transpose_kernel<<<dim3(16,16), 256>>>(Wv, WvT, Cc, Cc);
    transpose_kernel<<<dim3(16,16), 256>>>(Wm, WmT, Cc, Cc);
    transpose_kernel<<<dim3(16,16), 256>>>(Wp, WpT, Cc, Cc);
    transpose_kernel<<<dim3(32,16), 256>>>(Wmg, WmgT, Cc, 2*Cc);

    auto tgemm = [&](const float* A, const float* WT, const float* bias, float* o,
                     int N, int NO, int relu, int dotanh){
        tf32_gemm_kernel<<<dim3(NO/128, (N+127)/128), 256, TG_SMEM>>>(
            A, WT, bias, o, N, Cc, NO, relu, dotanh);
    };

    // inp = ipts @ Wp + bp ; k,v from inp are LOOP-INVARIANT
    tgemm(ipts, WpT, bp, inp, Bc*Tc, Cc, 0, 0);
    tgemm(inp,  WkT, bk, kb,  Bc*Tc, Cc, 0, 0);
    tgemm(inp,  WvT, bv, vb,  Bc*Tc, Cc, 0, 0);
    cudaMemcpyAsync(mem, memory, sizeof(float)*(size_t)Bc*Mc*Cc, cudaMemcpyDeviceToDevice);

    for (int blk = 0; blk < NBLK; blk++) {
        tgemm(mem, WqT, bq, qb, Bc*Mc, Cc, 0, 0);
        attn_topk_kernel<<<dim3(Bc*Hc, Q_BLOCKS), 256, SMEM_TOPK>>>(qb, kb, vb, ao);
        add_ln_kernel<<<(Bc*Mc + 7)/8, 256>>>(mem, ao, g1, b1, mem, Bc*Mc);
        tgemm(mem, WmT, bm, h1, Bc*Mc, Cc, 1, 0);
        tgemm(h1,  WmT, bm, h2, Bc*Mc, Cc, 1, 0);
        add_ln_kernel<<<(Bc*Mc + 7)/8, 256>>>(mem, h2, g2, b2, mem, Bc*Mc);
    }

    // gates
    repmean_kernel<<<Bc, Cc>>>(inp, rep_w, rm);
    gemm_kernel<<<dim3(2*Cc/64, 1), 256>>>(rm, Wig, big, gi, Bc, Cc, 2*Cc, 0);
    tgemm(memory, WmgT, bmg, gt, Bc*Mc, 2*Cc, 0, 1);   // tanh fused into A staging
    gate_kernel<<<2048, 256>>>(gt, gi, mem, memory, ib, fb, out_nm);

    // hx = attention(q from inp, k/v from next_memory), no topk
    tgemm(inp,    WqT, bq, qb, Bc*Tc, Cc, 0, 0);
    tgemm(out_nm, WkT, bk, kb, Bc*Mc, Cc, 0, 0);
    tgemm(out_nm, WvT, bv, vb, Bc*Mc, Cc, 0, 0);
    attn_hx_kernel<<<dim3(Bc*Hc, Tc/32), 256, SMEM_HX>>>(qb, kb, vb, out_hx);
}

// round 5
// speedup vs baseline: 3.4207x; 1.5781x over previous
#include <cuda_runtime.h>
#include <math.h>
#include <stdint.h>

#define Bc 32
#define Tc 128
#define Mc 1290
#define Cc 512
#define Hc 8
#define NBLK 4
#define TOPK 8

static __device__ float d_inp[Bc*Tc*Cc];
static __device__ float d_mem[(size_t)Bc*Mc*Cc];
static __device__ float d_qb [(size_t)Bc*Mc*Cc];
static __device__ float d_kb [(size_t)Bc*Mc*Cc];
static __device__ float d_vb [(size_t)Bc*Mc*Cc];
static __device__ float d_ao [(size_t)Bc*Mc*Cc];
static __device__ float d_h1 [(size_t)Bc*Mc*Cc];
static __device__ float d_h2 [(size_t)Bc*Mc*Cc];
static __device__ float d_gt [(size_t)Bc*Mc*2*Cc];
static __device__ float d_rm [Bc*Cc];
static __device__ float d_gi [Bc*2*Cc];
static __device__ float d_WqT[Cc*Cc];
static __device__ float d_WkT[Cc*Cc];
static __device__ float d_WvT[Cc*Cc];
static __device__ float d_WmT[Cc*Cc];
static __device__ float d_WpT[Cc*Cc];
static __device__ float d_WmgT[Cc*2*Cc];

#define F_INF __int_as_float(0x7f800000)

__device__ __forceinline__ float to_tf32(float x){
    float r;
    asm("cvt.rna.tf32.f32 %0, %1;" : "=f"(r) : "f"(x));
    return r;
}
__device__ __forceinline__ void mma_tf32(float* d, const uint32_t* a, const uint32_t* b){
    asm volatile("mma.sync.aligned.m16n8k8.row.col.f32.tf32.tf32.f32 "
        "{%0,%1,%2,%3}, {%4,%5,%6,%7}, {%8,%9}, {%0,%1,%2,%3};"
        : "+f"(d[0]), "+f"(d[1]), "+f"(d[2]), "+f"(d[3])
        : "r"(a[0]), "r"(a[1]), "r"(a[2]), "r"(a[3]), "r"(b[0]), "r"(b[1]));
}

// ============ tf32 mma.sync GEMM: out[N,NO] = A[N,512] @ WT[NO,512]^T + bias ============
// block 128x128, K-chunk 32, 256 thr = 8 warps (4m x 2n), warp tile 32x64.
// Natural-layout SMEM (pitch 36), conflict-free STS.128 staging + conflict-free scalar LDS frags.
#define TGK 32
#define AP 36
#define TG_SMEM (128*AP*2*4)
__global__ __launch_bounds__(256) void tf32_gemm_kernel(
    const float* __restrict__ A, const float* __restrict__ WT,
    const float* __restrict__ bias, float* __restrict__ out,
    int Nrows, int K, int NO, int relu, int dotanh)
{
    extern __shared__ float sm[];
    float* As = sm;             // [128][AP]
    float* Bs = sm + 128*AP;    // [128][AP]

    int tid = threadIdx.x;
    int wid = tid >> 5, lane = tid & 31;
    int wm = wid & 3, wn = wid >> 2;
    int lr = lane >> 2, lc = lane & 3;
    int row0 = blockIdx.y * 128;
    int col0 = blockIdx.x * 128;

    float acc[2][8][4];
    #pragma unroll
    for (int i=0;i<2;i++)
        #pragma unroll
        for (int j=0;j<8;j++)
            #pragma unroll
            for (int l=0;l<4;l++) acc[i][j][l] = 0.f;

    int srow = tid >> 1;            // 0..127
    int skb  = (tid & 1) * 16;      // 0 or 16

    for (int k0 = 0; k0 < K; k0 += TGK) {
        __syncthreads();
        // ---- stage A: natural [row][k], STS.128 conflict-free ----
        {
            int grow = row0 + srow;
            if (grow < Nrows) {
                #pragma unroll
                for (int jj = 0; jj < 4; jj++) {
                    float4 v = *reinterpret_cast<const float4*>(A + (size_t)grow*K + k0 + skb + jj*4);
                    if (dotanh) { v.x=tanhf(v.x); v.y=tanhf(v.y); v.z=tanhf(v.z); v.w=tanhf(v.w); }
                    v.x=to_tf32(v.x); v.y=to_tf32(v.y); v.z=to_tf32(v.z); v.w=to_tf32(v.w);
                    *reinterpret_cast<float4*>(&As[srow*AP + skb + jj*4]) = v;
                }
            }
        }
        // ---- stage B ----
        {
            #pragma unroll
            for (int jj = 0; jj < 4; jj++) {
                float4 v = *reinterpret_cast<const float4*>(WT + (size_t)(col0 + srow)*K + k0 + skb + jj*4);
                v.x=to_tf32(v.x); v.y=to_tf32(v.y); v.z=to_tf32(v.z); v.w=to_tf32(v.w);
                *reinterpret_cast<float4*>(&Bs[srow*AP + skb + jj*4]) = v;
            }
        }
        __syncthreads();
        // ---- compute: 4 k-steps of 8 (scalar LDS, conflict-free) ----
        #pragma unroll
        for (int ki = 0; ki < 4; ki++) {
            int kc = ki*8;
            float af[2][4];
            #pragma unroll
            for (int ma = 0; ma < 2; ma++) {
                int r = wm*32 + ma*16;
                af[ma][0] = As[(r+lr  )*AP + kc + lc    ];
                af[ma][1] = As[(r+lr+8)*AP + kc + lc    ];
                af[ma][2] = As[(r+lr  )*AP + kc + lc + 4];
                af[ma][3] = As[(r+lr+8)*AP + kc + lc + 4];
            }
            float bf[8][2];
            #pragma unroll
            for (int na = 0; na < 8; na++) {
                int n = wn*64 + na*8 + lr;
                bf[na][0] = Bs[n*AP + kc + lc    ];
                bf[na][1] = Bs[n*AP + kc + lc + 4];
            }
            #pragma unroll
            for (int ma = 0; ma < 2; ma++)
                #pragma unroll
                for (int na = 0; na < 8; na++)
                    mma_tf32(acc[ma][na],
                             reinterpret_cast<const uint32_t*>(af[ma]),
                             reinterpret_cast<const uint32_t*>(bf[na]));
        }
    }

    // ---- epilogue ----
    #pragma unroll
    for (int ma = 0; ma < 2; ma++) {
        int r1 = row0 + wm*32 + ma*16 + lr;
        int r2 = r1 + 8;
        #pragma unroll
        for (int na = 0; na < 8; na++) {
            int col = col0 + wn*64 + na*8 + lc*2;
            float bx = bias[col], by = bias[col+1];
            float2 o1 = make_float2(acc[ma][na][0] + bx, acc[ma][na][1] + by);
            float2 o2 = make_float2(acc[ma][na][2] + bx, acc[ma][na][3] + by);
            if (relu) {
                o1.x = fmaxf(o1.x,0.f); o1.y = fmaxf(o1.y,0.f);
                o2.x = fmaxf(o2.x,0.f); o2.y = fmaxf(o2.y,0.f);
            }
            if (r1 < Nrows) *reinterpret_cast<float2*>(out + (size_t)r1*NO + col) = o1;
            if (r2 < Nrows) *reinterpret_cast<float2*>(out + (size_t)r2*NO + col) = o2;
        }
    }
}

// ============ transpose ============
__global__ __launch_bounds__(256) void transpose_kernel(
    const float* __restrict__ in, float* __restrict__ out, int R, int C)
{
    __shared__ float t[32][33];
    int c0 = blockIdx.x*32, r0 = blockIdx.y*32;
    int x = threadIdx.x & 31, y = threadIdx.x >> 5;
    #pragma unroll
    for (int i = 0; i < 4; i++)
        t[y + i*8][x] = in[(size_t)(r0 + y + i*8)*C + c0 + x];
    __syncthreads();
    #pragma unroll
    for (int i = 0; i < 4; i++)
        out[(size_t)(c0 + y + i*8)*R + r0 + x] = t[x][y + i*8];
}

// ============ SIMT GEMM (tiny) ============
__global__ __launch_bounds__(256) void gemm_kernel(
    const float* __restrict__ A, const float* __restrict__ W,
    const float* __restrict__ bias, float* __restrict__ out,
    int N, int K, int NO, int relu)
{
    __shared__ float As[16][64];
    __shared__ float Bs[16][64];
    int t  = threadIdx.x;
    int tx = t & 15, ty = t >> 4;
    int row0 = blockIdx.y * 64;
    int col0 = blockIdx.x * 64;
    float acc[4][4] = {};
    for (int k0 = 0; k0 < K; k0 += 16) {
        {
            int r = t >> 2;
            int c4 = (t & 3) * 4;
            float4 av = make_float4(0.f,0.f,0.f,0.f);
            if (row0 + r < N)
                av = *reinterpret_cast<const float4*>(A + (size_t)(row0 + r) * K + k0 + c4);
            As[c4+0][r] = av.x; As[c4+1][r] = av.y; As[c4+2][r] = av.z; As[c4+3][r] = av.w;
        }
        {
            int r  = t >> 4;
            int c4 = (t & 15) * 4;
            float4 bv = *reinterpret_cast<const float4*>(W + (size_t)(k0 + r) * NO + col0 + c4);
            *reinterpret_cast<float4*>(&Bs[r][c4]) = bv;
        }
        __syncthreads();
        #pragma unroll
        for (int kk = 0; kk < 16; kk++) {
            float4 a4 = *reinterpret_cast<const float4*>(&As[kk][ty*4]);
            float4 b4 = *reinterpret_cast<const float4*>(&Bs[kk][tx*4]);
            float a[4] = {a4.x,a4.y,a4.z,a4.w};
            float b[4] = {b4.x,b4.y,b4.z,b4.w};
            #pragma unroll
            for (int i=0;i<4;i++)
                #pragma unroll
                for (int j=0;j<4;j++) acc[i][j] += a[i]*b[j];
        }
        __syncthreads();
    }
    float4 bb = *reinterpret_cast<const float4*>(bias + col0 + tx*4);
    #pragma unroll
    for (int i=0;i<4;i++) {
        int r = row0 + ty*4 + i;
        if (r >= N) continue;
        float4 o4;
        o4.x = acc[i][0] + bb.x; o4.y = acc[i][1] + bb.y;
        o4.z = acc[i][2] + bb.z; o4.w = acc[i][3] + bb.w;
        if (relu) {
            o4.x = fmaxf(o4.x,0.f); o4.y = fmaxf(o4.y,0.f);
            o4.z = fmaxf(o4.z,0.f); o4.w = fmaxf(o4.w,0.f);
        }
        *reinterpret_cast<float4*>(out + (size_t)r * NO + col0 + tx*4) = o4;
    }
}

// ============ warp reductions ============
__device__ __forceinline__ float warpMax(float v){
    #pragma unroll
    for (int o=16;o;o>>=1) v = fmaxf(v, __shfl_xor_sync(0xffffffffu, v, o));
    return v;
}
__device__ __forceinline__ float warpSum(float v){
    #pragma unroll
    for (int o=16;o;o>>=1) v += __shfl_xor_sync(0xffffffffu, v, o);
    return v;
}

// ============ top-k attention: 4 queries per warp iteration ============
#define Q_BLOCKS 6
#define SMEM_TOPK ((64*128 + 128*64 + 8*4*64)*4)
__global__ __launch_bounds__(256) void attn_topk_kernel(
    const float* __restrict__ q, const float* __restrict__ k,
    const float* __restrict__ v, float* __restrict__ o)
{
    extern __shared__ float sm[];
    float* Kt = sm;             // [64][128]
    float* Vs = Kt + 64*128;    // [128][64]
    float* sq = Vs + 128*64;    // [8 warps][4 q][64]

    int tid = threadIdx.x;
    int warp = tid >> 5, lane = tid & 31;
    int bh = blockIdx.x, b = bh / Hc, h = bh % Hc;

    for (int idx = tid; idx < 128*16; idx += 256) {
        int t = idx >> 4, j = idx & 15;
        size_t row = ((size_t)b*Tc + t)*Cc + h*64 + j*4;
        float4 kv = *reinterpret_cast<const float4*>(k + row);
        float4 vv = *reinterpret_cast<const float4*>(v + row);
        Kt[(j*4+0)*128 + t] = kv.x;
        Kt[(j*4+1)*128 + t] = kv.y;
        Kt[(j*4+2)*128 + t] = kv.z;
        Kt[(j*4+3)*128 + t] = kv.w;
        *reinterpret_cast<float4*>(&Vs[t*64 + j*4]) = vv;
    }
    __syncthreads();

    const int nq = (Mc + Q_BLOCKS - 1) / Q_BLOCKS;   // 215
    int q0 = blockIdx.y * nq;
    int qend = min(q0 + nq, Mc);
    float* sqw = sq + warp*256;

    for (int qi0 = q0 + warp*4; qi0 < qend; qi0 += 32) {
        // load up to 4 query rows
        #pragma unroll
        for (int f = 0; f < 2; f++) {
            int ff = lane + f*32;
            int qq = ff >> 4, j = ff & 15;
            int qi = qi0 + qq;
            if (qi < qend) {
                float4 qv = *reinterpret_cast<const float4*>(q + ((size_t)b*Mc + qi)*Cc + h*64 + j*4);
                *reinterpret_cast<float4*>(&sqw[qq*64 + j*4]) = qv;
            }
        }
        __syncwarp();
        // joint QK: Kt loads shared across 4 queries
        float s[4][4];
        #pragma unroll
        for (int qq=0;qq<4;qq++)
            #pragma unroll
            for (int j=0;j<4;j++) s[qq][j] = 0.f;
        #pragma unroll 4
        for (int d0 = 0; d0 < 64; d0 += 4) {
            float4 kk4[4];
            #pragma unroll
            for (int dd = 0; dd < 4; dd++)
                kk4[dd] = *reinterpret_cast<const float4*>(&Kt[(d0+dd)*128 + lane*4]);
            #pragma unroll
            for (int qq = 0; qq < 4; qq++) {
                float4 qd = *reinterpret_cast<const float4*>(&sqw[qq*64 + d0]);
                s[qq][0] += qd.x*kk4[0].x + qd.y*kk4[1].x + qd.z*kk4[2].x + qd.w*kk4[3].x;
                s[qq][1] += qd.x*kk4[0].y + qd.y*kk4[1].y + qd.z*kk4[2].y + qd.w*kk4[3].y;
                s[qq][2] += qd.x*kk4[0].z + qd.y*kk4[1].z + qd.z*kk4[2].z + qd.w*kk4[3].z;
                s[qq][3] += qd.x*kk4[0].w + qd.y*kk4[1].w + qd.z*kk4[2].w + qd.w*kk4[3].w;
            }
        }
        int d0v = lane*2;
        #pragma unroll
        for (int qq = 0; qq < 4; qq++) {
            int qi = qi0 + qq;
            if (qi >= qend) break;
            float sv[4];
            #pragma unroll
            for (int j=0;j<4;j++) sv[j] = s[qq][j]*0.125f;
            // top-8 threshold via iterative warp max
            float thr = F_INF, gmax = 0.f;
            #pragma unroll
            for (int it = 0; it < TOPK; it++) {
                float c = -F_INF;
                #pragma unroll
                for (int j=0;j<4;j++) c = fmaxf(c, (sv[j] < thr) ? sv[j] : -F_INF);
                float mx = warpMax(c);
                if (it == 0) gmax = mx;
                thr = mx;
            }
            float e[4], le = 0.f;
            #pragma unroll
            for (int j=0;j<4;j++){ e[j] = __expf(sv[j] - gmax); le += e[j]; }
            float inv = 1.f / warpSum(le);
            float p[4];
            #pragma unroll
            for (int j=0;j<4;j++) p[j] = (sv[j] >= thr) ? e[j]*inv : 0.f;
            // sparse AV
            float2 acc = make_float2(0.f, 0.f);
            #pragma unroll
            for (int j=0;j<4;j++) {
                unsigned msk = __ballot_sync(0xffffffffu, p[j] != 0.f);
                while (msk) {
                    int src = __ffs(msk) - 1;
                    msk &= msk - 1;
                    float pv = __shfl_sync(0xffffffffu, p[j], src);
                    int key = src*4 + j;
                    float2 vv = *reinterpret_cast<const float2*>(&Vs[key*64 + d0v]);
                    acc.x += pv*vv.x; acc.y += pv*vv.y;
                }
            }
            *reinterpret_cast<float2*>(o + ((size_t)b*Mc + qi)*Cc + h*64 + d0v) = acc;
        }
    }
}

// ============ hx attention: joint-4 QK and AV ============
#define SMEM_HX ((64*128 + 128*64 + 32*64 + 8*4*128)*4)
__global__ __launch_bounds__(256) void attn_hx_kernel(
    const float* __restrict__ q, const float* __restrict__ k,
    const float* __restrict__ v, float* __restrict__ o)
{
    extern __shared__ float sm[];
    float* Kt = sm;              // [64][128]
    float* Vs = Kt + 64*128;     // [128][64]
    float* sq = Vs + 128*64;     // [32][64]
    float* ps = sq + 32*64;      // [8 warps][4 q][128]

    int tid = threadIdx.x;
    int warp = tid >> 5, lane = tid & 31;
    int bh = blockIdx.x, b = bh / Hc, h = bh % Hc;
    int q0 = blockIdx.y * 32;

    for (int idx = tid; idx < 32*16; idx += 256) {
        int qi = idx >> 4, j = idx & 15;
        float4 qv = *reinterpret_cast<const float4*>(q + ((size_t)b*Tc + q0 + qi)*Cc + h*64 + j*4);
        *reinterpret_cast<float4*>(&sq[qi*64 + j*4]) = qv;
    }

    float m[4], den[4];
    float2 acc[4];
    #pragma unroll
    for (int i=0;i<4;i++){ m[i] = -F_INF; den[i] = 0.f; acc[i] = make_float2(0.f,0.f); }
    int d0v = lane*2;
    float* psw = ps + warp*512;

    for (int c0 = 0; c0 < Mc; c0 += 128) {
        int nk = min(128, Mc - c0);
        __syncthreads();
        for (int idx = tid; idx < 128*16; idx += 256) {
            int t = idx >> 4, j = idx & 15;
            float4 kv = make_float4(0.f,0.f,0.f,0.f), vv = kv;
            if (t < nk) {
                size_t row = ((size_t)b*Mc + c0 + t)*Cc + h*64 + j*4;
                kv = *reinterpret_cast<const float4*>(k + row);
                vv = *reinterpret_cast<const float4*>(v + row);
            }
            Kt[(j*4+0)*128 + t] = kv.x;
            Kt[(j*4+1)*128 + t] = kv.y;
            Kt[(j*4+2)*128 + t] = kv.z;
            Kt[(j*4+3)*128 + t] = kv.w;
            *reinterpret_cast<float4*>(&Vs[t*64 + j*4]) = vv;
        }
        __syncthreads();

        // joint QK for the warp's 4 queries
        float s[4][4];
        #pragma unroll
        for (int i=0;i<4;i++)
            #pragma unroll
            for (int j=0;j<4;j++) s[i][j] = 0.f;
        #pragma unroll 4
        for (int d0 = 0; d0 < 64; d0 += 4) {
            float4 kk4[4];
            #pragma unroll
            for (int dd = 0; dd < 4; dd++)
                kk4[dd] = *reinterpret_cast<const float4*>(&Kt[(d0+dd)*128 + lane*4]);
            #pragma unroll
            for (int i = 0; i < 4; i++) {
                float4 qd = *reinterpret_cast<const float4*>(&sq[(warp*4+i)*64 + d0]);
                s[i][0] += qd.x*kk4[0].x + qd.y*kk4[1].x + qd.z*kk4[2].x + qd.w*kk4[3].x;
                s[i][1] += qd.x*kk4[0].y + qd.y*kk4[1].y + qd.z*kk4[2].y + qd.w*kk4[3].y;
                s[i][2] += qd.x*kk4[0].z + qd.y*kk4[1].z + qd.z*kk4[2].z + qd.w*kk4[3].z;
                s[i][3] += qd.x*kk4[0].w + qd.y*kk4[1].w + qd.z*kk4[2].w + qd.w*kk4[3].w;
            }
        }
        // per-query softmax state update; stash e-vectors
        #pragma unroll
        for (int i = 0; i < 4; i++) {
            float lm = -F_INF;
            #pragma unroll
            for (int j=0;j<4;j++) {
                s[i][j] = (lane*4 + j < nk) ? s[i][j]*0.125f : -F_INF;
                lm = fmaxf(lm, s[i][j]);
            }
            float tmax = warpMax(lm);
            float newm = fmaxf(m[i], tmax);
            float f = __expf(m[i] - newm);
            float e[4], le = 0.f;
            #pragma unroll
            for (int j=0;j<4;j++){ e[j] = __expf(s[i][j] - newm); le += e[j]; }
            den[i] = den[i]*f + warpSum(le);
            m[i] = newm;
            acc[i].x *= f; acc[i].y *= f;
            *reinterpret_cast<float4*>(&psw[i*128 + lane*4]) = make_float4(e[0],e[1],e[2],e[3]);
        }
        __syncwarp();
        // joint AV: one V pass for 4 queries
        #pragma unroll 4
        for (int kk = 0; kk < 128; kk++) {
            float2 vv = *reinterpret_cast<const float2*>(&Vs[kk*64 + d0v]);
            float p0 = psw[0*128 + kk], p1 = psw[1*128 + kk];
            float p2 = psw[2*128 + kk], p3 = psw[3*128 + kk];
            acc[0].x += p0*vv.x; acc[0].y += p0*vv.y;
            acc[1].x += p1*vv.x; acc[1].y += p1*vv.y;
            acc[2].x += p2*vv.x; acc[2].y += p2*vv.y;
            acc[3].x += p3*vv.x; acc[3].y += p3*vv.y;
        }
    }
    #pragma unroll
    for (int i=0;i<4;i++) {
        int qi = q0 + warp*4 + i;
        float invd = 1.f / den[i];
        float2 ov = make_float2(acc[i].x*invd, acc[i].y*invd);
        *reinterpret_cast<float2*>(o + ((size_t)b*Tc + qi)*Cc + h*64 + d0v) = ov;
    }
}

// ============ add + layernorm ============
__global__ __launch_bounds__(256) void add_ln_kernel(
    const float* __restrict__ x, const float* __restrict__ r,
    const float* __restrict__ g, const float* __restrict__ bb,
    float* __restrict__ out, int nrows)
{
    int warp = (blockIdx.x * blockDim.x + threadIdx.x) >> 5;
    int lane = threadIdx.x & 31;
    if (warp >= nrows) return;
    const float* xr = x + (size_t)warp * Cc;
    const float* rr = r + (size_t)warp * Cc;
    float vals[16];
    float s = 0.f;
    #pragma unroll
    for (int i=0;i<16;i++) { float vv = xr[lane + i*32] + rr[lane + i*32]; vals[i] = vv; s += vv; }
    #pragma unroll
    for (int o2=16;o2;o2>>=1) s += __shfl_xor_sync(0xffffffffu, s, o2);
    float mu = s * (1.f/512.f);
    float vs = 0.f;
    #pragma unroll
    for (int i=0;i<16;i++){ float d = vals[i]-mu; vs += d*d; }
    #pragma unroll
    for (int o2=16;o2;o2>>=1) vs += __shfl_xor_sync(0xffffffffu, vs, o2);
    float rstd = rsqrtf(vs*(1.f/512.f) + 1e-5f);
    float* outr = out + (size_t)warp * Cc;
    #pragma unroll
    for (int i=0;i<16;i++){ int cc = lane + i*32; outr[cc] = (vals[i]-mu)*rstd*g[cc] + bb[cc]; }
}

// ============ misc elementwise ============
__global__ void repmean_kernel(const float* __restrict__ inp, const float* __restrict__ rep_w,
                               float* __restrict__ out)
{
    int b = blockIdx.x, c = threadIdx.x;
    const float* base = inp + (size_t)b*Tc*Cc + c;
    float rw = rep_w[c];
    float s = 0.f;
    for (int t=0;t<Tc;t++) s += fmaxf(rw * base[(size_t)t*Cc], 0.f);
    out[b*Cc + c] = s * (1.f/Tc);
}

__global__ void gate_kernel(const float* __restrict__ gates, const float* __restrict__ gi,
                            const float* __restrict__ mem_final, const float* __restrict__ mem0,
                            const float* __restrict__ ib, const float* __restrict__ fb,
                            float* __restrict__ nm)
{
    size_t n = (size_t)Bc*Mc*Cc;
    size_t i = (size_t)blockIdx.x*blockDim.x + threadIdx.x;
    size_t st = (size_t)gridDim.x*blockDim.x;
    float ibv = ib[0], fbv = fb[0];
    for (; i < n; i += st) {
        int c = (int)(i % Cc);
        size_t bm = i / Cc;
        int b = (int)(bm / Mc);
        float gI = gates[bm*2*Cc + c]      + gi[b*2*Cc + c]      + ibv;
        float gF = gates[bm*2*Cc + Cc + c] + gi[b*2*Cc + Cc + c] + fbv;
        float igv = 1.f/(1.f + __expf(-gI));
        float fgv = 1.f/(1.f + __expf(-gF));
        nm[i] = igv * tanhf(mem_final[i]) + fgv * mem0[i];
    }
}

// ============ launch ============
extern "C" void kernel_launch(void* const* d_in, const int* in_sizes, int n_in,
                              void* d_out, int out_size)
{
    const float* ipts   = (const float*)d_in[0];
    const float* memory = (const float*)d_in[1];
    const float* Wq=(const float*)d_in[2],  *bq=(const float*)d_in[3];
    const float* Wk=(const float*)d_in[4],  *bk=(const float*)d_in[5];
    const float* Wv=(const float*)d_in[6],  *bv=(const float*)d_in[7];
    const float* Wm=(const float*)d_in[8],  *bm=(const float*)d_in[9];
    const float* g1=(const float*)d_in[10], *b1=(const float*)d_in[11];
    const float* g2=(const float*)d_in[12], *b2=(const float*)d_in[13];
    const float* Wp=(const float*)d_in[14], *bp=(const float*)d_in[15];
    const float* rep_w=(const float*)d_in[16];
    const float* Wig=(const float*)d_in[17], *big=(const float*)d_in[18];
    const float* Wmg=(const float*)d_in[19], *bmg=(const float*)d_in[20];
    const float* fb=(const float*)d_in[21], *ib=(const float*)d_in[22];

    float* out_nm = (float*)d_out;
    float* out_hx = out_nm + (size_t)Bc*Mc*Cc;

    float *inp,*mem,*qb,*kb,*vb,*ao,*h1,*h2,*gt,*rm,*gi;
    float *WqT,*WkT,*WvT,*WmT,*WpT,*WmgT;
    cudaGetSymbolAddress((void**)&inp, d_inp);
    cudaGetSymbolAddress((void**)&mem, d_mem);
    cudaGetSymbolAddress((void**)&qb,  d_qb);
    cudaGetSymbolAddress((void**)&kb,  d_kb);
    cudaGetSymbolAddress((void**)&vb,  d_vb);
    cudaGetSymbolAddress((void**)&ao,  d_ao);
    cudaGetSymbolAddress((void**)&h1,  d_h1);
    cudaGetSymbolAddress((void**)&h2,  d_h2);
    cudaGetSymbolAddress((void**)&gt,  d_gt);
    cudaGetSymbolAddress((void**)&rm,  d_rm);
    cudaGetSymbolAddress((void**)&gi,  d_gi);
    cudaGetSymbolAddress((void**)&WqT, d_WqT);
    cudaGetSymbolAddress((void**)&WkT, d_WkT);
    cudaGetSymbolAddress((void**)&WvT, d_WvT);
    cudaGetSymbolAddress((void**)&WmT, d_WmT);
    cudaGetSymbolAddress((void**)&WpT, d_WpT);
    cudaGetSymbolAddress((void**)&WmgT, d_WmgT);

    cudaFuncSetAttribute(attn_topk_kernel, cudaFuncAttributeMaxDynamicSharedMemorySize, SMEM_TOPK);
    cudaFuncSetAttribute(attn_hx_kernel,   cudaFuncAttributeMaxDynamicSharedMemorySize, SMEM_HX);
    cudaFuncSetAttribute(tf32_gemm_kernel, cudaFuncAttributeMaxDynamicSharedMemorySize, TG_SMEM);

    transpose_kernel<<<dim3(16,16), 256>>>(Wq, WqT, Cc, Cc);
    transpose_kernel<<<dim3(16,16), 256>>>(Wk, WkT, Cc, Cc);
    transpose_kernel<<<dim3(16,16), 256>>>(Wv, WvT, Cc, Cc);
    transpose_kernel<<<dim3(16,16), 256>>>(Wm, WmT, Cc, Cc);
    transpose_kernel<<<dim3(16,16), 256>>>(Wp, WpT, Cc, Cc);
    transpose_kernel<<<dim3(32,16), 256>>>(Wmg, WmgT, Cc, 2*Cc);

    auto tgemm = [&](const float* A, const float* WT, const float* bias, float* o,
                     int N, int NO, int relu, int dotanh){
        tf32_gemm_kernel<<<dim3(NO/128, (N+127)/128), 256, TG_SMEM>>>(
            A, WT, bias, o, N, Cc, NO, relu, dotanh);
    };

    // inp = ipts @ Wp + bp ; k,v from inp are LOOP-INVARIANT
    tgemm(ipts, WpT, bp, inp, Bc*Tc, Cc, 0, 0);
    tgemm(inp,  WkT, bk, kb,  Bc*Tc, Cc, 0, 0);
    tgemm(inp,  WvT, bv, vb,  Bc*Tc, Cc, 0, 0);
    cudaMemcpyAsync(mem, memory, sizeof(float)*(size_t)Bc*Mc*Cc, cudaMemcpyDeviceToDevice);

    for (int blk = 0; blk < NBLK; blk++) {
        tgemm(mem, WqT, bq, qb, Bc*Mc, Cc, 0, 0);
        attn_topk_kernel<<<dim3(Bc*Hc, Q_BLOCKS), 256, SMEM_TOPK>>>(qb, kb, vb, ao);
        add_ln_kernel<<<(Bc*Mc + 7)/8, 256>>>(mem, ao, g1, b1, mem, Bc*Mc);
        tgemm(mem, WmT, bm, h1, Bc*Mc, Cc, 1, 0);
        tgemm(h1,  WmT, bm, h2, Bc*Mc, Cc, 1, 0);
        add_ln_kernel<<<(Bc*Mc + 7)/8, 256>>>(mem, h2, g2, b2, mem, Bc*Mc);
    }

    // gates
    repmean_kernel<<<Bc, Cc>>>(inp, rep_w, rm);
    gemm_kernel<<<dim3(2*Cc/64, 1), 256>>>(rm, Wig, big, gi, Bc, Cc, 2*Cc, 0);
    tgemm(memory, WmgT, bmg, gt, Bc*Mc, 2*Cc, 0, 1);   // tanh fused into A staging
    gate_kernel<<<2048, 256>>>(gt, gi, mem, memory, ib, fb, out_nm);

    // hx = attention(q from inp, k/v from next_memory), no topk
    tgemm(inp,    WqT, bq, qb, Bc*Tc, Cc, 0, 0);
    tgemm(out_nm, WkT, bk, kb, Bc*Mc, Cc, 0, 0);
    tgemm(out_nm, WvT, bv, vb, Bc*Mc, Cc, 0, 0);
    attn_hx_kernel<<<dim3(Bc*Hc, Tc/32), 256, SMEM_HX>>>(qb, kb, vb, out_hx);
}

// round 6
// speedup vs baseline: 3.4620x; 1.0121x over previous
#include <cuda_runtime.h>
#include <math.h>
#include <stdint.h>

#define Bc 32
#define Tc 128
#define Mc 1290
#define Cc 512
#define Hc 8
#define NBLK 4
#define TOPK 8

static __device__ float d_inp[Bc*Tc*Cc];
static __device__ float d_mem[(size_t)Bc*Mc*Cc];
static __device__ float d_qb [(size_t)Bc*Mc*Cc];
static __device__ float d_kb [(size_t)Bc*Mc*Cc];
static __device__ float d_vb [(size_t)Bc*Mc*Cc];
static __device__ float d_ao [(size_t)Bc*Mc*Cc];
static __device__ float d_h1 [(size_t)Bc*Mc*Cc];
static __device__ float d_h2 [(size_t)Bc*Mc*Cc];
static __device__ float d_gt [(size_t)Bc*Mc*2*Cc];
static __device__ float d_rm [Bc*Cc];
static __device__ float d_gi [Bc*2*Cc];
static __device__ float d_WqT[Cc*Cc];
static __device__ float d_WkT[Cc*Cc];
static __device__ float d_WvT[Cc*Cc];
static __device__ float d_WmT[Cc*Cc];
static __device__ float d_WpT[Cc*Cc];
static __device__ float d_WmgT[Cc*2*Cc];

#define F_INF __int_as_float(0x7f800000)

__device__ __forceinline__ uint32_t smem_u32(const void* p){
    uint32_t a;
    asm("{ .reg .u64 t; cvta.to.shared.u64 t, %1; cvt.u32.u64 %0, t; }" : "=r"(a) : "l"(p));
    return a;
}
__device__ __forceinline__ float to_tf32(float x){
    float r;
    asm("cvt.rna.tf32.f32 %0, %1;" : "=f"(r) : "f"(x));
    return r;
}
__device__ __forceinline__ void cpasync16(uint32_t dst, const void* src, bool pred){
    int sz = pred ? 16 : 0;
    asm volatile("cp.async.cg.shared.global [%0], [%1], 16, %2;"
                 :: "r"(dst), "l"(src), "r"(sz) : "memory");
}
__device__ __forceinline__ void cp_commit(){
    asm volatile("cp.async.commit_group;" ::: "memory");
}
__device__ __forceinline__ void mma_tf32(float* d, const uint32_t* a, const uint32_t* b){
    asm volatile("mma.sync.aligned.m16n8k8.row.col.f32.tf32.tf32.f32 "
        "{%0,%1,%2,%3}, {%4,%5,%6,%7}, {%8,%9}, {%0,%1,%2,%3};"
        : "+f"(d[0]), "+f"(d[1]), "+f"(d[2]), "+f"(d[3])
        : "r"(a[0]), "r"(a[1]), "r"(a[2]), "r"(a[3]), "r"(b[0]), "r"(b[1]));
}

// ============ tf32 mma.sync GEMM, cp.async 2-stage pipeline ============
// block 128x128, K-chunk 32, 256 thr = 8 warps (4m x 2n), warp tile 32x64.
// SMEM natural layout pitch 36; WT pre-converted to tf32; A converted at frag load.
#define TGK 32
#define AP 36
#define CH (128*AP)
#define TG_SMEM (4*CH*4)
__global__ __launch_bounds__(256) void tf32_gemm_kernel(
    const float* __restrict__ A, const float* __restrict__ WT,
    const float* __restrict__ bias, float* __restrict__ out,
    int Nrows, int K, int NO, int relu, int dotanh)
{
    extern __shared__ float sm[];
    int tid = threadIdx.x;
    int wid = tid >> 5, lane = tid & 31;
    int wm = wid & 3, wn = wid >> 2;
    int lr = lane >> 2, lc = lane & 3;
    int row0 = blockIdx.y * 128;
    int col0 = blockIdx.x * 128;

    float acc[2][8][4];
    #pragma unroll
    for (int i=0;i<2;i++)
        #pragma unroll
        for (int j=0;j<8;j++)
            #pragma unroll
            for (int l=0;l<4;l++) acc[i][j][l] = 0.f;

    int srow = tid >> 1;
    int skb  = (tid & 1) * 16;
    bool apred = (row0 + srow) < Nrows;
    const float* abase = A + (size_t)(row0 + srow)*K + skb;
    const float* bbase = WT + (size_t)(col0 + srow)*K + skb;
    uint32_t sdst_off = smem_u32(&sm[srow*AP + skb]);

    const int nc = K / TGK;   // 16

    auto issue = [&](int c){
        int st = c & 1;
        uint32_t ad = sdst_off + st*2*CH*4;
        uint32_t bd = ad + CH*4;
        int k0 = c * TGK;
        #pragma unroll
        for (int jj = 0; jj < 4; jj++) {
            cpasync16(ad + jj*16, abase + k0 + jj*4, apred);
            cpasync16(bd + jj*16, bbase + k0 + jj*4, true);
        }
        cp_commit();
    };

    issue(0);
    for (int c = 0; c < nc; c++) {
        if (c + 1 < nc) {
            issue(c + 1);
            asm volatile("cp.async.wait_group 1;" ::: "memory");
        } else {
            asm volatile("cp.async.wait_group 0;" ::: "memory");
        }
        __syncthreads();
        const float* As = sm + (c & 1)*2*CH;
        const float* Bs = As + CH;
        #pragma unroll
        for (int ki = 0; ki < 4; ki++) {
            int kc = ki*8;
            float af[2][4];
            #pragma unroll
            for (int ma = 0; ma < 2; ma++) {
                int r = wm*32 + ma*16;
                float a0 = As[(r+lr  )*AP + kc + lc    ];
                float a1 = As[(r+lr+8)*AP + kc + lc    ];
                float a2 = As[(r+lr  )*AP + kc + lc + 4];
                float a3 = As[(r+lr+8)*AP + kc + lc + 4];
                if (dotanh) { a0=tanhf(a0); a1=tanhf(a1); a2=tanhf(a2); a3=tanhf(a3); }
                af[ma][0]=to_tf32(a0); af[ma][1]=to_tf32(a1);
                af[ma][2]=to_tf32(a2); af[ma][3]=to_tf32(a3);
            }
            float bf[8][2];
            #pragma unroll
            for (int na = 0; na < 8; na++) {
                int n = wn*64 + na*8 + lr;
                bf[na][0] = Bs[n*AP + kc + lc    ];
                bf[na][1] = Bs[n*AP + kc + lc + 4];
            }
            #pragma unroll
            for (int ma = 0; ma < 2; ma++)
                #pragma unroll
                for (int na = 0; na < 8; na++)
                    mma_tf32(acc[ma][na],
                             reinterpret_cast<const uint32_t*>(af[ma]),
                             reinterpret_cast<const uint32_t*>(bf[na]));
        }
        __syncthreads();
    }

    #pragma unroll
    for (int ma = 0; ma < 2; ma++) {
        int r1 = row0 + wm*32 + ma*16 + lr;
        int r2 = r1 + 8;
        #pragma unroll
        for (int na = 0; na < 8; na++) {
            int col = col0 + wn*64 + na*8 + lc*2;
            float bx = bias[col], by = bias[col+1];
            float2 o1 = make_float2(acc[ma][na][0] + bx, acc[ma][na][1] + by);
            float2 o2 = make_float2(acc[ma][na][2] + bx, acc[ma][na][3] + by);
            if (relu) {
                o1.x = fmaxf(o1.x,0.f); o1.y = fmaxf(o1.y,0.f);
                o2.x = fmaxf(o2.x,0.f); o2.y = fmaxf(o2.y,0.f);
            }
            if (r1 < Nrows) *reinterpret_cast<float2*>(out + (size_t)r1*NO + col) = o1;
            if (r2 < Nrows) *reinterpret_cast<float2*>(out + (size_t)r2*NO + col) = o2;
        }
    }
}

// ============ transpose + tf32 pre-convert ============
__global__ __launch_bounds__(256) void transpose_kernel(
    const float* __restrict__ in, float* __restrict__ out, int R, int C)
{
    __shared__ float t[32][33];
    int c0 = blockIdx.x*32, r0 = blockIdx.y*32;
    int x = threadIdx.x & 31, y = threadIdx.x >> 5;
    #pragma unroll
    for (int i = 0; i < 4; i++)
        t[y + i*8][x] = in[(size_t)(r0 + y + i*8)*C + c0 + x];
    __syncthreads();
    #pragma unroll
    for (int i = 0; i < 4; i++)
        out[(size_t)(c0 + y + i*8)*R + r0 + x] = to_tf32(t[x][y + i*8]);
}

// ============ SIMT GEMM (tiny) ============
__global__ __launch_bounds__(256) void gemm_kernel(
    const float* __restrict__ A, const float* __restrict__ W,
    const float* __restrict__ bias, float* __restrict__ out,
    int N, int K, int NO, int relu)
{
    __shared__ float As[16][64];
    __shared__ float Bs[16][64];
    int t  = threadIdx.x;
    int tx = t & 15, ty = t >> 4;
    int row0 = blockIdx.y * 64;
    int col0 = blockIdx.x * 64;
    float acc[4][4] = {};
    for (int k0 = 0; k0 < K; k0 += 16) {
        {
            int r = t >> 2;
            int c4 = (t & 3) * 4;
            float4 av = make_float4(0.f,0.f,0.f,0.f);
            if (row0 + r < N)
                av = *reinterpret_cast<const float4*>(A + (size_t)(row0 + r) * K + k0 + c4);
            As[c4+0][r] = av.x; As[c4+1][r] = av.y; As[c4+2][r] = av.z; As[c4+3][r] = av.w;
        }
        {
            int r  = t >> 4;
            int c4 = (t & 15) * 4;
            float4 bv = *reinterpret_cast<const float4*>(W + (size_t)(k0 + r) * NO + col0 + c4);
            *reinterpret_cast<float4*>(&Bs[r][c4]) = bv;
        }
        __syncthreads();
        #pragma unroll
        for (int kk = 0; kk < 16; kk++) {
            float4 a4 = *reinterpret_cast<const float4*>(&As[kk][ty*4]);
            float4 b4 = *reinterpret_cast<const float4*>(&Bs[kk][tx*4]);
            float a[4] = {a4.x,a4.y,a4.z,a4.w};
            float b[4] = {b4.x,b4.y,b4.z,b4.w};
            #pragma unroll
            for (int i=0;i<4;i++)
                #pragma unroll
                for (int j=0;j<4;j++) acc[i][j] += a[i]*b[j];
        }
        __syncthreads();
    }
    float4 bb = *reinterpret_cast<const float4*>(bias + col0 + tx*4);
    #pragma unroll
    for (int i=0;i<4;i++) {
        int r = row0 + ty*4 + i;
        if (r >= N) continue;
        float4 o4;
        o4.x = acc[i][0] + bb.x; o4.y = acc[i][1] + bb.y;
        o4.z = acc[i][2] + bb.z; o4.w = acc[i][3] + bb.w;
        if (relu) {
            o4.x = fmaxf(o4.x,0.f); o4.y = fmaxf(o4.y,0.f);
            o4.z = fmaxf(o4.z,0.f); o4.w = fmaxf(o4.w,0.f);
        }
        *reinterpret_cast<float4*>(out + (size_t)r * NO + col0 + tx*4) = o4;
    }
}

// ============ warp reductions (x4-interleaved: shared latency chain) ============
__device__ __forceinline__ void warpMax4(float* c){
    #pragma unroll
    for (int o=16;o;o>>=1){
        #pragma unroll
        for (int qq=0;qq<4;qq++) c[qq] = fmaxf(c[qq], __shfl_xor_sync(0xffffffffu, c[qq], o));
    }
}
__device__ __forceinline__ void warpSum4(float* c){
    #pragma unroll
    for (int o=16;o;o>>=1){
        #pragma unroll
        for (int qq=0;qq<4;qq++) c[qq] += __shfl_xor_sync(0xffffffffu, c[qq], o);
    }
}

// ============ top-k attention: 4 queries/warp, interleaved reductions ============
#define Q_BLOCKS 6
#define SMEM_TOPK ((64*128 + 128*64 + 8*4*64)*4)
__global__ __launch_bounds__(256) void attn_topk_kernel(
    const float* __restrict__ q, const float* __restrict__ k,
    const float* __restrict__ v, float* __restrict__ o)
{
    extern __shared__ float sm[];
    float* Kt = sm;             // [64][128]
    float* Vs = Kt + 64*128;    // [128][64]
    float* sq = Vs + 128*64;    // [8 warps][4 q][64]

    int tid = threadIdx.x;
    int warp = tid >> 5, lane = tid & 31;
    int bh = blockIdx.x, b = bh / Hc, h = bh % Hc;

    for (int idx = tid; idx < 128*16; idx += 256) {
        int t = idx >> 4, j = idx & 15;
        size_t row = ((size_t)b*Tc + t)*Cc + h*64 + j*4;
        float4 kv = *reinterpret_cast<const float4*>(k + row);
        float4 vv = *reinterpret_cast<const float4*>(v + row);
        Kt[(j*4+0)*128 + t] = kv.x;
        Kt[(j*4+1)*128 + t] = kv.y;
        Kt[(j*4+2)*128 + t] = kv.z;
        Kt[(j*4+3)*128 + t] = kv.w;
        *reinterpret_cast<float4*>(&Vs[t*64 + j*4]) = vv;
    }
    __syncthreads();

    const int nq = (Mc + Q_BLOCKS - 1) / Q_BLOCKS;
    int q0 = blockIdx.y * nq;
    int qend = min(q0 + nq, Mc);
    float* sqw = sq + warp*256;

    for (int qi0 = q0 + warp*4; qi0 < qend; qi0 += 32) {
        #pragma unroll
        for (int f = 0; f < 2; f++) {
            int ff = lane + f*32;
            int qq = ff >> 4, j = ff & 15;
            int qi = qi0 + qq;
            if (qi < qend) {
                float4 qv = *reinterpret_cast<const float4*>(q + ((size_t)b*Mc + qi)*Cc + h*64 + j*4);
                *reinterpret_cast<float4*>(&sqw[qq*64 + j*4]) = qv;
            }
        }
        __syncwarp();
        // joint QK
        float s[4][4];
        #pragma unroll
        for (int qq=0;qq<4;qq++)
            #pragma unroll
            for (int j=0;j<4;j++) s[qq][j] = 0.f;
        #pragma unroll 4
        for (int d0 = 0; d0 < 64; d0 += 4) {
            float4 kk4[4];
            #pragma unroll
            for (int dd = 0; dd < 4; dd++)
                kk4[dd] = *reinterpret_cast<const float4*>(&Kt[(d0+dd)*128 + lane*4]);
            #pragma unroll
            for (int qq = 0; qq < 4; qq++) {
                float4 qd = *reinterpret_cast<const float4*>(&sqw[qq*64 + d0]);
                s[qq][0] += qd.x*kk4[0].x + qd.y*kk4[1].x + qd.z*kk4[2].x + qd.w*kk4[3].x;
                s[qq][1] += qd.x*kk4[0].y + qd.y*kk4[1].y + qd.z*kk4[2].y + qd.w*kk4[3].y;
                s[qq][2] += qd.x*kk4[0].z + qd.y*kk4[1].z + qd.z*kk4[2].z + qd.w*kk4[3].z;
                s[qq][3] += qd.x*kk4[0].w + qd.y*kk4[1].w + qd.z*kk4[2].w + qd.w*kk4[3].w;
            }
        }
        #pragma unroll
        for (int qq=0;qq<4;qq++)
            #pragma unroll
            for (int j=0;j<4;j++) s[qq][j] *= 0.125f;

        // batched top-8: 8 rounds, 4 queries interleaved per round
        float thr[4], gmax[4], c[4];
        #pragma unroll
        for (int qq=0;qq<4;qq++)
            c[qq] = fmaxf(fmaxf(s[qq][0],s[qq][1]), fmaxf(s[qq][2],s[qq][3]));
        warpMax4(c);
        #pragma unroll
        for (int qq=0;qq<4;qq++){ gmax[qq] = c[qq]; thr[qq] = c[qq]; }
        #pragma unroll
        for (int it = 1; it < TOPK; it++) {
            #pragma unroll
            for (int qq=0;qq<4;qq++){
                float m = -F_INF;
                #pragma unroll
                for (int j=0;j<4;j++) m = fmaxf(m, (s[qq][j] < thr[qq]) ? s[qq][j] : -F_INF);
                c[qq] = m;
            }
            warpMax4(c);
            #pragma unroll
            for (int qq=0;qq<4;qq++) thr[qq] = c[qq];
        }
        // batched softmax denom
        float e[4][4], le[4];
        #pragma unroll
        for (int qq=0;qq<4;qq++){
            le[qq] = 0.f;
            #pragma unroll
            for (int j=0;j<4;j++){ e[qq][j] = __expf(s[qq][j] - gmax[qq]); le[qq] += e[qq][j]; }
        }
        warpSum4(le);

        int d0v = lane*2;
        #pragma unroll
        for (int qq = 0; qq < 4; qq++) {
            int qi = qi0 + qq;
            if (qi >= qend) break;
            float inv = 1.f / le[qq];
            float p[4];
            #pragma unroll
            for (int j=0;j<4;j++) p[j] = (s[qq][j] >= thr[qq]) ? e[qq][j]*inv : 0.f;
            float2 acc = make_float2(0.f, 0.f);
            #pragma unroll
            for (int j=0;j<4;j++) {
                unsigned msk = __ballot_sync(0xffffffffu, p[j] != 0.f);
                while (msk) {
                    int src = __ffs(msk) - 1;
                    msk &= msk - 1;
                    float pv = __shfl_sync(0xffffffffu, p[j], src);
                    int key = src*4 + j;
                    float2 vv = *reinterpret_cast<const float2*>(&Vs[key*64 + d0v]);
                    acc.x += pv*vv.x; acc.y += pv*vv.y;
                }
            }
            *reinterpret_cast<float2*>(o + ((size_t)b*Mc + qi)*Cc + h*64 + d0v) = acc;
        }
    }
}

// ============ hx attention: joint-4 QK/AV, interleaved reductions ============
#define SMEM_HX ((64*128 + 128*64 + 32*64 + 8*4*128)*4)
__global__ __launch_bounds__(256) void attn_hx_kernel(
    const float* __restrict__ q, const float* __restrict__ k,
    const float* __restrict__ v, float* __restrict__ o)
{
    extern __shared__ float sm[];
    float* Kt = sm;              // [64][128]
    float* Vs = Kt + 64*128;     // [128][64]
    float* sq = Vs + 128*64;     // [32][64]
    float* ps = sq + 32*64;      // [8 warps][4 q][128]

    int tid = threadIdx.x;
    int warp = tid >> 5, lane = tid & 31;
    int bh = blockIdx.x, b = bh / Hc, h = bh % Hc;
    int q0 = blockIdx.y * 32;

    for (int idx = tid; idx < 32*16; idx += 256) {
        int qi = idx >> 4, j = idx & 15;
        float4 qv = *reinterpret_cast<const float4*>(q + ((size_t)b*Tc + q0 + qi)*Cc + h*64 + j*4);
        *reinterpret_cast<float4*>(&sq[qi*64 + j*4]) = qv;
    }

    float m[4], den[4];
    float2 acc[4];
    #pragma unroll
    for (int i=0;i<4;i++){ m[i] = -F_INF; den[i] = 0.f; acc[i] = make_float2(0.f,0.f); }
    int d0v = lane*2;
    float* psw = ps + warp*512;

    for (int c0 = 0; c0 < Mc; c0 += 128) {
        int nk = min(128, Mc - c0);
        __syncthreads();
        for (int idx = tid; idx < 128*16; idx += 256) {
            int t = idx >> 4, j = idx & 15;
            float4 kv = make_float4(0.f,0.f,0.f,0.f), vv = kv;
            if (t < nk) {
                size_t row = ((size_t)b*Mc + c0 + t)*Cc + h*64 + j*4;
                kv = *reinterpret_cast<const float4*>(k + row);
                vv = *reinterpret_cast<const float4*>(v + row);
            }
            Kt[(j*4+0)*128 + t] = kv.x;
            Kt[(j*4+1)*128 + t] = kv.y;
            Kt[(j*4+2)*128 + t] = kv.z;
            Kt[(j*4+3)*128 + t] = kv.w;
            *reinterpret_cast<float4*>(&Vs[t*64 + j*4]) = vv;
        }
        __syncthreads();

        float s[4][4];
        #pragma unroll
        for (int i=0;i<4;i++)
            #pragma unroll
            for (int j=0;j<4;j++) s[i][j] = 0.f;
        #pragma unroll 4
        for (int d0 = 0; d0 < 64; d0 += 4) {
            float4 kk4[4];
            #pragma unroll
            for (int dd = 0; dd < 4; dd++)
                kk4[dd] = *reinterpret_cast<const float4*>(&Kt[(d0+dd)*128 + lane*4]);
            #pragma unroll
            for (int i = 0; i < 4; i++) {
                float4 qd = *reinterpret_cast<const float4*>(&sq[(warp*4+i)*64 + d0]);
                s[i][0] += qd.x*kk4[0].x + qd.y*kk4[1].x + qd.z*kk4[2].x + qd.w*kk4[3].x;
                s[i][1] += qd.x*kk4[0].y + qd.y*kk4[1].y + qd.z*kk4[2].y + qd.w*kk4[3].y;
                s[i][2] += qd.x*kk4[0].z + qd.y*kk4[1].z + qd.z*kk4[2].z + qd.w*kk4[3].z;
                s[i][3] += qd.x*kk4[0].w + qd.y*kk4[1].w + qd.z*kk4[2].w + qd.w*kk4[3].w;
            }
        }
        // batched max
        float lm[4];
        #pragma unroll
        for (int i = 0; i < 4; i++) {
            float mm = -F_INF;
            #pragma unroll
            for (int j=0;j<4;j++) {
                s[i][j] = (lane*4 + j < nk) ? s[i][j]*0.125f : -F_INF;
                mm = fmaxf(mm, s[i][j]);
            }
            lm[i] = mm;
        }
        warpMax4(lm);
        // batched exp + sum
        float f[4], le[4];
        #pragma unroll
        for (int i = 0; i < 4; i++) {
            float newm = fmaxf(m[i], lm[i]);
            f[i] = __expf(m[i] - newm);
            m[i] = newm;
            float e0 = __expf(s[i][0]-newm), e1 = __expf(s[i][1]-newm);
            float e2 = __expf(s[i][2]-newm), e3 = __expf(s[i][3]-newm);
            le[i] = e0+e1+e2+e3;
            *reinterpret_cast<float4*>(&psw[i*128 + lane*4]) = make_float4(e0,e1,e2,e3);
        }
        warpSum4(le);
        #pragma unroll
        for (int i = 0; i < 4; i++) {
            den[i] = den[i]*f[i] + le[i];
            acc[i].x *= f[i]; acc[i].y *= f[i];
        }
        __syncwarp();
        #pragma unroll 4
        for (int kk = 0; kk < 128; kk++) {
            float2 vv = *reinterpret_cast<const float2*>(&Vs[kk*64 + d0v]);
            float p0 = psw[0*128 + kk], p1 = psw[1*128 + kk];
            float p2 = psw[2*128 + kk], p3 = psw[3*128 + kk];
            acc[0].x += p0*vv.x; acc[0].y += p0*vv.y;
            acc[1].x += p1*vv.x; acc[1].y += p1*vv.y;
            acc[2].x += p2*vv.x; acc[2].y += p2*vv.y;
            acc[3].x += p3*vv.x; acc[3].y += p3*vv.y;
        }
    }
    #pragma unroll
    for (int i=0;i<4;i++) {
        int qi = q0 + warp*4 + i;
        float invd = 1.f / den[i];
        float2 ov = make_float2(acc[i].x*invd, acc[i].y*invd);
        *reinterpret_cast<float2*>(o + ((size_t)b*Tc + qi)*Cc + h*64 + d0v) = ov;
    }
}

// ============ add + layernorm ============
__global__ __launch_bounds__(256) void add_ln_kernel(
    const float* __restrict__ x, const float* __restrict__ r,
    const float* __restrict__ g, const float* __restrict__ bb,
    float* __restrict__ out, int nrows)
{
    int warp = (blockIdx.x * blockDim.x + threadIdx.x) >> 5;
    int lane = threadIdx.x & 31;
    if (warp >= nrows) return;
    const float* xr = x + (size_t)warp * Cc;
    const float* rr = r + (size_t)warp * Cc;
    float vals[16];
    float s = 0.f;
    #pragma unroll
    for (int i=0;i<16;i++) { float vv = xr[lane + i*32] + rr[lane + i*32]; vals[i] = vv; s += vv; }
    #pragma unroll
    for (int o2=16;o2;o2>>=1) s += __shfl_xor_sync(0xffffffffu, s, o2);
    float mu = s * (1.f/512.f);
    float vs = 0.f;
    #pragma unroll
    for (int i=0;i<16;i++){ float d = vals[i]-mu; vs += d*d; }
    #pragma unroll
    for (int o2=16;o2;o2>>=1) vs += __shfl_xor_sync(0xffffffffu, vs, o2);
    float rstd = rsqrtf(vs*(1.f/512.f) + 1e-5f);
    float* outr = out + (size_t)warp * Cc;
    #pragma unroll
    for (int i=0;i<16;i++){ int cc = lane + i*32; outr[cc] = (vals[i]-mu)*rstd*g[cc] + bb[cc]; }
}

// ============ misc elementwise ============
__global__ void repmean_kernel(const float* __restrict__ inp, const float* __restrict__ rep_w,
                               float* __restrict__ out)
{
    int b = blockIdx.x, c = threadIdx.x;
    const float* base = inp + (size_t)b*Tc*Cc + c;
    float rw = rep_w[c];
    float s = 0.f;
    for (int t=0;t<Tc;t++) s += fmaxf(rw * base[(size_t)t*Cc], 0.f);
    out[b*Cc + c] = s * (1.f/Tc);
}

__global__ void gate_kernel(const float* __restrict__ gates, const float* __restrict__ gi,
                            const float* __restrict__ mem_final, const float* __restrict__ mem0,
                            const float* __restrict__ ib, const float* __restrict__ fb,
                            float* __restrict__ nm)
{
    size_t n = (size_t)Bc*Mc*Cc;
    size_t i = (size_t)blockIdx.x*blockDim.x + threadIdx.x;
    size_t st = (size_t)gridDim.x*blockDim.x;
    float ibv = ib[0], fbv = fb[0];
    for (; i < n; i += st) {
        int c = (int)(i % Cc);
        size_t bm = i / Cc;
        int b = (int)(bm / Mc);
        float gI = gates[bm*2*Cc + c]      + gi[b*2*Cc + c]      + ibv;
        float gF = gates[bm*2*Cc + Cc + c] + gi[b*2*Cc + Cc + c] + fbv;
        float igv = 1.f/(1.f + __expf(-gI));
        float fgv = 1.f/(1.f + __expf(-gF));
        nm[i] = igv * tanhf(mem_final[i]) + fgv * mem0[i];
    }
}

// ============ launch ============
extern "C" void kernel_launch(void* const* d_in, const int* in_sizes, int n_in,
                              void* d_out, int out_size)
{
    const float* ipts   = (const float*)d_in[0];
    const float* memory = (const float*)d_in[1];
    const float* Wq=(const float*)d_in[2],  *bq=(const float*)d_in[3];
    const float* Wk=(const float*)d_in[4],  *bk=(const float*)d_in[5];
    const float* Wv=(const float*)d_in[6],  *bv=(const float*)d_in[7];
    const float* Wm=(const float*)d_in[8],  *bm=(const float*)d_in[9];
    const float* g1=(const float*)d_in[10], *b1=(const float*)d_in[11];
    const float* g2=(const float*)d_in[12], *b2=(const float*)d_in[13];
    const float* Wp=(const float*)d_in[14], *bp=(const float*)d_in[15];
    const float* rep_w=(const float*)d_in[16];
    const float* Wig=(const float*)d_in[17], *big=(const float*)d_in[18];
    const float* Wmg=(const float*)d_in[19], *bmg=(const float*)d_in[20];
    const float* fb=(const float*)d_in[21], *ib=(const float*)d_in[22];

    float* out_nm = (float*)d_out;
    float* out_hx = out_nm + (size_t)Bc*Mc*Cc;

    float *inp,*mem,*qb,*kb,*vb,*ao,*h1,*h2,*gt,*rm,*gi;
    float *WqT,*WkT,*WvT,*WmT,*WpT,*WmgT;
    cudaGetSymbolAddress((void**)&inp, d_inp);
    cudaGetSymbolAddress((void**)&mem, d_mem);
    cudaGetSymbolAddress((void**)&qb,  d_qb);
    cudaGetSymbolAddress((void**)&kb,  d_kb);
    cudaGetSymbolAddress((void**)&vb,  d_vb);
    cudaGetSymbolAddress((void**)&ao,  d_ao);
    cudaGetSymbolAddress((void**)&h1,  d_h1);
    cudaGetSymbolAddress((void**)&h2,  d_h2);
    cudaGetSymbolAddress((void**)&gt,  d_gt);
    cudaGetSymbolAddress((void**)&rm,  d_rm);
    cudaGetSymbolAddress((void**)&gi,  d_gi);
    cudaGetSymbolAddress((void**)&WqT, d_WqT);
    cudaGetSymbolAddress((void**)&WkT, d_WkT);
    cudaGetSymbolAddress((void**)&WvT, d_WvT);
    cudaGetSymbolAddress((void**)&WmT, d_WmT);
    cudaGetSymbolAddress((void**)&WpT, d_WpT);
    cudaGetSymbolAddress((void**)&WmgT, d_WmgT);

    cudaFuncSetAttribute(attn_topk_kernel, cudaFuncAttributeMaxDynamicSharedMemorySize, SMEM_TOPK);
    cudaFuncSetAttribute(attn_hx_kernel,   cudaFuncAttributeMaxDynamicSharedMemorySize, SMEM_HX);
    cudaFuncSetAttribute(tf32_gemm_kernel, cudaFuncAttributeMaxDynamicSharedMemorySize, TG_SMEM);

    transpose_kernel<<<dim3(16,16), 256>>>(Wq, WqT, Cc, Cc);
    transpose_kernel<<<dim3(16,16), 256>>>(Wk, WkT, Cc, Cc);
    transpose_kernel<<<dim3(16,16), 256>>>(Wv, WvT, Cc, Cc);
    transpose_kernel<<<dim3(16,16), 256>>>(Wm, WmT, Cc, Cc);
    transpose_kernel<<<dim3(16,16), 256>>>(Wp, WpT, Cc, Cc);
    transpose_kernel<<<dim3(32,16), 256>>>(Wmg, WmgT, Cc, 2*Cc);

    auto tgemm = [&](const float* A, const float* WT, const float* bias, float* o,
                     int N, int NO, int relu, int dotanh){
        tf32_gemm_kernel<<<dim3(NO/128, (N+127)/128), 256, TG_SMEM>>>(
            A, WT, bias, o, N, Cc, NO, relu, dotanh);
    };

    // inp = ipts @ Wp + bp ; k,v from inp are LOOP-INVARIANT
    tgemm(ipts, WpT, bp, inp, Bc*Tc, Cc, 0, 0);
    tgemm(inp,  WkT, bk, kb,  Bc*Tc, Cc, 0, 0);
    tgemm(inp,  WvT, bv, vb,  Bc*Tc, Cc, 0, 0);
    cudaMemcpyAsync(mem, memory, sizeof(float)*(size_t)Bc*Mc*Cc, cudaMemcpyDeviceToDevice);

    for (int blk = 0; blk < NBLK; blk++) {
        tgemm(mem, WqT, bq, qb, Bc*Mc, Cc, 0, 0);
        attn_topk_kernel<<<dim3(Bc*Hc, Q_BLOCKS), 256, SMEM_TOPK>>>(qb, kb, vb, ao);
        add_ln_kernel<<<(Bc*Mc + 7)/8, 256>>>(mem, ao, g1, b1, mem, Bc*Mc);
        tgemm(mem, WmT, bm, h1, Bc*Mc, Cc, 1, 0);
        tgemm(h1,  WmT, bm, h2, Bc*Mc, Cc, 1, 0);
        add_ln_kernel<<<(Bc*Mc + 7)/8, 256>>>(mem, h2, g2, b2, mem, Bc*Mc);
    }

    // gates
    repmean_kernel<<<Bc, Cc>>>(inp, rep_w, rm);
    gemm_kernel<<<dim3(2*Cc/64, 1), 256>>>(rm, Wig, big, gi, Bc, Cc, 2*Cc, 0);
    tgemm(memory, WmgT, bmg, gt, Bc*Mc, 2*Cc, 0, 1);   // tanh fused into A frag load
    gate_kernel<<<2048, 256>>>(gt, gi, mem, memory, ib, fb, out_nm);

    // hx = attention(q from inp, k/v from next_memory), no topk
    tgemm(inp,    WqT, bq, qb, Bc*Tc, Cc, 0, 0);
    tgemm(out_nm, WkT, bk, kb, Bc*Mc, Cc, 0, 0);
    tgemm(out_nm, WvT, bv, vb, Bc*Mc, Cc, 0, 0);
    attn_hx_kernel<<<dim3(Bc*Hc, Tc/32), 256, SMEM_HX>>>(qb, kb, vb, out_hx);
}

// round 8
// speedup vs baseline: 3.7746x; 1.0903x over previous
#include <cuda_runtime.h>
#include <cuda_fp16.h>
#include <math.h>
#include <stdint.h>

#define Bc 32
#define Tc 128
#define Mc 1290
#define Cc 512
#define Hc 8
#define NBLK 4
#define TOPK 8

static __device__ float d_inp[Bc*Tc*Cc];
static __device__ float d_mem[(size_t)Bc*Mc*Cc];
static __device__ float d_qb [(size_t)Bc*Mc*Cc];
static __device__ float d_kb [(size_t)Bc*Mc*Cc];
static __device__ float d_vb [(size_t)Bc*Mc*Cc];
static __device__ float d_ao [(size_t)Bc*Mc*Cc];
static __device__ float d_h1 [(size_t)Bc*Mc*Cc];
static __device__ float d_h2 [(size_t)Bc*Mc*Cc];
static __device__ float d_gt [(size_t)Bc*Mc*2*Cc];
static __device__ float d_rm [Bc*Cc];
static __device__ float d_gi [Bc*2*Cc];
static __device__ __half d_WqT[Cc*Cc];
static __device__ __half d_WkT[Cc*Cc];
static __device__ __half d_WvT[Cc*Cc];
static __device__ __half d_WmT[Cc*Cc];
static __device__ __half d_WpT[Cc*Cc];
static __device__ __half d_WmgT[Cc*2*Cc];

#define F_INF __int_as_float(0x7f800000)

__device__ __forceinline__ uint32_t pack2(float x, float y){
    __half2 h = __floats2half2_rn(x, y);
    return *reinterpret_cast<uint32_t*>(&h);
}
__device__ __forceinline__ void mma_f16(float* d, const uint32_t* a, const uint32_t* b){
    asm volatile("mma.sync.aligned.m16n8k16.row.col.f32.f16.f16.f32 "
        "{%0,%1,%2,%3}, {%4,%5,%6,%7}, {%8,%9}, {%0,%1,%2,%3};"
        : "+f"(d[0]), "+f"(d[1]), "+f"(d[2]), "+f"(d[3])
        : "r"(a[0]), "r"(a[1]), "r"(a[2]), "r"(a[3]), "r"(b[0]), "r"(b[1]));
}

// ============ fp16 mma.sync GEMM: out[N,NO] = A[N,512] @ WT[NO,512]^T + bias ============
// block 128x128, K-chunk 32, 256 thr = 8 warps (4m x 2n), warp tile 32x64, m16n8k16.
// SMEM half pitch 40 (conflict-free STS.128 staging + LDS.32 frags), reg-prefetch pipeline.
#define APH 40
#define CHH (128*APH)
#define TG_SMEM (4*CHH*2)
__global__ __launch_bounds__(256) void f16_gemm_kernel(
    const float* __restrict__ A, const __half* __restrict__ WT,
    const float* __restrict__ bias, float* __restrict__ out,
    int Nrows, int K, int NO, int relu, int dotanh)
{
    extern __shared__ __half smh[];
    int tid = threadIdx.x;
    int wid = tid >> 5, lane = tid & 31;
    int wm = wid & 3, wn = wid >> 2;
    int lr = lane >> 2, lc = lane & 3;
    int row0 = blockIdx.y * 128;
    int col0 = blockIdx.x * 128;

    float acc[2][8][4];
    #pragma unroll
    for (int i=0;i<2;i++)
        #pragma unroll
        for (int j=0;j<8;j++)
            #pragma unroll
            for (int l=0;l<4;l++) acc[i][j][l] = 0.f;

    int arow = tid & 127;
    int akb  = (tid >> 7) * 16;
    bool apred = (row0 + arow) < Nrows;
    const float*  aptr = A  + (size_t)(row0 + arow)*K + akb;
    const __half* bptr = WT + (size_t)(col0 + arow)*K + akb;

    float4 pA[4];
    uint4  pB[2];
    #pragma unroll
    for (int j=0;j<4;j++) pA[j] = make_float4(0.f,0.f,0.f,0.f);

    const int nc = K / 32;   // 16

    auto preload = [&](int c){
        int k0 = c * 32;
        if (apred) {
            #pragma unroll
            for (int j = 0; j < 4; j++)
                pA[j] = *reinterpret_cast<const float4*>(aptr + k0 + j*4);
        }
        pB[0] = *reinterpret_cast<const uint4*>(bptr + k0);
        pB[1] = *reinterpret_cast<const uint4*>(bptr + k0 + 8);
    };

    preload(0);
    for (int c = 0; c < nc; c++) {
        // ---- stage into buf c&1 ----
        {
            __half* As = smh + (c & 1)*2*CHH;
            __half* Bs = As + CHH;
            float v[16];
            #pragma unroll
            for (int j=0;j<4;j++){
                v[j*4+0]=pA[j].x; v[j*4+1]=pA[j].y; v[j*4+2]=pA[j].z; v[j*4+3]=pA[j].w;
            }
            if (dotanh) {
                #pragma unroll
                for (int j=0;j<16;j++) v[j] = tanhf(v[j]);
            }
            uint4 h0, h1;
            h0.x = pack2(v[0],v[1]);   h0.y = pack2(v[2],v[3]);
            h0.z = pack2(v[4],v[5]);   h0.w = pack2(v[6],v[7]);
            h1.x = pack2(v[8],v[9]);   h1.y = pack2(v[10],v[11]);
            h1.z = pack2(v[12],v[13]); h1.w = pack2(v[14],v[15]);
            *reinterpret_cast<uint4*>(As + arow*APH + akb)     = h0;
            *reinterpret_cast<uint4*>(As + arow*APH + akb + 8) = h1;
            *reinterpret_cast<uint4*>(Bs + arow*APH + akb)     = pB[0];
            *reinterpret_cast<uint4*>(Bs + arow*APH + akb + 8) = pB[1];
        }
        __syncthreads();
        if (c + 1 < nc) preload(c + 1);   // LDG overlaps compute below
        // ---- compute from buf c&1 ----
        {
            const __half* As = smh + (c & 1)*2*CHH;
            const __half* Bs = As + CHH;
            #pragma unroll
            for (int ks = 0; ks < 2; ks++) {
                int kb = ks*16;
                uint32_t af[2][4];
                #pragma unroll
                for (int ma = 0; ma < 2; ma++) {
                    int r = wm*32 + ma*16;
                    af[ma][0] = *reinterpret_cast<const uint32_t*>(As + (r+lr  )*APH + kb + 2*lc);
                    af[ma][1] = *reinterpret_cast<const uint32_t*>(As + (r+lr+8)*APH + kb + 2*lc);
                    af[ma][2] = *reinterpret_cast<const uint32_t*>(As + (r+lr  )*APH + kb + 8 + 2*lc);
                    af[ma][3] = *reinterpret_cast<const uint32_t*>(As + (r+lr+8)*APH + kb + 8 + 2*lc);
                }
                uint32_t bf[8][2];
                #pragma unroll
                for (int na = 0; na < 8; na++) {
                    int n = wn*64 + na*8 + lr;
                    bf[na][0] = *reinterpret_cast<const uint32_t*>(Bs + n*APH + kb + 2*lc);
                    bf[na][1] = *reinterpret_cast<const uint32_t*>(Bs + n*APH + kb + 8 + 2*lc);
                }
                #pragma unroll
                for (int ma = 0; ma < 2; ma++)
                    #pragma unroll
                    for (int na = 0; na < 8; na++)
                        mma_f16(acc[ma][na], af[ma], bf[na]);
            }
        }
        __syncthreads();
    }

    #pragma unroll
    for (int ma = 0; ma < 2; ma++) {
        int r1 = row0 + wm*32 + ma*16 + lr;
        int r2 = r1 + 8;
        #pragma unroll
        for (int na = 0; na < 8; na++) {
            int col = col0 + wn*64 + na*8 + lc*2;
            float bx = bias[col], by = bias[col+1];
            float2 o1 = make_float2(acc[ma][na][0] + bx, acc[ma][na][1] + by);
            float2 o2 = make_float2(acc[ma][na][2] + bx, acc[ma][na][3] + by);
            if (relu) {
                o1.x = fmaxf(o1.x,0.f); o1.y = fmaxf(o1.y,0.f);
                o2.x = fmaxf(o2.x,0.f); o2.y = fmaxf(o2.y,0.f);
            }
            if (r1 < Nrows) *reinterpret_cast<float2*>(out + (size_t)r1*NO + col) = o1;
            if (r2 < Nrows) *reinterpret_cast<float2*>(out + (size_t)r2*NO + col) = o2;
        }
    }
}

// ============ batched transpose + half convert (ONE launch) ============
struct TPack {
    const float* in[6];
    __half* out[6];
    int C[6];
};
__global__ __launch_bounds__(256) void transpose_all_kernel(TPack p)
{
    __shared__ float t[32][33];
    int w = blockIdx.z;
    int C = p.C[w];
    int c0 = blockIdx.x*32;
    if (c0 >= C) return;
    int r0 = blockIdx.y*32;
    const float* in = p.in[w];
    __half* out = p.out[w];
    int x = threadIdx.x & 31, y = threadIdx.x >> 5;
    #pragma unroll
    for (int i = 0; i < 4; i++)
        t[y + i*8][x] = in[(size_t)(r0 + y + i*8)*C + c0 + x];
    __syncthreads();
    #pragma unroll
    for (int i = 0; i < 4; i++)
        out[(size_t)(c0 + y + i*8)*Cc + r0 + x] = __float2half(t[x][y + i*8]);
}

// ============ SIMT GEMM (tiny) ============
__global__ __launch_bounds__(256) void gemm_kernel(
    const float* __restrict__ A, const float* __restrict__ W,
    const float* __restrict__ bias, float* __restrict__ out,
    int N, int K, int NO, int relu)
{
    __shared__ float As[16][64];
    __shared__ float Bs[16][64];
    int t  = threadIdx.x;
    int tx = t & 15, ty = t >> 4;
    int row0 = blockIdx.y * 64;
    int col0 = blockIdx.x * 64;
    float acc[4][4] = {};
    for (int k0 = 0; k0 < K; k0 += 16) {
        {
            int r = t >> 2;
            int c4 = (t & 3) * 4;
            float4 av = make_float4(0.f,0.f,0.f,0.f);
            if (row0 + r < N)
                av = *reinterpret_cast<const float4*>(A + (size_t)(row0 + r) * K + k0 + c4);
            As[c4+0][r] = av.x; As[c4+1][r] = av.y; As[c4+2][r] = av.z; As[c4+3][r] = av.w;
        }
        {
            int r  = t >> 4;
            int c4 = (t & 15) * 4;
            float4 bv = *reinterpret_cast<const float4*>(W + (size_t)(k0 + r) * NO + col0 + c4);
            *reinterpret_cast<float4*>(&Bs[r][c4]) = bv;
        }
        __syncthreads();
        #pragma unroll
        for (int kk = 0; kk < 16; kk++) {
            float4 a4 = *reinterpret_cast<const float4*>(&As[kk][ty*4]);
            float4 b4 = *reinterpret_cast<const float4*>(&Bs[kk][tx*4]);
            float a[4] = {a4.x,a4.y,a4.z,a4.w};
            float b[4] = {b4.x,b4.y,b4.z,b4.w};
            #pragma unroll
            for (int i=0;i<4;i++)
                #pragma unroll
                for (int j=0;j<4;j++) acc[i][j] += a[i]*b[j];
        }
        __syncthreads();
    }
    float4 bb = *reinterpret_cast<const float4*>(bias + col0 + tx*4);
    #pragma unroll
    for (int i=0;i<4;i++) {
        int r = row0 + ty*4 + i;
        if (r >= N) continue;
        float4 o4;
        o4.x = acc[i][0] + bb.x; o4.y = acc[i][1] + bb.y;
        o4.z = acc[i][2] + bb.z; o4.w = acc[i][3] + bb.w;
        if (relu) {
            o4.x = fmaxf(o4.x,0.f); o4.y = fmaxf(o4.y,0.f);
            o4.z = fmaxf(o4.z,0.f); o4.w = fmaxf(o4.w,0.f);
        }
        *reinterpret_cast<float4*>(out + (size_t)r * NO + col0 + tx*4) = o4;
    }
}

// ============ warp reductions (x4-interleaved) ============
__device__ __forceinline__ void warpMax4(float* c){
    #pragma unroll
    for (int o=16;o;o>>=1){
        #pragma unroll
        for (int qq=0;qq<4;qq++) c[qq] = fmaxf(c[qq], __shfl_xor_sync(0xffffffffu, c[qq], o));
    }
}
__device__ __forceinline__ void warpSum4(float* c){
    #pragma unroll
    for (int o=16;o;o>>=1){
        #pragma unroll
        for (int qq=0;qq<4;qq++) c[qq] += __shfl_xor_sync(0xffffffffu, c[qq], o);
    }
}

// ============ top-k attention: 4 queries/warp, interleaved reductions ============
#define Q_BLOCKS 6
#define SMEM_TOPK ((64*128 + 128*64 + 8*4*64)*4)
__global__ __launch_bounds__(256) void attn_topk_kernel(
    const float* __restrict__ q, const float* __restrict__ k,
    const float* __restrict__ v, float* __restrict__ o)
{
    extern __shared__ float sm[];
    float* Kt = sm;
    float* Vs = Kt + 64*128;
    float* sq = Vs + 128*64;

    int tid = threadIdx.x;
    int warp = tid >> 5, lane = tid & 31;
    int bh = blockIdx.x, b = bh / Hc, h = bh % Hc;

    for (int idx = tid; idx < 128*16; idx += 256) {
        int t = idx >> 4, j = idx & 15;
        size_t row = ((size_t)b*Tc + t)*Cc + h*64 + j*4;
        float4 kv = *reinterpret_cast<const float4*>(k + row);
        float4 vv = *reinterpret_cast<const float4*>(v + row);
        Kt[(j*4+0)*128 + t] = kv.x;
        Kt[(j*4+1)*128 + t] = kv.y;
        Kt[(j*4+2)*128 + t] = kv.z;
        Kt[(j*4+3)*128 + t] = kv.w;
        *reinterpret_cast<float4*>(&Vs[t*64 + j*4]) = vv;
    }
    __syncthreads();

    const int nq = (Mc + Q_BLOCKS - 1) / Q_BLOCKS;
    int q0 = blockIdx.y * nq;
    int qend = min(q0 + nq, Mc);
    float* sqw = sq + warp*256;

    for (int qi0 = q0 + warp*4; qi0 < qend; qi0 += 32) {
        #pragma unroll
        for (int f = 0; f < 2; f++) {
            int ff = lane + f*32;
            int qq = ff >> 4, j = ff & 15;
            int qi = qi0 + qq;
            if (qi < qend) {
                float4 qv = *reinterpret_cast<const float4*>(q + ((size_t)b*Mc + qi)*Cc + h*64 + j*4);
                *reinterpret_cast<float4*>(&sqw[qq*64 + j*4]) = qv;
            }
        }
        __syncwarp();
        float s[4][4];
        #pragma unroll
        for (int qq=0;qq<4;qq++)
            #pragma unroll
            for (int j=0;j<4;j++) s[qq][j] = 0.f;
        #pragma unroll 4
        for (int d0 = 0; d0 < 64; d0 += 4) {
            float4 kk4[4];
            #pragma unroll
            for (int dd = 0; dd < 4; dd++)
                kk4[dd] = *reinterpret_cast<const float4*>(&Kt[(d0+dd)*128 + lane*4]);
            #pragma unroll
            for (int qq = 0; qq < 4; qq++) {
                float4 qd = *reinterpret_cast<const float4*>(&sqw[qq*64 + d0]);
                s[qq][0] += qd.x*kk4[0].x + qd.y*kk4[1].x + qd.z*kk4[2].x + qd.w*kk4[3].x;
                s[qq][1] += qd.x*kk4[0].y + qd.y*kk4[1].y + qd.z*kk4[2].y + qd.w*kk4[3].y;
                s[qq][2] += qd.x*kk4[0].z + qd.y*kk4[1].z + qd.z*kk4[2].z + qd.w*kk4[3].z;
                s[qq][3] += qd.x*kk4[0].w + qd.y*kk4[1].w + qd.z*kk4[2].w + qd.w*kk4[3].w;
            }
        }
        #pragma unroll
        for (int qq=0;qq<4;qq++)
            #pragma unroll
            for (int j=0;j<4;j++) s[qq][j] *= 0.125f;

        float thr[4], gmax[4], c[4];
        #pragma unroll
        for (int qq=0;qq<4;qq++)
            c[qq] = fmaxf(fmaxf(s[qq][0],s[qq][1]), fmaxf(s[qq][2],s[qq][3]));
        warpMax4(c);
        #pragma unroll
        for (int qq=0;qq<4;qq++){ gmax[qq] = c[qq]; thr[qq] = c[qq]; }
        #pragma unroll
        for (int it = 1; it < TOPK; it++) {
            #pragma unroll
            for (int qq=0;qq<4;qq++){
                float m = -F_INF;
                #pragma unroll
                for (int j=0;j<4;j++) m = fmaxf(m, (s[qq][j] < thr[qq]) ? s[qq][j] : -F_INF);
                c[qq] = m;
            }
            warpMax4(c);
            #pragma unroll
            for (int qq=0;qq<4;qq++) thr[qq] = c[qq];
        }
        float e[4][4], le[4];
        #pragma unroll
        for (int qq=0;qq<4;qq++){
            le[qq] = 0.f;
            #pragma unroll
            for (int j=0;j<4;j++){ e[qq][j] = __expf(s[qq][j] - gmax[qq]); le[qq] += e[qq][j]; }
        }
        warpSum4(le);

        int d0v = lane*2;
        #pragma unroll
        for (int qq = 0; qq < 4; qq++) {
            int qi = qi0 + qq;
            if (qi >= qend) break;
            float inv = 1.f / le[qq];
            float p[4];
            #pragma unroll
            for (int j=0;j<4;j++) p[j] = (s[qq][j] >= thr[qq]) ? e[qq][j]*inv : 0.f;
            float2 acc = make_float2(0.f, 0.f);
            #pragma unroll
            for (int j=0;j<4;j++) {
                unsigned msk = __ballot_sync(0xffffffffu, p[j] != 0.f);
                while (msk) {
                    int src = __ffs(msk) - 1;
                    msk &= msk - 1;
                    float pv = __shfl_sync(0xffffffffu, p[j], src);
                    int key = src*4 + j;
                    float2 vv = *reinterpret_cast<const float2*>(&Vs[key*64 + d0v]);
                    acc.x += pv*vv.x; acc.y += pv*vv.y;
                }
            }
            *reinterpret_cast<float2*>(o + ((size_t)b*Mc + qi)*Cc + h*64 + d0v) = acc;
        }
    }
}

// ============ hx attention: joint-4 QK/AV, interleaved reductions ============
#define SMEM_HX ((64*128 + 128*64 + 32*64 + 8*4*128)*4)
__global__ __launch_bounds__(256) void attn_hx_kernel(
    const float* __restrict__ q, const float* __restrict__ k,
    const float* __restrict__ v, float* __restrict__ o)
{
    extern __shared__ float sm[];
    float* Kt = sm;
    float* Vs = Kt + 64*128;
    float* sq = Vs + 128*64;
    float* ps = sq + 32*64;

    int tid = threadIdx.x;
    int warp = tid >> 5, lane = tid & 31;
    int bh = blockIdx.x, b = bh / Hc, h = bh % Hc;
    int q0 = blockIdx.y * 32;

    for (int idx = tid; idx < 32*16; idx += 256) {
        int qi = idx >> 4, j = idx & 15;
        float4 qv = *reinterpret_cast<const float4*>(q + ((size_t)b*Tc + q0 + qi)*Cc + h*64 + j*4);
        *reinterpret_cast<float4*>(&sq[qi*64 + j*4]) = qv;
    }

    float m[4], den[4];
    float2 acc[4];
    #pragma unroll
    for (int i=0;i<4;i++){ m[i] = -F_INF; den[i] = 0.f; acc[i] = make_float2(0.f,0.f); }
    int d0v = lane*2;
    float* psw = ps + warp*512;

    for (int c0 = 0; c0 < Mc; c0 += 128) {
        int nk = min(128, Mc - c0);
        __syncthreads();
        for (int idx = tid; idx < 128*16; idx += 256) {
            int t = idx >> 4, j = idx & 15;
            float4 kv = make_float4(0.f,0.f,0.f,0.f), vv = kv;
            if (t < nk) {
                size_t row = ((size_t)b*Mc + c0 + t)*Cc + h*64 + j*4;
                kv = *reinterpret_cast<const float4*>(k + row);
                vv = *reinterpret_cast<const float4*>(v + row);
            }
            Kt[(j*4+0)*128 + t] = kv.x;
            Kt[(j*4+1)*128 + t] = kv.y;
            Kt[(j*4+2)*128 + t] = kv.z;
            Kt[(j*4+3)*128 + t] = kv.w;
            *reinterpret_cast<float4*>(&Vs[t*64 + j*4]) = vv;
        }
        __syncthreads();

        float s[4][4];
        #pragma unroll
        for (int i=0;i<4;i++)
            #pragma unroll
            for (int j=0;j<4;j++) s[i][j] = 0.f;
        #pragma unroll 4
        for (int d0 = 0; d0 < 64; d0 += 4) {
            float4 kk4[4];
            #pragma unroll
            for (int dd = 0; dd < 4; dd++)
                kk4[dd] = *reinterpret_cast<const float4*>(&Kt[(d0+dd)*128 + lane*4]);
            #pragma unroll
            for (int i = 0; i < 4; i++) {
                float4 qd = *reinterpret_cast<const float4*>(&sq[(warp*4+i)*64 + d0]);
                s[i][0] += qd.x*kk4[0].x + qd.y*kk4[1].x + qd.z*kk4[2].x + qd.w*kk4[3].x;
                s[i][1] += qd.x*kk4[0].y + qd.y*kk4[1].y + qd.z*kk4[2].y + qd.w*kk4[3].y;
                s[i][2] += qd.x*kk4[0].z + qd.y*kk4[1].z + qd.z*kk4[2].z + qd.w*kk4[3].z;
                s[i][3] += qd.x*kk4[0].w + qd.y*kk4[1].w + qd.z*kk4[2].w + qd.w*kk4[3].w;
            }
        }
        float lm[4];
        #pragma unroll
        for (int i = 0; i < 4; i++) {
            float mm = -F_INF;
            #pragma unroll
            for (int j=0;j<4;j++) {
                s[i][j] = (lane*4 + j < nk) ? s[i][j]*0.125f : -F_INF;
                mm = fmaxf(mm, s[i][j]);
            }
            lm[i] = mm;
        }
        warpMax4(lm);
        float f[4], le[4];
        #pragma unroll
        for (int i = 0; i < 4; i++) {
            float newm = fmaxf(m[i], lm[i]);
            f[i] = __expf(m[i] - newm);
            m[i] = newm;
            float e0 = __expf(s[i][0]-newm), e1 = __expf(s[i][1]-newm);
            float e2 = __expf(s[i][2]-newm), e3 = __expf(s[i][3]-newm);
            le[i] = e0+e1+e2+e3;
            *reinterpret_cast<float4*>(&psw[i*128 + lane*4]) = make_float4(e0,e1,e2,e3);
        }
        warpSum4(le);
        #pragma unroll
        for (int i = 0; i < 4; i++) {
            den[i] = den[i]*f[i] + le[i];
            acc[i].x *= f[i]; acc[i].y *= f[i];
        }
        __syncwarp();
        #pragma unroll 4
        for (int kk = 0; kk < 128; kk++) {
            float2 vv = *reinterpret_cast<const float2*>(&Vs[kk*64 + d0v]);
            float p0 = psw[0*128 + kk], p1 = psw[1*128 + kk];
            float p2 = psw[2*128 + kk], p3 = psw[3*128 + kk];
            acc[0].x += p0*vv.x; acc[0].y += p0*vv.y;
            acc[1].x += p1*vv.x; acc[1].y += p1*vv.y;
            acc[2].x += p2*vv.x; acc[2].y += p2*vv.y;
            acc[3].x += p3*vv.x; acc[3].y += p3*vv.y;
        }
    }
    #pragma unroll
    for (int i=0;i<4;i++) {
        int qi = q0 + warp*4 + i;
        float invd = 1.f / den[i];
        float2 ov = make_float2(acc[i].x*invd, acc[i].y*invd);
        *reinterpret_cast<float2*>(o + ((size_t)b*Tc + qi)*Cc + h*64 + d0v) = ov;
    }
}

// ============ add + layernorm ============
__global__ __launch_bounds__(256) void add_ln_kernel(
    const float* __restrict__ x, const float* __restrict__ r,
    const float* __restrict__ g, const float* __restrict__ bb,
    float* __restrict__ out, int nrows)
{
    int warp = (blockIdx.x * blockDim.x + threadIdx.x) >> 5;
    int lane = threadIdx.x & 31;
    if (warp >= nrows) return;
    const float* xr = x + (size_t)warp * Cc;
    const float* rr = r + (size_t)warp * Cc;
    float vals[16];
    float s = 0.f;
    #pragma unroll
    for (int i=0;i<16;i++) { float vv = xr[lane + i*32] + rr[lane + i*32]; vals[i] = vv; s += vv; }
    #pragma unroll
    for (int o2=16;o2;o2>>=1) s += __shfl_xor_sync(0xffffffffu, s, o2);
    float mu = s * (1.f/512.f);
    float vs = 0.f;
    #pragma unroll
    for (int i=0;i<16;i++){ float d = vals[i]-mu; vs += d*d; }
    #pragma unroll
    for (int o2=16;o2;o2>>=1) vs += __shfl_xor_sync(0xffffffffu, vs, o2);
    float rstd = rsqrtf(vs*(1.f/512.f) + 1e-5f);
    float* outr = out + (size_t)warp * Cc;
    #pragma unroll
    for (int i=0;i<16;i++){ int cc = lane + i*32; outr[cc] = (vals[i]-mu)*rstd*g[cc] + bb[cc]; }
}

// ============ misc elementwise ============
__global__ void repmean_kernel(const float* __restrict__ inp, const float* __restrict__ rep_w,
                               float* __restrict__ out)
{
    int b = blockIdx.x, c = threadIdx.x;
    const float* base = inp + (size_t)b*Tc*Cc + c;
    float rw = rep_w[c];
    float s = 0.f;
    for (int t=0;t<Tc;t++) s += fmaxf(rw * base[(size_t)t*Cc], 0.f);
    out[b*Cc + c] = s * (1.f/Tc);
}

__global__ void gate_kernel(const float* __restrict__ gates, const float* __restrict__ gi,
                            const float* __restrict__ mem_final, const float* __restrict__ mem0,
                            const float* __restrict__ ib, const float* __restrict__ fb,
                            float* __restrict__ nm)
{
    size_t n = (size_t)Bc*Mc*Cc;
    size_t i = (size_t)blockIdx.x*blockDim.x + threadIdx.x;
    size_t st = (size_t)gridDim.x*blockDim.x;
    float ibv = ib[0], fbv = fb[0];
    for (; i < n; i += st) {
        int c = (int)(i % Cc);
        size_t bm = i / Cc;
        int b = (int)(bm / Mc);
        float gI = gates[bm*2*Cc + c]      + gi[b*2*Cc + c]      + ibv;
        float gF = gates[bm*2*Cc + Cc + c] + gi[b*2*Cc + Cc + c] + fbv;
        float igv = 1.f/(1.f + __expf(-gI));
        float fgv = 1.f/(1.f + __expf(-gF));
        nm[i] = igv * tanhf(mem_final[i]) + fgv * mem0[i];
    }
}

// ============ launch ============
extern "C" void kernel_launch(void* const* d_in, const int* in_sizes, int n_in,
                              void* d_out, int out_size)
{
    const float* ipts   = (const float*)d_in[0];
    const float* memory = (const float*)d_in[1];
    const float* Wq=(const float*)d_in[2],  *bq=(const float*)d_in[3];
    const float* Wk=(const float*)d_in[4],  *bk=(const float*)d_in[5];
    const float* Wv=(const float*)d_in[6],  *bv=(const float*)d_in[7];
    const float* Wm=(const float*)d_in[8],  *bm=(const float*)d_in[9];
    const float* g1=(const float*)d_in[10], *b1=(const float*)d_in[11];
    const float* g2=(const float*)d_in[12], *b2=(const float*)d_in[13];
    const float* Wp=(const float*)d_in[14], *bp=(const float*)d_in[15];
    const float* rep_w=(const float*)d_in[16];
    const float* Wig=(const float*)d_in[17], *big=(const float*)d_in[18];
    const float* Wmg=(const float*)d_in[19], *bmg=(const float*)d_in[20];
    const float* fb=(const float*)d_in[21], *ib=(const float*)d_in[22];

    float* out_nm = (float*)d_out;
    float* out_hx = out_nm + (size_t)Bc*Mc*Cc;

    float *inp,*mem,*qb,*kb,*vb,*ao,*h1,*h2,*gt,*rm,*gi;
    __half *WqT,*WkT,*WvT,*WmT,*WpT,*WmgT;
    cudaGetSymbolAddress((void**)&inp, d_inp);
    cudaGetSymbolAddress((void**)&mem, d_mem);
    cudaGetSymbolAddress((void**)&qb,  d_qb);
    cudaGetSymbolAddress((void**)&kb,  d_kb);
    cudaGetSymbolAddress((void**)&vb,  d_vb);
    cudaGetSymbolAddress((void**)&ao,  d_ao);
    cudaGetSymbolAddress((void**)&h1,  d_h1);
    cudaGetSymbolAddress((void**)&h2,  d_h2);
    cudaGetSymbolAddress((void**)&gt,  d_gt);
    cudaGetSymbolAddress((void**)&rm,  d_rm);
    cudaGetSymbolAddress((void**)&gi,  d_gi);
    cudaGetSymbolAddress((void**)&WqT, d_WqT);
    cudaGetSymbolAddress((void**)&WkT, d_WkT);
    cudaGetSymbolAddress((void**)&WvT, d_WvT);
    cudaGetSymbolAddress((void**)&WmT, d_WmT);
    cudaGetSymbolAddress((void**)&WpT, d_WpT);
    cudaGetSymbolAddress((void**)&WmgT, d_WmgT);

    cudaFuncSetAttribute(attn_topk_kernel, cudaFuncAttributeMaxDynamicSharedMemorySize, SMEM_TOPK);
    cudaFuncSetAttribute(attn_hx_kernel,   cudaFuncAttributeMaxDynamicSharedMemorySize, SMEM_HX);
    cudaFuncSetAttribute(f16_gemm_kernel,  cudaFuncAttributeMaxDynamicSharedMemorySize, TG_SMEM);

    // single batched transpose launch (also positions ncu capture onto a real kernel)
    TPack tp;
    tp.in[0]=Wq;  tp.out[0]=WqT;  tp.C[0]=Cc;
    tp.in[1]=Wk;  tp.out[1]=WkT;  tp.C[1]=Cc;
    tp.in[2]=Wv;  tp.out[2]=WvT;  tp.C[2]=Cc;
    tp.in[3]=Wm;  tp.out[3]=WmT;  tp.C[3]=Cc;
    tp.in[4]=Wp;  tp.out[4]=WpT;  tp.C[4]=Cc;
    tp.in[5]=Wmg; tp.out[5]=WmgT; tp.C[5]=2*Cc;
    transpose_all_kernel<<<dim3(32,16,6), 256>>>(tp);
    cudaMemcpyAsync(mem, memory, sizeof(float)*(size_t)Bc*Mc*Cc, cudaMemcpyDeviceToDevice);

    auto tgemm = [&](const float* A, const __half* WT, const float* bias, float* o,
                     int N, int NO, int relu, int dotanh){
        f16_gemm_kernel<<<dim3(NO/128, (N+127)/128), 256, TG_SMEM>>>(
            A, WT, bias, o, N, Cc, NO, relu, dotanh);
    };

    // inp = ipts @ Wp + bp ; k,v from inp are LOOP-INVARIANT
    tgemm(ipts, WpT, bp, inp, Bc*Tc, Cc, 0, 0);
    tgemm(inp,  WkT, bk, kb,  Bc*Tc, Cc, 0, 0);
    tgemm(inp,  WvT, bv, vb,  Bc*Tc, Cc, 0, 0);

    for (int blk = 0; blk < NBLK; blk++) {
        tgemm(mem, WqT, bq, qb, Bc*Mc, Cc, 0, 0);
        attn_topk_kernel<<<dim3(Bc*Hc, Q_BLOCKS), 256, SMEM_TOPK>>>(qb, kb, vb, ao);
        add_ln_kernel<<<(Bc*Mc + 7)/8, 256>>>(mem, ao, g1, b1, mem, Bc*Mc);
        tgemm(mem, WmT, bm, h1, Bc*Mc, Cc, 1, 0);
        tgemm(h1,  WmT, bm, h2, Bc*Mc, Cc, 1, 0);
        add_ln_kernel<<<(Bc*Mc + 7)/8, 256>>>(mem, h2, g2, b2, mem, Bc*Mc);
    }

    // gates
    repmean_kernel<<<Bc, Cc>>>(inp, rep_w, rm);
    gemm_kernel<<<dim3(2*Cc/64, 1), 256>>>(rm, Wig, big, gi, Bc, Cc, 2*Cc, 0);
    tgemm(memory, WmgT, bmg, gt, Bc*Mc, 2*Cc, 0, 1);   // tanh fused into A staging
    gate_kernel<<<2048, 256>>>(gt, gi, mem, memory, ib, fb, out_nm);

    // hx = attention(q from inp, k/v from next_memory), no topk
    tgemm(inp,    WqT, bq, qb, Bc*Tc, Cc, 0, 0);
    tgemm(out_nm, WkT, bk, kb, Bc*Mc, Cc, 0, 0);
    tgemm(out_nm, WvT, bv, vb, Bc*Mc, Cc, 0, 0);
    attn_hx_kernel<<<dim3(Bc*Hc, Tc/32), 256, SMEM_HX>>>(qb, kb, vb, out_hx);
}

// round 9
// speedup vs baseline: 3.9165x; 1.0376x over previous
#include <cuda_runtime.h>
#include <cuda_fp16.h>
#include <math.h>
#include <stdint.h>

#define Bc 32
#define Tc 128
#define Mc 1290
#define Cc 512
#define Hc 8
#define NBLK 4
#define TOPK 8
#define KVS 1024   // kv row stride (k | v interleaved)

static __device__ float d_inp[Bc*Tc*Cc];
static __device__ float d_mem[(size_t)Bc*Mc*Cc];
static __device__ float d_qb [(size_t)Bc*Mc*Cc];
static __device__ float d_kvs[(size_t)Bc*Tc*KVS];     // small kv (from inp)
static __device__ float d_ao [(size_t)Bc*Mc*Cc];
static __device__ float d_h1 [(size_t)Bc*Mc*Cc];
static __device__ float d_h2 [(size_t)Bc*Mc*Cc];
static __device__ float d_gt [(size_t)Bc*Mc*2*Cc];    // gates, later reused as kv_big
static __device__ float d_rm [Bc*Cc];
static __device__ float d_gi [Bc*2*Cc];
static __device__ float d_bkv[2*Cc];
static __device__ __half d_WqT[Cc*Cc];
static __device__ __half d_WkvT[2*Cc*Cc];
static __device__ __half d_WmT[Cc*Cc];
static __device__ __half d_WpT[Cc*Cc];
static __device__ __half d_WmgT[Cc*2*Cc];

#define F_INF __int_as_float(0x7f800000)

__device__ __forceinline__ uint32_t smem_u32(const void* p){
    uint32_t a;
    asm("{ .reg .u64 t; cvta.to.shared.u64 t, %1; cvt.u32.u64 %0, t; }" : "=r"(a) : "l"(p));
    return a;
}
__device__ __forceinline__ uint32_t pack2(float x, float y){
    __half2 h = __floats2half2_rn(x, y);
    return *reinterpret_cast<uint32_t*>(&h);
}
__device__ __forceinline__ void mma_f16(float* d, const uint32_t* a, const uint32_t* b){
    asm volatile("mma.sync.aligned.m16n8k16.row.col.f32.f16.f16.f32 "
        "{%0,%1,%2,%3}, {%4,%5,%6,%7}, {%8,%9}, {%0,%1,%2,%3};"
        : "+f"(d[0]), "+f"(d[1]), "+f"(d[2]), "+f"(d[3])
        : "r"(a[0]), "r"(a[1]), "r"(a[2]), "r"(a[3]), "r"(b[0]), "r"(b[1]));
}

// ============ fp16 mma.sync GEMM: out[N,NO] = A[N,512] @ WT[NO,512]^T + bias ============
// block 128x128, K-chunk 32, 256 thr = 8 warps (4m x 2n), warp tile 32x64, m16n8k16.
// A: reg-prefetch + convert + STS; B: cp.async (already half). SMEM pitch 40 halves.
#define APH 40
#define CHH (128*APH)
#define TG_SMEM (4*CHH*2)
__global__ __launch_bounds__(256) void f16_gemm_kernel(
    const float* __restrict__ A, const __half* __restrict__ WT,
    const float* __restrict__ bias, float* __restrict__ out,
    int Nrows, int K, int NO, int relu, int dotanh)
{
    extern __shared__ __half smh[];
    int tid = threadIdx.x;
    int wid = tid >> 5, lane = tid & 31;
    int wm = wid & 3, wn = wid >> 2;
    int lr = lane >> 2, lc = lane & 3;
    int row0 = blockIdx.y * 128;
    int col0 = blockIdx.x * 128;

    float acc[2][8][4];
    #pragma unroll
    for (int i=0;i<2;i++)
        #pragma unroll
        for (int j=0;j<8;j++)
            #pragma unroll
            for (int l=0;l<4;l++) acc[i][j][l] = 0.f;

    int arow = tid & 127;
    int akb  = (tid >> 7) * 16;
    bool apred = (row0 + arow) < Nrows;
    const float*  aptr = A  + (size_t)(row0 + arow)*K + akb;
    const __half* bptr = WT + (size_t)(col0 + arow)*K + akb;
    uint32_t bsts = smem_u32(smh + arow*APH + akb);   // byte addr of B slot (buf 0 A-region)

    float4 pA[4];
    #pragma unroll
    for (int j=0;j<4;j++) pA[j] = make_float4(0.f,0.f,0.f,0.f);

    const int nc = K / 32;   // 16

    auto issueB = [&](int c){
        uint32_t bd = bsts + ((c & 1)*2*CHH + CHH)*2;   // bytes
        const __half* src = bptr + c*32;
        asm volatile("cp.async.ca.shared.global [%0], [%1], 16;" :: "r"(bd), "l"(src) : "memory");
        asm volatile("cp.async.ca.shared.global [%0], [%1], 16;" :: "r"(bd+16), "l"(src+8) : "memory");
        asm volatile("cp.async.commit_group;" ::: "memory");
    };
    auto preloadA = [&](int c){
        if (apred) {
            #pragma unroll
            for (int j = 0; j < 4; j++)
                pA[j] = *reinterpret_cast<const float4*>(aptr + c*32 + j*4);
        }
    };

    issueB(0);
    preloadA(0);
    for (int c = 0; c < nc; c++) {
        // ---- stage A into buf c&1 ----
        {
            __half* As = smh + (c & 1)*2*CHH;
            float v[16];
            #pragma unroll
            for (int j=0;j<4;j++){
                v[j*4+0]=pA[j].x; v[j*4+1]=pA[j].y; v[j*4+2]=pA[j].z; v[j*4+3]=pA[j].w;
            }
            if (dotanh) {
                #pragma unroll
                for (int j=0;j<16;j++) v[j] = tanhf(v[j]);
            }
            uint4 h0, h1;
            h0.x = pack2(v[0],v[1]);   h0.y = pack2(v[2],v[3]);
            h0.z = pack2(v[4],v[5]);   h0.w = pack2(v[6],v[7]);
            h1.x = pack2(v[8],v[9]);   h1.y = pack2(v[10],v[11]);
            h1.z = pack2(v[12],v[13]); h1.w = pack2(v[14],v[15]);
            *reinterpret_cast<uint4*>(As + arow*APH + akb)     = h0;
            *reinterpret_cast<uint4*>(As + arow*APH + akb + 8) = h1;
        }
        asm volatile("cp.async.wait_group 0;" ::: "memory");
        __syncthreads();
        if (c + 1 < nc) { issueB(c + 1); preloadA(c + 1); }
        // ---- compute from buf c&1 ----
        {
            const __half* As = smh + (c & 1)*2*CHH;
            const __half* Bs = As + CHH;
            #pragma unroll
            for (int ks = 0; ks < 2; ks++) {
                int kb = ks*16;
                uint32_t af[2][4];
                #pragma unroll
                for (int ma = 0; ma < 2; ma++) {
                    int r = wm*32 + ma*16;
                    af[ma][0] = *reinterpret_cast<const uint32_t*>(As + (r+lr  )*APH + kb + 2*lc);
                    af[ma][1] = *reinterpret_cast<const uint32_t*>(As + (r+lr+8)*APH + kb + 2*lc);
                    af[ma][2] = *reinterpret_cast<const uint32_t*>(As + (r+lr  )*APH + kb + 8 + 2*lc);
                    af[ma][3] = *reinterpret_cast<const uint32_t*>(As + (r+lr+8)*APH + kb + 8 + 2*lc);
                }
                uint32_t bf[8][2];
                #pragma unroll
                for (int na = 0; na < 8; na++) {
                    int n = wn*64 + na*8 + lr;
                    bf[na][0] = *reinterpret_cast<const uint32_t*>(Bs + n*APH + kb + 2*lc);
                    bf[na][1] = *reinterpret_cast<const uint32_t*>(Bs + n*APH + kb + 8 + 2*lc);
                }
                #pragma unroll
                for (int ma = 0; ma < 2; ma++)
                    #pragma unroll
                    for (int na = 0; na < 8; na++)
                        mma_f16(acc[ma][na], af[ma], bf[na]);
            }
        }
        __syncthreads();
    }

    #pragma unroll
    for (int ma = 0; ma < 2; ma++) {
        int r1 = row0 + wm*32 + ma*16 + lr;
        int r2 = r1 + 8;
        #pragma unroll
        for (int na = 0; na < 8; na++) {
            int col = col0 + wn*64 + na*8 + lc*2;
            float bx = bias[col], by = bias[col+1];
            float2 o1 = make_float2(acc[ma][na][0] + bx, acc[ma][na][1] + by);
            float2 o2 = make_float2(acc[ma][na][2] + bx, acc[ma][na][3] + by);
            if (relu) {
                o1.x = fmaxf(o1.x,0.f); o1.y = fmaxf(o1.y,0.f);
                o2.x = fmaxf(o2.x,0.f); o2.y = fmaxf(o2.y,0.f);
            }
            if (r1 < Nrows) *reinterpret_cast<float2*>(out + (size_t)r1*NO + col) = o1;
            if (r2 < Nrows) *reinterpret_cast<float2*>(out + (size_t)r2*NO + col) = o2;
        }
    }
}

// ============ batched transpose + half convert + bias concat (ONE launch) ============
struct TPack {
    const float* in[6];
    __half* out[6];
    int C[6];
    const float* bk; const float* bv; float* bkv;
};
__global__ __launch_bounds__(256) void transpose_all_kernel(TPack p)
{
    __shared__ float t[32][33];
    int w = blockIdx.z;
    int C = p.C[w];
    int c0 = blockIdx.x*32;
    if (c0 >= C) return;
    int r0 = blockIdx.y*32;
    if (w == 0 && c0 == 0 && r0 == 0) {   // bias concat piggyback
        int i = threadIdx.x;
        if (i < 256) { p.bkv[i*2] = p.bk[i*2]; p.bkv[i*2+1] = p.bk[i*2+1]; }
        p.bkv[Cc + i*2] = p.bv[i*2]; p.bkv[Cc + i*2+1] = p.bv[i*2+1];
    }
    const float* in = p.in[w];
    __half* out = p.out[w];
    int x = threadIdx.x & 31, y = threadIdx.x >> 5;
    #pragma unroll
    for (int i = 0; i < 4; i++)
        t[y + i*8][x] = in[(size_t)(r0 + y + i*8)*C + c0 + x];
    __syncthreads();
    #pragma unroll
    for (int i = 0; i < 4; i++)
        out[(size_t)(c0 + y + i*8)*Cc + r0 + x] = __float2half(t[x][y + i*8]);
}

// ============ SIMT GEMM (tiny) ============
__global__ __launch_bounds__(256) void gemm_kernel(
    const float* __restrict__ A, const float* __restrict__ W,
    const float* __restrict__ bias, float* __restrict__ out,
    int N, int K, int NO, int relu)
{
    __shared__ float As[16][64];
    __shared__ float Bs[16][64];
    int t  = threadIdx.x;
    int tx = t & 15, ty = t >> 4;
    int row0 = blockIdx.y * 64;
    int col0 = blockIdx.x * 64;
    float acc[4][4] = {};
    for (int k0 = 0; k0 < K; k0 += 16) {
        {
            int r = t >> 2;
            int c4 = (t & 3) * 4;
            float4 av = make_float4(0.f,0.f,0.f,0.f);
            if (row0 + r < N)
                av = *reinterpret_cast<const float4*>(A + (size_t)(row0 + r) * K + k0 + c4);
            As[c4+0][r] = av.x; As[c4+1][r] = av.y; As[c4+2][r] = av.z; As[c4+3][r] = av.w;
        }
        {
            int r  = t >> 4;
            int c4 = (t & 15) * 4;
            float4 bv = *reinterpret_cast<const float4*>(W + (size_t)(k0 + r) * NO + col0 + c4);
            *reinterpret_cast<float4*>(&Bs[r][c4]) = bv;
        }
        __syncthreads();
        #pragma unroll
        for (int kk = 0; kk < 16; kk++) {
            float4 a4 = *reinterpret_cast<const float4*>(&As[kk][ty*4]);
            float4 b4 = *reinterpret_cast<const float4*>(&Bs[kk][tx*4]);
            float a[4] = {a4.x,a4.y,a4.z,a4.w};
            float b[4] = {b4.x,b4.y,b4.z,b4.w};
            #pragma unroll
            for (int i=0;i<4;i++)
                #pragma unroll
                for (int j=0;j<4;j++) acc[i][j] += a[i]*b[j];
        }
        __syncthreads();
    }
    float4 bb = *reinterpret_cast<const float4*>(bias + col0 + tx*4);
    #pragma unroll
    for (int i=0;i<4;i++) {
        int r = row0 + ty*4 + i;
        if (r >= N) continue;
        float4 o4;
        o4.x = acc[i][0] + bb.x; o4.y = acc[i][1] + bb.y;
        o4.z = acc[i][2] + bb.z; o4.w = acc[i][3] + bb.w;
        if (relu) {
            o4.x = fmaxf(o4.x,0.f); o4.y = fmaxf(o4.y,0.f);
            o4.z = fmaxf(o4.z,0.f); o4.w = fmaxf(o4.w,0.f);
        }
        *reinterpret_cast<float4*>(out + (size_t)r * NO + col0 + tx*4) = o4;
    }
}

// ============ warp reductions (x4-interleaved) ============
__device__ __forceinline__ void warpMax4(float* c){
    #pragma unroll
    for (int o=16;o;o>>=1){
        #pragma unroll
        for (int qq=0;qq<4;qq++) c[qq] = fmaxf(c[qq], __shfl_xor_sync(0xffffffffu, c[qq], o));
    }
}
__device__ __forceinline__ void warpSum4(float* c){
    #pragma unroll
    for (int o=16;o;o>>=1){
        #pragma unroll
        for (int qq=0;qq<4;qq++) c[qq] += __shfl_xor_sync(0xffffffffu, c[qq], o);
    }
}

// ============ top-k attention: kv interleaved input ============
#define Q_BLOCKS 6
#define SMEM_TOPK ((64*128 + 128*64 + 8*4*64)*4)
__global__ __launch_bounds__(256) void attn_topk_kernel(
    const float* __restrict__ q, const float* __restrict__ kv,
    float* __restrict__ o)
{
    extern __shared__ float sm[];
    float* Kt = sm;
    float* Vs = Kt + 64*128;
    float* sq = Vs + 128*64;

    int tid = threadIdx.x;
    int warp = tid >> 5, lane = tid & 31;
    int bh = blockIdx.x, b = bh / Hc, h = bh % Hc;

    for (int idx = tid; idx < 128*16; idx += 256) {
        int t = idx >> 4, j = idx & 15;
        size_t row = ((size_t)b*Tc + t)*KVS + h*64 + j*4;
        float4 kvv = *reinterpret_cast<const float4*>(kv + row);
        float4 vv  = *reinterpret_cast<const float4*>(kv + row + Cc);
        Kt[(j*4+0)*128 + t] = kvv.x;
        Kt[(j*4+1)*128 + t] = kvv.y;
        Kt[(j*4+2)*128 + t] = kvv.z;
        Kt[(j*4+3)*128 + t] = kvv.w;
        *reinterpret_cast<float4*>(&Vs[t*64 + j*4]) = vv;
    }
    __syncthreads();

    const int nq = (Mc + Q_BLOCKS - 1) / Q_BLOCKS;
    int q0 = blockIdx.y * nq;
    int qend = min(q0 + nq, Mc);
    float* sqw = sq + warp*256;

    for (int qi0 = q0 + warp*4; qi0 < qend; qi0 += 32) {
        #pragma unroll
        for (int f = 0; f < 2; f++) {
            int ff = lane + f*32;
            int qq = ff >> 4, j = ff & 15;
            int qi = qi0 + qq;
            if (qi < qend) {
                float4 qv = *reinterpret_cast<const float4*>(q + ((size_t)b*Mc + qi)*Cc + h*64 + j*4);
                *reinterpret_cast<float4*>(&sqw[qq*64 + j*4]) = qv;
            }
        }
        __syncwarp();
        float s[4][4];
        #pragma unroll
        for (int qq=0;qq<4;qq++)
            #pragma unroll
            for (int j=0;j<4;j++) s[qq][j] = 0.f;
        #pragma unroll 4
        for (int d0 = 0; d0 < 64; d0 += 4) {
            float4 kk4[4];
            #pragma unroll
            for (int dd = 0; dd < 4; dd++)
                kk4[dd] = *reinterpret_cast<const float4*>(&Kt[(d0+dd)*128 + lane*4]);
            #pragma unroll
            for (int qq = 0; qq < 4; qq++) {
                float4 qd = *reinterpret_cast<const float4*>(&sqw[qq*64 + d0]);
                s[qq][0] += qd.x*kk4[0].x + qd.y*kk4[1].x + qd.z*kk4[2].x + qd.w*kk4[3].x;
                s[qq][1] += qd.x*kk4[0].y + qd.y*kk4[1].y + qd.z*kk4[2].y + qd.w*kk4[3].y;
                s[qq][2] += qd.x*kk4[0].z + qd.y*kk4[1].z + qd.z*kk4[2].z + qd.w*kk4[3].z;
                s[qq][3] += qd.x*kk4[0].w + qd.y*kk4[1].w + qd.z*kk4[2].w + qd.w*kk4[3].w;
            }
        }
        #pragma unroll
        for (int qq=0;qq<4;qq++)
            #pragma unroll
            for (int j=0;j<4;j++) s[qq][j] *= 0.125f;

        float thr[4], gmax[4], c[4];
        #pragma unroll
        for (int qq=0;qq<4;qq++)
            c[qq] = fmaxf(fmaxf(s[qq][0],s[qq][1]), fmaxf(s[qq][2],s[qq][3]));
        warpMax4(c);
        #pragma unroll
        for (int qq=0;qq<4;qq++){ gmax[qq] = c[qq]; thr[qq] = c[qq]; }
        #pragma unroll
        for (int it = 1; it < TOPK; it++) {
            #pragma unroll
            for (int qq=0;qq<4;qq++){
                float m = -F_INF;
                #pragma unroll
                for (int j=0;j<4;j++) m = fmaxf(m, (s[qq][j] < thr[qq]) ? s[qq][j] : -F_INF);
                c[qq] = m;
            }
            warpMax4(c);
            #pragma unroll
            for (int qq=0;qq<4;qq++) thr[qq] = c[qq];
        }
        float e[4][4], le[4];
        #pragma unroll
        for (int qq=0;qq<4;qq++){
            le[qq] = 0.f;
            #pragma unroll
            for (int j=0;j<4;j++){ e[qq][j] = __expf(s[qq][j] - gmax[qq]); le[qq] += e[qq][j]; }
        }
        warpSum4(le);

        int d0v = lane*2;
        #pragma unroll
        for (int qq = 0; qq < 4; qq++) {
            int qi = qi0 + qq;
            if (qi >= qend) break;
            float inv = 1.f / le[qq];
            float p[4];
            #pragma unroll
            for (int j=0;j<4;j++) p[j] = (s[qq][j] >= thr[qq]) ? e[qq][j]*inv : 0.f;
            float2 acc = make_float2(0.f, 0.f);
            #pragma unroll
            for (int j=0;j<4;j++) {
                unsigned msk = __ballot_sync(0xffffffffu, p[j] != 0.f);
                while (msk) {
                    int src = __ffs(msk) - 1;
                    msk &= msk - 1;
                    float pv = __shfl_sync(0xffffffffu, p[j], src);
                    int key = src*4 + j;
                    float2 vv = *reinterpret_cast<const float2*>(&Vs[key*64 + d0v]);
                    acc.x += pv*vv.x; acc.y += pv*vv.y;
                }
            }
            *reinterpret_cast<float2*>(o + ((size_t)b*Mc + qi)*Cc + h*64 + d0v) = acc;
        }
    }
}

// ============ hx attention: kv interleaved input ============
#define SMEM_HX ((64*128 + 128*64 + 32*64 + 8*4*128)*4)
__global__ __launch_bounds__(256) void attn_hx_kernel(
    const float* __restrict__ q, const float* __restrict__ kv,
    float* __restrict__ o)
{
    extern __shared__ float sm[];
    float* Kt = sm;
    float* Vs = Kt + 64*128;
    float* sq = Vs + 128*64;
    float* ps = sq + 32*64;

    int tid = threadIdx.x;
    int warp = tid >> 5, lane = tid & 31;
    int bh = blockIdx.x, b = bh / Hc, h = bh % Hc;
    int q0 = blockIdx.y * 32;

    for (int idx = tid; idx < 32*16; idx += 256) {
        int qi = idx >> 4, j = idx & 15;
        float4 qv = *reinterpret_cast<const float4*>(q + ((size_t)b*Tc + q0 + qi)*Cc + h*64 + j*4);
        *reinterpret_cast<float4*>(&sq[qi*64 + j*4]) = qv;
    }

    float m[4], den[4];
    float2 acc[4];
    #pragma unroll
    for (int i=0;i<4;i++){ m[i] = -F_INF; den[i] = 0.f; acc[i] = make_float2(0.f,0.f); }
    int d0v = lane*2;
    float* psw = ps + warp*512;

    for (int c0 = 0; c0 < Mc; c0 += 128) {
        int nk = min(128, Mc - c0);
        __syncthreads();
        for (int idx = tid; idx < 128*16; idx += 256) {
            int t = idx >> 4, j = idx & 15;
            float4 kvv = make_float4(0.f,0.f,0.f,0.f), vv = kvv;
            if (t < nk) {
                size_t row = ((size_t)b*Mc + c0 + t)*KVS + h*64 + j*4;
                kvv = *reinterpret_cast<const float4*>(kv + row);
                vv  = *reinterpret_cast<const float4*>(kv + row + Cc);
            }
            Kt[(j*4+0)*128 + t] = kvv.x;
            Kt[(j*4+1)*128 + t] = kvv.y;
            Kt[(j*4+2)*128 + t] = kvv.z;
            Kt[(j*4+3)*128 + t] = kvv.w;
            *reinterpret_cast<float4*>(&Vs[t*64 + j*4]) = vv;
        }
        __syncthreads();

        float s[4][4];
        #pragma unroll
        for (int i=0;i<4;i++)
            #pragma unroll
            for (int j=0;j<4;j++) s[i][j] = 0.f;
        #pragma unroll 4
        for (int d0 = 0; d0 < 64; d0 += 4) {
            float4 kk4[4];
            #pragma unroll
            for (int dd = 0; dd < 4; dd++)
                kk4[dd] = *reinterpret_cast<const float4*>(&Kt[(d0+dd)*128 + lane*4]);
            #pragma unroll
            for (int i = 0; i < 4; i++) {
                float4 qd = *reinterpret_cast<const float4*>(&sq[(warp*4+i)*64 + d0]);
                s[i][0] += qd.x*kk4[0].x + qd.y*kk4[1].x + qd.z*kk4[2].x + qd.w*kk4[3].x;
                s[i][1] += qd.x*kk4[0].y + qd.y*kk4[1].y + qd.z*kk4[2].y + qd.w*kk4[3].y;
                s[i][2] += qd.x*kk4[0].z + qd.y*kk4[1].z + qd.z*kk4[2].z + qd.w*kk4[3].z;
                s[i][3] += qd.x*kk4[0].w + qd.y*kk4[1].w + qd.z*kk4[2].w + qd.w*kk4[3].w;
            }
        }
        float lm[4];
        #pragma unroll
        for (int i = 0; i < 4; i++) {
            float mm = -F_INF;
            #pragma unroll
            for (int j=0;j<4;j++) {
                s[i][j] = (lane*4 + j < nk) ? s[i][j]*0.125f : -F_INF;
                mm = fmaxf(mm, s[i][j]);
            }
            lm[i] = mm;
        }
        warpMax4(lm);
        float f[4], le[4];
        #pragma unroll
        for (int i = 0; i < 4; i++) {
            float newm = fmaxf(m[i], lm[i]);
            f[i] = __expf(m[i] - newm);
            m[i] = newm;
            float e0 = __expf(s[i][0]-newm), e1 = __expf(s[i][1]-newm);
            float e2 = __expf(s[i][2]-newm), e3 = __expf(s[i][3]-newm);
            le[i] = e0+e1+e2+e3;
            *reinterpret_cast<float4*>(&psw[i*128 + lane*4]) = make_float4(e0,e1,e2,e3);
        }
        warpSum4(le);
        #pragma unroll
        for (int i = 0; i < 4; i++) {
            den[i] = den[i]*f[i] + le[i];
            acc[i].x *= f[i]; acc[i].y *= f[i];
        }
        __syncwarp();
        #pragma unroll 4
        for (int kk = 0; kk < 128; kk++) {
            float2 vv = *reinterpret_cast<const float2*>(&Vs[kk*64 + d0v]);
            float p0 = psw[0*128 + kk], p1 = psw[1*128 + kk];
            float p2 = psw[2*128 + kk], p3 = psw[3*128 + kk];
            acc[0].x += p0*vv.x; acc[0].y += p0*vv.y;
            acc[1].x += p1*vv.x; acc[1].y += p1*vv.y;
            acc[2].x += p2*vv.x; acc[2].y += p2*vv.y;
            acc[3].x += p3*vv.x; acc[3].y += p3*vv.y;
        }
    }
    #pragma unroll
    for (int i=0;i<4;i++) {
        int qi = q0 + warp*4 + i;
        float invd = 1.f / den[i];
        float2 ov = make_float2(acc[i].x*invd, acc[i].y*invd);
        *reinterpret_cast<float2*>(o + ((size_t)b*Tc + qi)*Cc + h*64 + d0v) = ov;
    }
}

// ============ add + layernorm ============
__global__ __launch_bounds__(256) void add_ln_kernel(
    const float* __restrict__ x, const float* __restrict__ r,
    const float* __restrict__ g, const float* __restrict__ bb,
    float* __restrict__ out, int nrows)
{
    int warp = (blockIdx.x * blockDim.x + threadIdx.x) >> 5;
    int lane = threadIdx.x & 31;
    if (warp >= nrows) return;
    const float* xr = x + (size_t)warp * Cc;
    const float* rr = r + (size_t)warp * Cc;
    float vals[16];
    float s = 0.f;
    #pragma unroll
    for (int i=0;i<16;i++) { float vv = xr[lane + i*32] + rr[lane + i*32]; vals[i] = vv; s += vv; }
    #pragma unroll
    for (int o2=16;o2;o2>>=1) s += __shfl_xor_sync(0xffffffffu, s, o2);
    float mu = s * (1.f/512.f);
    float vs = 0.f;
    #pragma unroll
    for (int i=0;i<16;i++){ float d = vals[i]-mu; vs += d*d; }
    #pragma unroll
    for (int o2=16;o2;o2>>=1) vs += __shfl_xor_sync(0xffffffffu, vs, o2);
    float rstd = rsqrtf(vs*(1.f/512.f) + 1e-5f);
    float* outr = out + (size_t)warp * Cc;
    #pragma unroll
    for (int i=0;i<16;i++){ int cc = lane + i*32; outr[cc] = (vals[i]-mu)*rstd*g[cc] + bb[cc]; }
}

// ============ misc elementwise ============
__global__ void repmean_kernel(const float* __restrict__ inp, const float* __restrict__ rep_w,
                               float* __restrict__ out)
{
    int b = blockIdx.x, c = threadIdx.x;
    const float* base = inp + (size_t)b*Tc*Cc + c;
    float rw = rep_w[c];
    float s = 0.f;
    for (int t=0;t<Tc;t++) s += fmaxf(rw * base[(size_t)t*Cc], 0.f);
    out[b*Cc + c] = s * (1.f/Tc);
}

__global__ void gate_kernel(const float* __restrict__ gates, const float* __restrict__ gi,
                            const float* __restrict__ mem_final, const float* __restrict__ mem0,
                            const float* __restrict__ ib, const float* __restrict__ fb,
                            float* __restrict__ nm)
{
    size_t n = (size_t)Bc*Mc*Cc;
    size_t i = (size_t)blockIdx.x*blockDim.x + threadIdx.x;
    size_t st = (size_t)gridDim.x*blockDim.x;
    float ibv = ib[0], fbv = fb[0];
    for (; i < n; i += st) {
        int c = (int)(i % Cc);
        size_t bm = i / Cc;
        int b = (int)(bm / Mc);
        float gI = gates[bm*2*Cc + c]      + gi[b*2*Cc + c]      + ibv;
        float gF = gates[bm*2*Cc + Cc + c] + gi[b*2*Cc + Cc + c] + fbv;
        float igv = 1.f/(1.f + __expf(-gI));
        float fgv = 1.f/(1.f + __expf(-gF));
        nm[i] = igv * tanhf(mem_final[i]) + fgv * mem0[i];
    }
}

// ============ launch ============
extern "C" void kernel_launch(void* const* d_in, const int* in_sizes, int n_in,
                              void* d_out, int out_size)
{
    const float* ipts   = (const float*)d_in[0];
    const float* memory = (const float*)d_in[1];
    const float* Wq=(const float*)d_in[2],  *bq=(const float*)d_in[3];
    const float* Wk=(const float*)d_in[4],  *bk=(const float*)d_in[5];
    const float* Wv=(const float*)d_in[6],  *bv=(const float*)d_in[7];
    const float* Wm=(const float*)d_in[8],  *bm=(const float*)d_in[9];
    const float* g1=(const float*)d_in[10], *b1=(const float*)d_in[11];
    const float* g2=(const float*)d_in[12], *b2=(const float*)d_in[13];
    const float* Wp=(const float*)d_in[14], *bp=(const float*)d_in[15];
    const float* rep_w=(const float*)d_in[16];
    const float* Wig=(const float*)d_in[17], *big=(const float*)d_in[18];
    const float* Wmg=(const float*)d_in[19], *bmg=(const float*)d_in[20];
    const float* fb=(const float*)d_in[21], *ib=(const float*)d_in[22];

    float* out_nm = (float*)d_out;
    float* out_hx = out_nm + (size_t)Bc*Mc*Cc;

    float *inp,*mem,*qb,*kvs,*ao,*h1,*h2,*gt,*rm,*gi,*bkv;
    __half *WqT,*WkvT,*WmT,*WpT,*WmgT;
    cudaGetSymbolAddress((void**)&inp, d_inp);
    cudaGetSymbolAddress((void**)&mem, d_mem);
    cudaGetSymbolAddress((void**)&qb,  d_qb);
    cudaGetSymbolAddress((void**)&kvs, d_kvs);
    cudaGetSymbolAddress((void**)&ao,  d_ao);
    cudaGetSymbolAddress((void**)&h1,  d_h1);
    cudaGetSymbolAddress((void**)&h2,  d_h2);
    cudaGetSymbolAddress((void**)&gt,  d_gt);
    cudaGetSymbolAddress((void**)&rm,  d_rm);
    cudaGetSymbolAddress((void**)&gi,  d_gi);
    cudaGetSymbolAddress((void**)&bkv, d_bkv);
    cudaGetSymbolAddress((void**)&WqT, d_WqT);
    cudaGetSymbolAddress((void**)&WkvT, d_WkvT);
    cudaGetSymbolAddress((void**)&WmT, d_WmT);
    cudaGetSymbolAddress((void**)&WpT, d_WpT);
    cudaGetSymbolAddress((void**)&WmgT, d_WmgT);

    cudaFuncSetAttribute(attn_topk_kernel, cudaFuncAttributeMaxDynamicSharedMemorySize, SMEM_TOPK);
    cudaFuncSetAttribute(attn_hx_kernel,   cudaFuncAttributeMaxDynamicSharedMemorySize, SMEM_HX);
    cudaFuncSetAttribute(f16_gemm_kernel,  cudaFuncAttributeMaxDynamicSharedMemorySize, TG_SMEM);

    TPack tp;
    tp.in[0]=Wq;  tp.out[0]=WqT;           tp.C[0]=Cc;
    tp.in[1]=Wk;  tp.out[1]=WkvT;          tp.C[1]=Cc;
    tp.in[2]=Wv;  tp.out[2]=WkvT + Cc*Cc;  tp.C[2]=Cc;
    tp.in[3]=Wm;  tp.out[3]=WmT;           tp.C[3]=Cc;
    tp.in[4]=Wp;  tp.out[4]=WpT;           tp.C[4]=Cc;
    tp.in[5]=Wmg; tp.out[5]=WmgT;          tp.C[5]=2*Cc;
    tp.bk = bk; tp.bv = bv; tp.bkv = bkv;
    transpose_all_kernel<<<dim3(32,16,6), 256>>>(tp);
    cudaMemcpyAsync(mem, memory, sizeof(float)*(size_t)Bc*Mc*Cc, cudaMemcpyDeviceToDevice);

    auto tgemm = [&](const float* A, const __half* WT, const float* bias, float* o,
                     int N, int NO, int relu, int dotanh){
        f16_gemm_kernel<<<dim3(NO/128, (N+127)/128), 256, TG_SMEM>>>(
            A, WT, bias, o, N, Cc, NO, relu, dotanh);
    };

    // inp = ipts @ Wp + bp ; fused k|v (loop-invariant) in ONE GEMM
    tgemm(ipts, WpT, bp, inp, Bc*Tc, Cc, 0, 0);
    tgemm(inp, WkvT, bkv, kvs, Bc*Tc, KVS, 0, 0);

    for (int blk = 0; blk < NBLK; blk++) {
        tgemm(mem, WqT, bq, qb, Bc*Mc, Cc, 0, 0);
        attn_topk_kernel<<<dim3(Bc*Hc, Q_BLOCKS), 256, SMEM_TOPK>>>(qb, kvs, ao);
        add_ln_kernel<<<(Bc*Mc + 7)/8, 256>>>(mem, ao, g1, b1, mem, Bc*Mc);
        tgemm(mem, WmT, bm, h1, Bc*Mc, Cc, 1, 0);
        tgemm(h1,  WmT, bm, h2, Bc*Mc, Cc, 1, 0);
        add_ln_kernel<<<(Bc*Mc + 7)/8, 256>>>(mem, h2, g2, b2, mem, Bc*Mc);
    }

    // gates
    repmean_kernel<<<Bc, Cc>>>(inp, rep_w, rm);
    gemm_kernel<<<dim3(2*Cc/64, 1), 256>>>(rm, Wig, big, gi, Bc, Cc, 2*Cc, 0);
    tgemm(memory, WmgT, bmg, gt, Bc*Mc, 2*Cc, 0, 1);   // tanh fused into A staging
    gate_kernel<<<2048, 256>>>(gt, gi, mem, memory, ib, fb, out_nm);

    // hx: q from inp; fused k|v from next_memory in ONE GEMM (reuse gt as kv_big)
    tgemm(inp,    WqT, bq, qb, Bc*Tc, Cc, 0, 0);
    tgemm(out_nm, WkvT, bkv, gt, Bc*Mc, KVS, 0, 0);
    attn_hx_kernel<<<dim3(Bc*Hc, Tc/32), 256, SMEM_HX>>>(qb, gt, out_hx);
}

// round 10
// speedup vs baseline: 4.1119x; 1.0499x over previous
#include <cuda_runtime.h>
#include <cuda_fp16.h>
#include <math.h>
#include <stdint.h>

#define Bc 32
#define Tc 128
#define Mc 1290
#define Cc 512
#define Hc 8
#define NBLK 4
#define TOPK 8
#define KVS 1024

static __device__ float d_inp[Bc*Tc*Cc];
static __device__ float d_mem[(size_t)Bc*Mc*Cc];
static __device__ float d_qb [(size_t)Bc*Mc*Cc];
static __device__ float d_kvs[(size_t)Bc*Tc*KVS];
static __device__ float d_ao [(size_t)Bc*Mc*Cc];
static __device__ float d_h1 [(size_t)Bc*Mc*Cc];
static __device__ float d_h2 [(size_t)Bc*Mc*Cc];
static __device__ float d_gt [(size_t)Bc*Mc*2*Cc];
static __device__ float d_rm [Bc*Cc];
static __device__ float d_gi [Bc*2*Cc];
static __device__ float d_bkv[2*Cc];
static __device__ __half d_WqT[Cc*Cc];
static __device__ __half d_WkvT[2*Cc*Cc];
static __device__ __half d_WmT[Cc*Cc];
static __device__ __half d_WpT[Cc*Cc];
static __device__ __half d_WmgT[Cc*2*Cc];

#define F_INF __int_as_float(0x7f800000)

__device__ __forceinline__ uint32_t smem_u32(const void* p){
    uint32_t a;
    asm("{ .reg .u64 t; cvta.to.shared.u64 t, %1; cvt.u32.u64 %0, t; }" : "=r"(a) : "l"(p));
    return a;
}
__device__ __forceinline__ uint32_t pack2(float x, float y){
    __half2 h = __floats2half2_rn(x, y);
    return *reinterpret_cast<uint32_t*>(&h);
}
__device__ __forceinline__ void mma_f16(float* d, const uint32_t* a, const uint32_t* b){
    asm volatile("mma.sync.aligned.m16n8k16.row.col.f32.f16.f16.f32 "
        "{%0,%1,%2,%3}, {%4,%5,%6,%7}, {%8,%9}, {%0,%1,%2,%3};"
        : "+f"(d[0]), "+f"(d[1]), "+f"(d[2]), "+f"(d[3])
        : "r"(a[0]), "r"(a[1]), "r"(a[2]), "r"(a[3]), "r"(b[0]), "r"(b[1]));
}
__device__ __forceinline__ void ldsm4(uint32_t* r, uint32_t addr){
    asm volatile("ldmatrix.sync.aligned.m8n8.x4.shared.b16 {%0,%1,%2,%3}, [%4];"
        : "=r"(r[0]), "=r"(r[1]), "=r"(r[2]), "=r"(r[3]) : "r"(addr));
}

// ============ fp16 mma.sync GEMM with ldmatrix fragments ============
// block 128x128, K-chunk 32, 256 thr = 8 warps (4m x 2n), warp tile 32x64.
#define APH 40
#define CHH (128*APH)
#define TG_SMEM (4*CHH*2)
__global__ __launch_bounds__(256) void f16_gemm_kernel(
    const float* __restrict__ A, const __half* __restrict__ WT,
    const float* __restrict__ bias, float* __restrict__ out,
    int Nrows, int K, int NO, int relu, int dotanh)
{
    extern __shared__ __half smh[];
    int tid = threadIdx.x;
    int wid = tid >> 5, lane = tid & 31;
    int wm = wid & 3, wn = wid >> 2;
    int lr = lane >> 2, lc = lane & 3;
    int row0 = blockIdx.y * 128;
    int col0 = blockIdx.x * 128;

    float acc[2][8][4];
    #pragma unroll
    for (int i=0;i<2;i++)
        #pragma unroll
        for (int j=0;j<8;j++)
            #pragma unroll
            for (int l=0;l<4;l++) acc[i][j][l] = 0.f;

    int arow = tid & 127;
    int akb  = (tid >> 7) * 16;
    bool apred = (row0 + arow) < Nrows;
    const float*  aptr = A  + (size_t)(row0 + arow)*K + akb;
    const __half* bptr = WT + (size_t)(col0 + arow)*K + akb;
    uint32_t bsts = smem_u32(smh + arow*APH + akb);

    // ldmatrix per-lane relative byte offsets (within a buffer, kb=0)
    int lt = lane >> 3;           // tile index 0..3
    int lrw = lane & 7;           // row within tile
    uint32_t aoff[2], boff[4];
    #pragma unroll
    for (int ma = 0; ma < 2; ma++) {
        int r = wm*32 + ma*16 + lrw + ((lt & 1) << 3);
        int kk = (lt >> 1) * 8;
        aoff[ma] = (uint32_t)((r*APH + kk) * 2);
    }
    #pragma unroll
    for (int g = 0; g < 4; g++) {
        int n = wn*64 + (g*2 + (lt >> 1))*8 + lrw;
        int kk = (lt & 1) * 8;
        boff[g] = (uint32_t)(CHH*2 + (n*APH + kk) * 2);
    }
    uint32_t sbase = smem_u32(smh);

    float4 pA[4];
    #pragma unroll
    for (int j=0;j<4;j++) pA[j] = make_float4(0.f,0.f,0.f,0.f);

    const int nc = K / 32;

    auto issueB = [&](int c){
        uint32_t bd = bsts + ((c & 1)*2*CHH + CHH)*2;
        const __half* src = bptr + c*32;
        asm volatile("cp.async.ca.shared.global [%0], [%1], 16;" :: "r"(bd), "l"(src) : "memory");
        asm volatile("cp.async.ca.shared.global [%0], [%1], 16;" :: "r"(bd+16), "l"(src+8) : "memory");
        asm volatile("cp.async.commit_group;" ::: "memory");
    };
    auto preloadA = [&](int c){
        if (apred) {
            #pragma unroll
            for (int j = 0; j < 4; j++)
                pA[j] = *reinterpret_cast<const float4*>(aptr + c*32 + j*4);
        }
    };

    issueB(0);
    preloadA(0);
    for (int c = 0; c < nc; c++) {
        {
            __half* As = smh + (c & 1)*2*CHH;
            float v[16];
            #pragma unroll
            for (int j=0;j<4;j++){
                v[j*4+0]=pA[j].x; v[j*4+1]=pA[j].y; v[j*4+2]=pA[j].z; v[j*4+3]=pA[j].w;
            }
            if (dotanh) {
                #pragma unroll
                for (int j=0;j<16;j++) v[j] = tanhf(v[j]);
            }
            uint4 h0, h1;
            h0.x = pack2(v[0],v[1]);   h0.y = pack2(v[2],v[3]);
            h0.z = pack2(v[4],v[5]);   h0.w = pack2(v[6],v[7]);
            h1.x = pack2(v[8],v[9]);   h1.y = pack2(v[10],v[11]);
            h1.z = pack2(v[12],v[13]); h1.w = pack2(v[14],v[15]);
            *reinterpret_cast<uint4*>(As + arow*APH + akb)     = h0;
            *reinterpret_cast<uint4*>(As + arow*APH + akb + 8) = h1;
        }
        asm volatile("cp.async.wait_group 0;" ::: "memory");
        __syncthreads();
        if (c + 1 < nc) { issueB(c + 1); preloadA(c + 1); }
        {
            uint32_t buf = sbase + (c & 1)*2*CHH*2;
            #pragma unroll
            for (int ks = 0; ks < 2; ks++) {
                uint32_t kbb = ks*16*2;
                uint32_t af[2][4];
                #pragma unroll
                for (int ma = 0; ma < 2; ma++)
                    ldsm4(af[ma], buf + aoff[ma] + kbb);
                uint32_t bf[8][2];
                #pragma unroll
                for (int g = 0; g < 4; g++) {
                    uint32_t r4[4];
                    ldsm4(r4, buf + boff[g] + kbb);
                    bf[g*2  ][0] = r4[0]; bf[g*2  ][1] = r4[1];
                    bf[g*2+1][0] = r4[2]; bf[g*2+1][1] = r4[3];
                }
                #pragma unroll
                for (int ma = 0; ma < 2; ma++)
                    #pragma unroll
                    for (int na = 0; na < 8; na++)
                        mma_f16(acc[ma][na], af[ma], bf[na]);
            }
        }
        __syncthreads();
    }

    #pragma unroll
    for (int ma = 0; ma < 2; ma++) {
        int r1 = row0 + wm*32 + ma*16 + lr;
        int r2 = r1 + 8;
        #pragma unroll
        for (int na = 0; na < 8; na++) {
            int col = col0 + wn*64 + na*8 + lc*2;
            float bx = bias[col], by = bias[col+1];
            float2 o1 = make_float2(acc[ma][na][0] + bx, acc[ma][na][1] + by);
            float2 o2 = make_float2(acc[ma][na][2] + bx, acc[ma][na][3] + by);
            if (relu) {
                o1.x = fmaxf(o1.x,0.f); o1.y = fmaxf(o1.y,0.f);
                o2.x = fmaxf(o2.x,0.f); o2.y = fmaxf(o2.y,0.f);
            }
            if (r1 < Nrows) *reinterpret_cast<float2*>(out + (size_t)r1*NO + col) = o1;
            if (r2 < Nrows) *reinterpret_cast<float2*>(out + (size_t)r2*NO + col) = o2;
        }
    }
}

// ============ batched transpose + half convert + bias concat ============
struct TPack {
    const float* in[6];
    __half* out[6];
    int C[6];
    const float* bk; const float* bv; float* bkv;
};
__global__ __launch_bounds__(256) void transpose_all_kernel(TPack p)
{
    __shared__ float t[32][33];
    int w = blockIdx.z;
    int C = p.C[w];
    int c0 = blockIdx.x*32;
    if (c0 >= C) return;
    int r0 = blockIdx.y*32;
    if (w == 0 && c0 == 0 && r0 == 0) {
        int i = threadIdx.x;
        p.bkv[i*2] = p.bk[i*2]; p.bkv[i*2+1] = p.bk[i*2+1];
        p.bkv[Cc + i*2] = p.bv[i*2]; p.bkv[Cc + i*2+1] = p.bv[i*2+1];
    }
    const float* in = p.in[w];
    __half* out = p.out[w];
    int x = threadIdx.x & 31, y = threadIdx.x >> 5;
    #pragma unroll
    for (int i = 0; i < 4; i++)
        t[y + i*8][x] = in[(size_t)(r0 + y + i*8)*C + c0 + x];
    __syncthreads();
    #pragma unroll
    for (int i = 0; i < 4; i++)
        out[(size_t)(c0 + y + i*8)*Cc + r0 + x] = __float2half(t[x][y + i*8]);
}

// ============ SIMT GEMM (tiny) ============
__global__ __launch_bounds__(256) void gemm_kernel(
    const float* __restrict__ A, const float* __restrict__ W,
    const float* __restrict__ bias, float* __restrict__ out,
    int N, int K, int NO, int relu)
{
    __shared__ float As[16][64];
    __shared__ float Bs[16][64];
    int t  = threadIdx.x;
    int tx = t & 15, ty = t >> 4;
    int row0 = blockIdx.y * 64;
    int col0 = blockIdx.x * 64;
    float acc[4][4] = {};
    for (int k0 = 0; k0 < K; k0 += 16) {
        {
            int r = t >> 2;
            int c4 = (t & 3) * 4;
            float4 av = make_float4(0.f,0.f,0.f,0.f);
            if (row0 + r < N)
                av = *reinterpret_cast<const float4*>(A + (size_t)(row0 + r) * K + k0 + c4);
            As[c4+0][r] = av.x; As[c4+1][r] = av.y; As[c4+2][r] = av.z; As[c4+3][r] = av.w;
        }
        {
            int r  = t >> 4;
            int c4 = (t & 15) * 4;
            float4 bv = *reinterpret_cast<const float4*>(W + (size_t)(k0 + r) * NO + col0 + c4);
            *reinterpret_cast<float4*>(&Bs[r][c4]) = bv;
        }
        __syncthreads();
        #pragma unroll
        for (int kk = 0; kk < 16; kk++) {
            float4 a4 = *reinterpret_cast<const float4*>(&As[kk][ty*4]);
            float4 b4 = *reinterpret_cast<const float4*>(&Bs[kk][tx*4]);
            float a[4] = {a4.x,a4.y,a4.z,a4.w};
            float b[4] = {b4.x,b4.y,b4.z,b4.w};
            #pragma unroll
            for (int i=0;i<4;i++)
                #pragma unroll
                for (int j=0;j<4;j++) acc[i][j] += a[i]*b[j];
        }
        __syncthreads();
    }
    float4 bb = *reinterpret_cast<const float4*>(bias + col0 + tx*4);
    #pragma unroll
    for (int i=0;i<4;i++) {
        int r = row0 + ty*4 + i;
        if (r >= N) continue;
        float4 o4;
        o4.x = acc[i][0] + bb.x; o4.y = acc[i][1] + bb.y;
        o4.z = acc[i][2] + bb.z; o4.w = acc[i][3] + bb.w;
        if (relu) {
            o4.x = fmaxf(o4.x,0.f); o4.y = fmaxf(o4.y,0.f);
            o4.z = fmaxf(o4.z,0.f); o4.w = fmaxf(o4.w,0.f);
        }
        *reinterpret_cast<float4*>(out + (size_t)r * NO + col0 + tx*4) = o4;
    }
}

// ============ warp reductions (x4-interleaved) ============
__device__ __forceinline__ void warpMax4(float* c){
    #pragma unroll
    for (int o=16;o;o>>=1){
        #pragma unroll
        for (int qq=0;qq<4;qq++) c[qq] = fmaxf(c[qq], __shfl_xor_sync(0xffffffffu, c[qq], o));
    }
}
__device__ __forceinline__ void warpSum4(float* c){
    #pragma unroll
    for (int o=16;o;o>>=1){
        #pragma unroll
        for (int qq=0;qq<4;qq++) c[qq] += __shfl_xor_sync(0xffffffffu, c[qq], o);
    }
}

// ============ top-k attention ============
#define Q_BLOCKS 6
#define SMEM_TOPK ((64*128 + 128*64 + 8*4*64)*4)
__global__ __launch_bounds__(256) void attn_topk_kernel(
    const float* __restrict__ q, const float* __restrict__ kv,
    float* __restrict__ o)
{
    extern __shared__ float sm[];
    float* Kt = sm;
    float* Vs = Kt + 64*128;
    float* sq = Vs + 128*64;

    int tid = threadIdx.x;
    int warp = tid >> 5, lane = tid & 31;
    int bh = blockIdx.x, b = bh / Hc, h = bh % Hc;

    for (int idx = tid; idx < 128*16; idx += 256) {
        int t = idx >> 4, j = idx & 15;
        size_t row = ((size_t)b*Tc + t)*KVS + h*64 + j*4;
        float4 kvv = *reinterpret_cast<const float4*>(kv + row);
        float4 vv  = *reinterpret_cast<const float4*>(kv + row + Cc);
        Kt[(j*4+0)*128 + t] = kvv.x;
        Kt[(j*4+1)*128 + t] = kvv.y;
        Kt[(j*4+2)*128 + t] = kvv.z;
        Kt[(j*4+3)*128 + t] = kvv.w;
        *reinterpret_cast<float4*>(&Vs[t*64 + j*4]) = vv;
    }
    __syncthreads();

    const int nq = (Mc + Q_BLOCKS - 1) / Q_BLOCKS;
    int q0 = blockIdx.y * nq;
    int qend = min(q0 + nq, Mc);
    float* sqw = sq + warp*256;

    for (int qi0 = q0 + warp*4; qi0 < qend; qi0 += 32) {
        #pragma unroll
        for (int f = 0; f < 2; f++) {
            int ff = lane + f*32;
            int qq = ff >> 4, j = ff & 15;
            int qi = qi0 + qq;
            if (qi < qend) {
                float4 qv = *reinterpret_cast<const float4*>(q + ((size_t)b*Mc + qi)*Cc + h*64 + j*4);
                *reinterpret_cast<float4*>(&sqw[qq*64 + j*4]) = qv;
            }
        }
        __syncwarp();
        float s[4][4];
        #pragma unroll
        for (int qq=0;qq<4;qq++)
            #pragma unroll
            for (int j=0;j<4;j++) s[qq][j] = 0.f;
        #pragma unroll 4
        for (int d0 = 0; d0 < 64; d0 += 4) {
            float4 kk4[4];
            #pragma unroll
            for (int dd = 0; dd < 4; dd++)
                kk4[dd] = *reinterpret_cast<const float4*>(&Kt[(d0+dd)*128 + lane*4]);
            #pragma unroll
            for (int qq = 0; qq < 4; qq++) {
                float4 qd = *reinterpret_cast<const float4*>(&sqw[qq*64 + d0]);
                s[qq][0] += qd.x*kk4[0].x + qd.y*kk4[1].x + qd.z*kk4[2].x + qd.w*kk4[3].x;
                s[qq][1] += qd.x*kk4[0].y + qd.y*kk4[1].y + qd.z*kk4[2].y + qd.w*kk4[3].y;
                s[qq][2] += qd.x*kk4[0].z + qd.y*kk4[1].z + qd.z*kk4[2].z + qd.w*kk4[3].z;
                s[qq][3] += qd.x*kk4[0].w + qd.y*kk4[1].w + qd.z*kk4[2].w + qd.w*kk4[3].w;
            }
        }
        #pragma unroll
        for (int qq=0;qq<4;qq++)
            #pragma unroll
            for (int j=0;j<4;j++) s[qq][j] *= 0.125f;

        float thr[4], gmax[4], c[4];
        #pragma unroll
        for (int qq=0;qq<4;qq++)
            c[qq] = fmaxf(fmaxf(s[qq][0],s[qq][1]), fmaxf(s[qq][2],s[qq][3]));
        warpMax4(c);
        #pragma unroll
        for (int qq=0;qq<4;qq++){ gmax[qq] = c[qq]; thr[qq] = c[qq]; }
        #pragma unroll
        for (int it = 1; it < TOPK; it++) {
            #pragma unroll
            for (int qq=0;qq<4;qq++){
                float m = -F_INF;
                #pragma unroll
                for (int j=0;j<4;j++) m = fmaxf(m, (s[qq][j] < thr[qq]) ? s[qq][j] : -F_INF);
                c[qq] = m;
            }
            warpMax4(c);
            #pragma unroll
            for (int qq=0;qq<4;qq++) thr[qq] = c[qq];
        }
        float e[4][4], le[4];
        #pragma unroll
        for (int qq=0;qq<4;qq++){
            le[qq] = 0.f;
            #pragma unroll
            for (int j=0;j<4;j++){ e[qq][j] = __expf(s[qq][j] - gmax[qq]); le[qq] += e[qq][j]; }
        }
        warpSum4(le);

        int d0v = lane*2;
        #pragma unroll
        for (int qq = 0; qq < 4; qq++) {
            int qi = qi0 + qq;
            if (qi >= qend) break;
            float inv = 1.f / le[qq];
            float p[4];
            #pragma unroll
            for (int j=0;j<4;j++) p[j] = (s[qq][j] >= thr[qq]) ? e[qq][j]*inv : 0.f;
            float2 acc = make_float2(0.f, 0.f);
            #pragma unroll
            for (int j=0;j<4;j++) {
                unsigned msk = __ballot_sync(0xffffffffu, p[j] != 0.f);
                while (msk) {
                    int src = __ffs(msk) - 1;
                    msk &= msk - 1;
                    float pv = __shfl_sync(0xffffffffu, p[j], src);
                    int key = src*4 + j;
                    float2 vv = *reinterpret_cast<const float2*>(&Vs[key*64 + d0v]);
                    acc.x += pv*vv.x; acc.y += pv*vv.y;
                }
            }
            *reinterpret_cast<float2*>(o + ((size_t)b*Mc + qi)*Cc + h*64 + d0v) = acc;
        }
    }
}

// ============ hx attention ============
#define SMEM_HX ((64*128 + 128*64 + 32*64 + 8*4*128)*4)
__global__ __launch_bounds__(256) void attn_hx_kernel(
    const float* __restrict__ q, const float* __restrict__ kv,
    float* __restrict__ o)
{
    extern __shared__ float sm[];
    float* Kt = sm;
    float* Vs = Kt + 64*128;
    float* sq = Vs + 128*64;
    float* ps = sq + 32*64;

    int tid = threadIdx.x;
    int warp = tid >> 5, lane = tid & 31;
    int bh = blockIdx.x, b = bh / Hc, h = bh % Hc;
    int q0 = blockIdx.y * 32;

    for (int idx = tid; idx < 32*16; idx += 256) {
        int qi = idx >> 4, j = idx & 15;
        float4 qv = *reinterpret_cast<const float4*>(q + ((size_t)b*Tc + q0 + qi)*Cc + h*64 + j*4);
        *reinterpret_cast<float4*>(&sq[qi*64 + j*4]) = qv;
    }

    float m[4], den[4];
    float2 acc[4];
    #pragma unroll
    for (int i=0;i<4;i++){ m[i] = -F_INF; den[i] = 0.f; acc[i] = make_float2(0.f,0.f); }
    int d0v = lane*2;
    float* psw = ps + warp*512;

    for (int c0 = 0; c0 < Mc; c0 += 128) {
        int nk = min(128, Mc - c0);
        __syncthreads();
        for (int idx = tid; idx < 128*16; idx += 256) {
            int t = idx >> 4, j = idx & 15;
            float4 kvv = make_float4(0.f,0.f,0.f,0.f), vv = kvv;
            if (t < nk) {
                size_t row = ((size_t)b*Mc + c0 + t)*KVS + h*64 + j*4;
                kvv = *reinterpret_cast<const float4*>(kv + row);
                vv  = *reinterpret_cast<const float4*>(kv + row + Cc);
            }
            Kt[(j*4+0)*128 + t] = kvv.x;
            Kt[(j*4+1)*128 + t] = kvv.y;
            Kt[(j*4+2)*128 + t] = kvv.z;
            Kt[(j*4+3)*128 + t] = kvv.w;
            *reinterpret_cast<float4*>(&Vs[t*64 + j*4]) = vv;
        }
        __syncthreads();

        float s[4][4];
        #pragma unroll
        for (int i=0;i<4;i++)
            #pragma unroll
            for (int j=0;j<4;j++) s[i][j] = 0.f;
        #pragma unroll 4
        for (int d0 = 0; d0 < 64; d0 += 4) {
            float4 kk4[4];
            #pragma unroll
            for (int dd = 0; dd < 4; dd++)
                kk4[dd] = *reinterpret_cast<const float4*>(&Kt[(d0+dd)*128 + lane*4]);
            #pragma unroll
            for (int i = 0; i < 4; i++) {
                float4 qd = *reinterpret_cast<const float4*>(&sq[(warp*4+i)*64 + d0]);
                s[i][0] += qd.x*kk4[0].x + qd.y*kk4[1].x + qd.z*kk4[2].x + qd.w*kk4[3].x;
                s[i][1] += qd.x*kk4[0].y + qd.y*kk4[1].y + qd.z*kk4[2].y + qd.w*kk4[3].y;
                s[i][2] += qd.x*kk4[0].z + qd.y*kk4[1].z + qd.z*kk4[2].z + qd.w*kk4[3].z;
                s[i][3] += qd.x*kk4[0].w + qd.y*kk4[1].w + qd.z*kk4[2].w + qd.w*kk4[3].w;
            }
        }
        float lm[4];
        #pragma unroll
        for (int i = 0; i < 4; i++) {
            float mm = -F_INF;
            #pragma unroll
            for (int j=0;j<4;j++) {
                s[i][j] = (lane*4 + j < nk) ? s[i][j]*0.125f : -F_INF;
                mm = fmaxf(mm, s[i][j]);
            }
            lm[i] = mm;
        }
        warpMax4(lm);
        float f[4], le[4];
        #pragma unroll
        for (int i = 0; i < 4; i++) {
            float newm = fmaxf(m[i], lm[i]);
            f[i] = __expf(m[i] - newm);
            m[i] = newm;
            float e0 = __expf(s[i][0]-newm), e1 = __expf(s[i][1]-newm);
            float e2 = __expf(s[i][2]-newm), e3 = __expf(s[i][3]-newm);
            le[i] = e0+e1+e2+e3;
            *reinterpret_cast<float4*>(&psw[i*128 + lane*4]) = make_float4(e0,e1,e2,e3);
        }
        warpSum4(le);
        #pragma unroll
        for (int i = 0; i < 4; i++) {
            den[i] = den[i]*f[i] + le[i];
            acc[i].x *= f[i]; acc[i].y *= f[i];
        }
        __syncwarp();
        #pragma unroll 4
        for (int kk = 0; kk < 128; kk++) {
            float2 vv = *reinterpret_cast<const float2*>(&Vs[kk*64 + d0v]);
            float p0 = psw[0*128 + kk], p1 = psw[1*128 + kk];
            float p2 = psw[2*128 + kk], p3 = psw[3*128 + kk];
            acc[0].x += p0*vv.x; acc[0].y += p0*vv.y;
            acc[1].x += p1*vv.x; acc[1].y += p1*vv.y;
            acc[2].x += p2*vv.x; acc[2].y += p2*vv.y;
            acc[3].x += p3*vv.x; acc[3].y += p3*vv.y;
        }
    }
    #pragma unroll
    for (int i=0;i<4;i++) {
        int qi = q0 + warp*4 + i;
        float invd = 1.f / den[i];
        float2 ov = make_float2(acc[i].x*invd, acc[i].y*invd);
        *reinterpret_cast<float2*>(o + ((size_t)b*Tc + qi)*Cc + h*64 + d0v) = ov;
    }
}

// ============ add + layernorm ============
__global__ __launch_bounds__(256) void add_ln_kernel(
    const float* __restrict__ x, const float* __restrict__ r,
    const float* __restrict__ g, const float* __restrict__ bb,
    float* __restrict__ out, int nrows)
{
    int warp = (blockIdx.x * blockDim.x + threadIdx.x) >> 5;
    int lane = threadIdx.x & 31;
    if (warp >= nrows) return;
    const float* xr = x + (size_t)warp * Cc;
    const float* rr = r + (size_t)warp * Cc;
    float vals[16];
    float s = 0.f;
    #pragma unroll
    for (int i=0;i<16;i++) { float vv = xr[lane + i*32] + rr[lane + i*32]; vals[i] = vv; s += vv; }
    #pragma unroll
    for (int o2=16;o2;o2>>=1) s += __shfl_xor_sync(0xffffffffu, s, o2);
    float mu = s * (1.f/512.f);
    float vs = 0.f;
    #pragma unroll
    for (int i=0;i<16;i++){ float d = vals[i]-mu; vs += d*d; }
    #pragma unroll
    for (int o2=16;o2;o2>>=1) vs += __shfl_xor_sync(0xffffffffu, vs, o2);
    float rstd = rsqrtf(vs*(1.f/512.f) + 1e-5f);
    float* outr = out + (size_t)warp * Cc;
    #pragma unroll
    for (int i=0;i<16;i++){ int cc = lane + i*32; outr[cc] = (vals[i]-mu)*rstd*g[cc] + bb[cc]; }
}

// ============ misc elementwise ============
__global__ void repmean_kernel(const float* __restrict__ inp, const float* __restrict__ rep_w,
                               float* __restrict__ out)
{
    int b = blockIdx.x, c = threadIdx.x;
    const float* base = inp + (size_t)b*Tc*Cc + c;
    float rw = rep_w[c];
    float s = 0.f;
    for (int t=0;t<Tc;t++) s += fmaxf(rw * base[(size_t)t*Cc], 0.f);
    out[b*Cc + c] = s * (1.f/Tc);
}

__global__ void gate_kernel(const float* __restrict__ gates, const float* __restrict__ gi,
                            const float* __restrict__ mem_final, const float* __restrict__ mem0,
                            const float* __restrict__ ib, const float* __restrict__ fb,
                            float* __restrict__ nm)
{
    size_t n = (size_t)Bc*Mc*Cc;
    size_t i = (size_t)blockIdx.x*blockDim.x + threadIdx.x;
    size_t st = (size_t)gridDim.x*blockDim.x;
    float ibv = ib[0], fbv = fb[0];
    for (; i < n; i += st) {
        int c = (int)(i % Cc);
        size_t bm = i / Cc;
        int b = (int)(bm / Mc);
        float gI = gates[bm*2*Cc + c]      + gi[b*2*Cc + c]      + ibv;
        float gF = gates[bm*2*Cc + Cc + c] + gi[b*2*Cc + Cc + c] + fbv;
        float igv = 1.f/(1.f + __expf(-gI));
        float fgv = 1.f/(1.f + __expf(-gF));
        nm[i] = igv * tanhf(mem_final[i]) + fgv * mem0[i];
    }
}

// ============ launch ============
extern "C" void kernel_launch(void* const* d_in, const int* in_sizes, int n_in,
                              void* d_out, int out_size)
{
    const float* ipts   = (const float*)d_in[0];
    const float* memory = (const float*)d_in[1];
    const float* Wq=(const float*)d_in[2],  *bq=(const float*)d_in[3];
    const float* Wk=(const float*)d_in[4],  *bk=(const float*)d_in[5];
    const float* Wv=(const float*)d_in[6],  *bv=(const float*)d_in[7];
    const float* Wm=(const float*)d_in[8],  *bm=(const float*)d_in[9];
    const float* g1=(const float*)d_in[10], *b1=(const float*)d_in[11];
    const float* g2=(const float*)d_in[12], *b2=(const float*)d_in[13];
    const float* Wp=(const float*)d_in[14], *bp=(const float*)d_in[15];
    const float* rep_w=(const float*)d_in[16];
    const float* Wig=(const float*)d_in[17], *big=(const float*)d_in[18];
    const float* Wmg=(const float*)d_in[19], *bmg=(const float*)d_in[20];
    const float* fb=(const float*)d_in[21], *ib=(const float*)d_in[22];

    float* out_nm = (float*)d_out;
    float* out_hx = out_nm + (size_t)Bc*Mc*Cc;

    float *inp,*mem,*qb,*kvs,*ao,*h1,*h2,*gt,*rm,*gi,*bkv;
    __half *WqT,*WkvT,*WmT,*WpT,*WmgT;
    cudaGetSymbolAddress((void**)&inp, d_inp);
    cudaGetSymbolAddress((void**)&mem, d_mem);
    cudaGetSymbolAddress((void**)&qb,  d_qb);
    cudaGetSymbolAddress((void**)&kvs, d_kvs);
    cudaGetSymbolAddress((void**)&ao,  d_ao);
    cudaGetSymbolAddress((void**)&h1,  d_h1);
    cudaGetSymbolAddress((void**)&h2,  d_h2);
    cudaGetSymbolAddress((void**)&gt,  d_gt);
    cudaGetSymbolAddress((void**)&rm,  d_rm);
    cudaGetSymbolAddress((void**)&gi,  d_gi);
    cudaGetSymbolAddress((void**)&bkv, d_bkv);
    cudaGetSymbolAddress((void**)&WqT, d_WqT);
    cudaGetSymbolAddress((void**)&WkvT, d_WkvT);
    cudaGetSymbolAddress((void**)&WmT, d_WmT);
    cudaGetSymbolAddress((void**)&WpT, d_WpT);
    cudaGetSymbolAddress((void**)&WmgT, d_WmgT);

    cudaFuncSetAttribute(attn_topk_kernel, cudaFuncAttributeMaxDynamicSharedMemorySize, SMEM_TOPK);
    cudaFuncSetAttribute(attn_hx_kernel,   cudaFuncAttributeMaxDynamicSharedMemorySize, SMEM_HX);
    cudaFuncSetAttribute(f16_gemm_kernel,  cudaFuncAttributeMaxDynamicSharedMemorySize, TG_SMEM);

    TPack tp;
    tp.in[0]=Wq;  tp.out[0]=WqT;           tp.C[0]=Cc;
    tp.in[1]=Wk;  tp.out[1]=WkvT;          tp.C[1]=Cc;
    tp.in[2]=Wv;  tp.out[2]=WkvT + Cc*Cc;  tp.C[2]=Cc;
    tp.in[3]=Wm;  tp.out[3]=WmT;           tp.C[3]=Cc;
    tp.in[4]=Wp;  tp.out[4]=WpT;           tp.C[4]=Cc;
    tp.in[5]=Wmg; tp.out[5]=WmgT;          tp.C[5]=2*Cc;
    tp.bk = bk; tp.bv = bv; tp.bkv = bkv;
    transpose_all_kernel<<<dim3(32,16,6), 256>>>(tp);
    cudaMemcpyAsync(mem, memory, sizeof(float)*(size_t)Bc*Mc*Cc, cudaMemcpyDeviceToDevice);

    auto tgemm = [&](const float* A, const __half* WT, const float* bias, float* o,
                     int N, int NO, int relu, int dotanh){
        f16_gemm_kernel<<<dim3(NO/128, (N+127)/128), 256, TG_SMEM>>>(
            A, WT, bias, o, N, Cc, NO, relu, dotanh);
    };

    tgemm(ipts, WpT, bp, inp, Bc*Tc, Cc, 0, 0);
    tgemm(inp, WkvT, bkv, kvs, Bc*Tc, KVS, 0, 0);

    for (int blk = 0; blk < NBLK; blk++) {
        tgemm(mem, WqT, bq, qb, Bc*Mc, Cc, 0, 0);
        attn_topk_kernel<<<dim3(Bc*Hc, Q_BLOCKS), 256, SMEM_TOPK>>>(qb, kvs, ao);
        add_ln_kernel<<<(Bc*Mc + 7)/8, 256>>>(mem, ao, g1, b1, mem, Bc*Mc);
        tgemm(mem, WmT, bm, h1, Bc*Mc, Cc, 1, 0);
        tgemm(h1,  WmT, bm, h2, Bc*Mc, Cc, 1, 0);
        add_ln_kernel<<<(Bc*Mc + 7)/8, 256>>>(mem, h2, g2, b2, mem, Bc*Mc);
    }

    repmean_kernel<<<Bc, Cc>>>(inp, rep_w, rm);
    gemm_kernel<<<dim3(2*Cc/64, 1), 256>>>(rm, Wig, big, gi, Bc, Cc, 2*Cc, 0);
    tgemm(memory, WmgT, bmg, gt, Bc*Mc, 2*Cc, 0, 1);
    gate_kernel<<<2048, 256>>>(gt, gi, mem, memory, ib, fb, out_nm);

    tgemm(inp,    WqT, bq, qb, Bc*Tc, Cc, 0, 0);
    tgemm(out_nm, WkvT, bkv, gt, Bc*Mc, KVS, 0, 0);
    attn_hx_kernel<<<dim3(Bc*Hc, Tc/32), 256, SMEM_HX>>>(qb, gt, out_hx);
}

// round 12
// speedup vs baseline: 4.7090x; 1.1452x over previous
#include <cuda_runtime.h>
#include <cuda_fp16.h>
#include <math.h>
#include <stdint.h>

#define Bc 32
#define Tc 128
#define Mc 1290
#define Cc 512
#define Hc 8
#define NBLK 4
#define TOPK 8
#define KVS 1024

static __device__ float d_inp[Bc*Tc*Cc];
static __device__ float d_mem[(size_t)Bc*Mc*Cc];
static __device__ float d_qb [(size_t)Bc*Mc*Cc];
static __device__ float d_kvs[(size_t)Bc*Tc*KVS];
static __device__ float d_ao [(size_t)Bc*Mc*Cc];
static __device__ float d_h2 [(size_t)Bc*Mc*Cc];
static __device__ float d_gt [(size_t)Bc*Mc*2*Cc];
static __device__ float d_rm [Bc*Cc];
static __device__ float d_gi [Bc*2*Cc];
static __device__ float d_bkv[2*Cc];
// half activation mirrors
static __device__ __half d_ipts_h[Bc*Tc*Cc];
static __device__ __half d_inp_h [Bc*Tc*Cc];
static __device__ __half d_mem_h [(size_t)Bc*Mc*Cc];
static __device__ __half d_h1_h  [(size_t)Bc*Mc*Cc];
static __device__ __half d_tm_h  [(size_t)Bc*Mc*Cc];
static __device__ __half d_nm_h  [(size_t)Bc*Mc*Cc];
// half weights (K-major)
static __device__ __half d_WqT[Cc*Cc];
static __device__ __half d_WkvT[2*Cc*Cc];
static __device__ __half d_WmT[Cc*Cc];
static __device__ __half d_WpT[Cc*Cc];
static __device__ __half d_WmgT[Cc*2*Cc];

#define F_INF __int_as_float(0x7f800000)

__device__ __forceinline__ uint32_t smem_u32(const void* p){
    uint32_t a;
    asm("{ .reg .u64 t; cvta.to.shared.u64 t, %1; cvt.u32.u64 %0, t; }" : "=r"(a) : "l"(p));
    return a;
}
__device__ __forceinline__ void mma_f16(float* d, const uint32_t* a, const uint32_t* b){
    asm volatile("mma.sync.aligned.m16n8k16.row.col.f32.f16.f16.f32 "
        "{%0,%1,%2,%3}, {%4,%5,%6,%7}, {%8,%9}, {%0,%1,%2,%3};"
        : "+f"(d[0]), "+f"(d[1]), "+f"(d[2]), "+f"(d[3])
        : "r"(a[0]), "r"(a[1]), "r"(a[2]), "r"(a[3]), "r"(b[0]), "r"(b[1]));
}
__device__ __forceinline__ void ldsm4(uint32_t* r, uint32_t addr){
    asm volatile("ldmatrix.sync.aligned.m8n8.x4.shared.b16 {%0,%1,%2,%3}, [%4];"
        : "=r"(r[0]), "=r"(r[1]), "=r"(r[2]), "=r"(r[3]) : "r"(addr));
}
__device__ __forceinline__ void cp16(uint32_t dst, const void* src, int sz){
    asm volatile("cp.async.ca.shared.global [%0], [%1], 16, %2;"
                 :: "r"(dst), "l"(src), "r"(sz) : "memory");
}

// ============ all-half GEMM: outf/outh[N,NO] = Ah[N,512] @ WT[NO,512]^T + bias ============
// block 128x128, K-chunk 32, 4-stage cp.async pipeline, ONE barrier per chunk.
// Tail iterations commit EMPTY groups so wait_group 2 always drains group c.
#define APH 40
#define CHH (128*APH)
#define NSTG 4
#define TG_SMEM (NSTG*2*CHH*2)
__global__ __launch_bounds__(256) void f16_gemm_kernel(
    const __half* __restrict__ A, const __half* __restrict__ WT,
    const float* __restrict__ bias, float* __restrict__ outf,
    __half* __restrict__ outh,
    int Nrows, int K, int NO, int relu)
{
    extern __shared__ __half smh[];
    int tid = threadIdx.x;
    int wid = tid >> 5, lane = tid & 31;
    int wm = wid & 3, wn = wid >> 2;
    int lr = lane >> 2, lc = lane & 3;
    int row0 = blockIdx.y * 128;
    int col0 = blockIdx.x * 128;

    float acc[2][8][4];
    #pragma unroll
    for (int i=0;i<2;i++)
        #pragma unroll
        for (int j=0;j<8;j++)
            #pragma unroll
            for (int l=0;l<4;l++) acc[i][j][l] = 0.f;

    int arow = tid & 127;
    int seg  = (tid >> 7) * 16;
    bool apred = (row0 + arow) < Nrows;
    const __half* aptr = A  + (size_t)(row0 + arow)*K + seg;
    const __half* bptr = WT + (size_t)(col0 + arow)*K + seg;
    uint32_t sbase = smem_u32(smh);
    uint32_t adst = sbase + (arow*APH + seg)*2;

    int lt = lane >> 3, lrw = lane & 7;
    uint32_t aoff[2], boff[4];
    #pragma unroll
    for (int ma = 0; ma < 2; ma++) {
        int r = wm*32 + ma*16 + lrw + ((lt & 1) << 3);
        int kk = (lt >> 1) * 8;
        aoff[ma] = (uint32_t)((r*APH + kk) * 2);
    }
    #pragma unroll
    for (int g = 0; g < 4; g++) {
        int n = wn*64 + (g*2 + (lt >> 1))*8 + lrw;
        int kk = (lt & 1) * 8;
        boff[g] = (uint32_t)(CHH*2 + (n*APH + kk) * 2);
    }

    const int nc = K / 32;
    int asz = apred ? 16 : 0;

    auto issue = [&](int c){
        uint32_t off = (uint32_t)(c & (NSTG-1)) * 2*CHH*2;
        const __half* as = aptr + c*32;
        const __half* bs = bptr + c*32;
        cp16(adst + off,            as,     asz);
        cp16(adst + off + 16,       as + 8, asz);
        cp16(adst + off + CHH*2,      bs,     16);
        cp16(adst + off + CHH*2 + 16, bs + 8, 16);
        asm volatile("cp.async.commit_group;" ::: "memory");
    };

    issue(0); issue(1); issue(2);
    for (int c = 0; c < nc; c++) {
        asm volatile("cp.async.wait_group 2;" ::: "memory");
        __syncthreads();
        if (c + 3 < nc) issue(c + 3);
        else asm volatile("cp.async.commit_group;" ::: "memory");  // empty group keeps count
        uint32_t buf = sbase + (uint32_t)(c & (NSTG-1))*2*CHH*2;
        #pragma unroll
        for (int ks = 0; ks < 2; ks++) {
            uint32_t kbb = ks*32;
            uint32_t af[2][4];
            #pragma unroll
            for (int ma = 0; ma < 2; ma++)
                ldsm4(af[ma], buf + aoff[ma] + kbb);
            uint32_t bf[8][2];
            #pragma unroll
            for (int g = 0; g < 4; g++) {
                uint32_t r4[4];
                ldsm4(r4, buf + boff[g] + kbb);
                bf[g*2  ][0] = r4[0]; bf[g*2  ][1] = r4[1];
                bf[g*2+1][0] = r4[2]; bf[g*2+1][1] = r4[3];
            }
            #pragma unroll
            for (int ma = 0; ma < 2; ma++)
                #pragma unroll
                for (int na = 0; na < 8; na++)
                    mma_f16(acc[ma][na], af[ma], bf[na]);
        }
    }

    #pragma unroll
    for (int ma = 0; ma < 2; ma++) {
        int r1 = row0 + wm*32 + ma*16 + lr;
        int r2 = r1 + 8;
        #pragma unroll
        for (int na = 0; na < 8; na++) {
            int col = col0 + wn*64 + na*8 + lc*2;
            float bx = bias[col], by = bias[col+1];
            float2 o1 = make_float2(acc[ma][na][0] + bx, acc[ma][na][1] + by);
            float2 o2 = make_float2(acc[ma][na][2] + bx, acc[ma][na][3] + by);
            if (relu) {
                o1.x = fmaxf(o1.x,0.f); o1.y = fmaxf(o1.y,0.f);
                o2.x = fmaxf(o2.x,0.f); o2.y = fmaxf(o2.y,0.f);
            }
            if (outf) {
                if (r1 < Nrows) *reinterpret_cast<float2*>(outf + (size_t)r1*NO + col) = o1;
                if (r2 < Nrows) *reinterpret_cast<float2*>(outf + (size_t)r2*NO + col) = o2;
            }
            if (outh) {
                if (r1 < Nrows)
                    *reinterpret_cast<__half2*>(outh + (size_t)r1*NO + col) = __floats2half2_rn(o1.x, o1.y);
                if (r2 < Nrows)
                    *reinterpret_cast<__half2*>(outh + (size_t)r2*NO + col) = __floats2half2_rn(o2.x, o2.y);
            }
        }
    }
}

// ============ preamble convert ============
__global__ void convert_pre_kernel(const float* __restrict__ ipts, const float* __restrict__ memory,
                                   __half* __restrict__ ipts_h, __half* __restrict__ mem_h,
                                   __half* __restrict__ tm_h)
{
    size_t i = (size_t)blockIdx.x*blockDim.x + threadIdx.x;
    size_t st = (size_t)gridDim.x*blockDim.x;
    const size_t ni = (size_t)Bc*Tc*Cc;
    const size_t nm = (size_t)Bc*Mc*Cc;
    for (size_t j = i; j < ni; j += st) ipts_h[j] = __float2half(ipts[j]);
    for (size_t j = i; j < nm; j += st) {
        float v = memory[j];
        mem_h[j] = __float2half(v);
        tm_h[j]  = __float2half(tanhf(v));
    }
}

// ============ batched transpose + half convert + bias concat ============
struct TPack {
    const float* in[6];
    __half* out[6];
    int C[6];
    const float* bk; const float* bv; float* bkv;
};
__global__ __launch_bounds__(256) void transpose_all_kernel(TPack p)
{
    __shared__ float t[32][33];
    int w = blockIdx.z;
    int C = p.C[w];
    int c0 = blockIdx.x*32;
    if (c0 >= C) return;
    int r0 = blockIdx.y*32;
    if (w == 0 && c0 == 0 && r0 == 0) {
        int i = threadIdx.x;
        p.bkv[i*2] = p.bk[i*2]; p.bkv[i*2+1] = p.bk[i*2+1];
        p.bkv[Cc + i*2] = p.bv[i*2]; p.bkv[Cc + i*2+1] = p.bv[i*2+1];
    }
    const float* in = p.in[w];
    __half* out = p.out[w];
    int x = threadIdx.x & 31, y = threadIdx.x >> 5;
    #pragma unroll
    for (int i = 0; i < 4; i++)
        t[y + i*8][x] = in[(size_t)(r0 + y + i*8)*C + c0 + x];
    __syncthreads();
    #pragma unroll
    for (int i = 0; i < 4; i++)
        out[(size_t)(c0 + y + i*8)*Cc + r0 + x] = __float2half(t[x][y + i*8]);
}

// ============ SIMT GEMM (tiny) ============
__global__ __launch_bounds__(256) void gemm_kernel(
    const float* __restrict__ A, const float* __restrict__ W,
    const float* __restrict__ bias, float* __restrict__ out,
    int N, int K, int NO, int relu)
{
    __shared__ float As[16][64];
    __shared__ float Bs[16][64];
    int t  = threadIdx.x;
    int tx = t & 15, ty = t >> 4;
    int row0 = blockIdx.y * 64;
    int col0 = blockIdx.x * 64;
    float acc[4][4] = {};
    for (int k0 = 0; k0 < K; k0 += 16) {
        {
            int r = t >> 2;
            int c4 = (t & 3) * 4;
            float4 av = make_float4(0.f,0.f,0.f,0.f);
            if (row0 + r < N)
                av = *reinterpret_cast<const float4*>(A + (size_t)(row0 + r) * K + k0 + c4);
            As[c4+0][r] = av.x; As[c4+1][r] = av.y; As[c4+2][r] = av.z; As[c4+3][r] = av.w;
        }
        {
            int r  = t >> 4;
            int c4 = (t & 15) * 4;
            float4 bv = *reinterpret_cast<const float4*>(W + (size_t)(k0 + r) * NO + col0 + c4);
            *reinterpret_cast<float4*>(&Bs[r][c4]) = bv;
        }
        __syncthreads();
        #pragma unroll
        for (int kk = 0; kk < 16; kk++) {
            float4 a4 = *reinterpret_cast<const float4*>(&As[kk][ty*4]);
            float4 b4 = *reinterpret_cast<const float4*>(&Bs[kk][tx*4]);
            float a[4] = {a4.x,a4.y,a4.z,a4.w};
            float b[4] = {b4.x,b4.y,b4.z,b4.w};
            #pragma unroll
            for (int i=0;i<4;i++)
                #pragma unroll
                for (int j=0;j<4;j++) acc[i][j] += a[i]*b[j];
        }
        __syncthreads();
    }
    float4 bb = *reinterpret_cast<const float4*>(bias + col0 + tx*4);
    #pragma unroll
    for (int i=0;i<4;i++) {
        int r = row0 + ty*4 + i;
        if (r >= N) continue;
        float4 o4;
        o4.x = acc[i][0] + bb.x; o4.y = acc[i][1] + bb.y;
        o4.z = acc[i][2] + bb.z; o4.w = acc[i][3] + bb.w;
        if (relu) {
            o4.x = fmaxf(o4.x,0.f); o4.y = fmaxf(o4.y,0.f);
            o4.z = fmaxf(o4.z,0.f); o4.w = fmaxf(o4.w,0.f);
        }
        *reinterpret_cast<float4*>(out + (size_t)r * NO + col0 + tx*4) = o4;
    }
}

// ============ warp reductions (x4-interleaved) ============
__device__ __forceinline__ void warpMax4(float* c){
    #pragma unroll
    for (int o=16;o;o>>=1){
        #pragma unroll
        for (int qq=0;qq<4;qq++) c[qq] = fmaxf(c[qq], __shfl_xor_sync(0xffffffffu, c[qq], o));
    }
}
__device__ __forceinline__ void warpSum4(float* c){
    #pragma unroll
    for (int o=16;o;o>>=1){
        #pragma unroll
        for (int qq=0;qq<4;qq++) c[qq] += __shfl_xor_sync(0xffffffffu, c[qq], o);
    }
}

// ============ top-k attention ============
#define Q_BLOCKS 6
#define SMEM_TOPK ((64*128 + 128*64 + 8*4*64)*4)
__global__ __launch_bounds__(256) void attn_topk_kernel(
    const float* __restrict__ q, const float* __restrict__ kv,
    float* __restrict__ o)
{
    extern __shared__ float sm[];
    float* Kt = sm;
    float* Vs = Kt + 64*128;
    float* sq = Vs + 128*64;

    int tid = threadIdx.x;
    int warp = tid >> 5, lane = tid & 31;
    int bh = blockIdx.x, b = bh / Hc, h = bh % Hc;

    for (int idx = tid; idx < 128*16; idx += 256) {
        int t = idx >> 4, j = idx & 15;
        size_t row = ((size_t)b*Tc + t)*KVS + h*64 + j*4;
        float4 kvv = *reinterpret_cast<const float4*>(kv + row);
        float4 vv  = *reinterpret_cast<const float4*>(kv + row + Cc);
        Kt[(j*4+0)*128 + t] = kvv.x;
        Kt[(j*4+1)*128 + t] = kvv.y;
        Kt[(j*4+2)*128 + t] = kvv.z;
        Kt[(j*4+3)*128 + t] = kvv.w;
        *reinterpret_cast<float4*>(&Vs[t*64 + j*4]) = vv;
    }
    __syncthreads();

    const int nq = (Mc + Q_BLOCKS - 1) / Q_BLOCKS;
    int q0 = blockIdx.y * nq;
    int qend = min(q0 + nq, Mc);
    float* sqw = sq + warp*256;

    for (int qi0 = q0 + warp*4; qi0 < qend; qi0 += 32) {
        #pragma unroll
        for (int f = 0; f < 2; f++) {
            int ff = lane + f*32;
            int qq = ff >> 4, j = ff & 15;
            int qi = qi0 + qq;
            if (qi < qend) {
                float4 qv = *reinterpret_cast<const float4*>(q + ((size_t)b*Mc + qi)*Cc + h*64 + j*4);
                *reinterpret_cast<float4*>(&sqw[qq*64 + j*4]) = qv;
            }
        }
        __syncwarp();
        float s[4][4];
        #pragma unroll
        for (int qq=0;qq<4;qq++)
            #pragma unroll
            for (int j=0;j<4;j++) s[qq][j] = 0.f;
        #pragma unroll 4
        for (int d0 = 0; d0 < 64; d0 += 4) {
            float4 kk4[4];
            #pragma unroll
            for (int dd = 0; dd < 4; dd++)
                kk4[dd] = *reinterpret_cast<const float4*>(&Kt[(d0+dd)*128 + lane*4]);
            #pragma unroll
            for (int qq = 0; qq < 4; qq++) {
                float4 qd = *reinterpret_cast<const float4*>(&sqw[qq*64 + d0]);
                s[qq][0] += qd.x*kk4[0].x + qd.y*kk4[1].x + qd.z*kk4[2].x + qd.w*kk4[3].x;
                s[qq][1] += qd.x*kk4[0].y + qd.y*kk4[1].y + qd.z*kk4[2].y + qd.w*kk4[3].y;
                s[qq][2] += qd.x*kk4[0].z + qd.y*kk4[1].z + qd.z*kk4[2].z + qd.w*kk4[3].z;
                s[qq][3] += qd.x*kk4[0].w + qd.y*kk4[1].w + qd.z*kk4[2].w + qd.w*kk4[3].w;
            }
        }
        #pragma unroll
        for (int qq=0;qq<4;qq++)
            #pragma unroll
            for (int j=0;j<4;j++) s[qq][j] *= 0.125f;

        float thr[4], gmax[4], c[4];
        #pragma unroll
        for (int qq=0;qq<4;qq++)
            c[qq] = fmaxf(fmaxf(s[qq][0],s[qq][1]), fmaxf(s[qq][2],s[qq][3]));
        warpMax4(c);
        #pragma unroll
        for (int qq=0;qq<4;qq++){ gmax[qq] = c[qq]; thr[qq] = c[qq]; }
        #pragma unroll
        for (int it = 1; it < TOPK; it++) {
            #pragma unroll
            for (int qq=0;qq<4;qq++){
                float m = -F_INF;
                #pragma unroll
                for (int j=0;j<4;j++) m = fmaxf(m, (s[qq][j] < thr[qq]) ? s[qq][j] : -F_INF);
                c[qq] = m;
            }
            warpMax4(c);
            #pragma unroll
            for (int qq=0;qq<4;qq++) thr[qq] = c[qq];
        }
        float e[4][4], le[4];
        #pragma unroll
        for (int qq=0;qq<4;qq++){
            le[qq] = 0.f;
            #pragma unroll
            for (int j=0;j<4;j++){ e[qq][j] = __expf(s[qq][j] - gmax[qq]); le[qq] += e[qq][j]; }
        }
        warpSum4(le);

        int d0v = lane*2;
        #pragma unroll
        for (int qq = 0; qq < 4; qq++) {
            int qi = qi0 + qq;
            if (qi >= qend) break;
            float inv = 1.f / le[qq];
            float p[4];
            #pragma unroll
            for (int j=0;j<4;j++) p[j] = (s[qq][j] >= thr[qq]) ? e[qq][j]*inv : 0.f;
            float2 acc = make_float2(0.f, 0.f);
            #pragma unroll
            for (int j=0;j<4;j++) {
                unsigned msk = __ballot_sync(0xffffffffu, p[j] != 0.f);
                while (msk) {
                    int src = __ffs(msk) - 1;
                    msk &= msk - 1;
                    float pv = __shfl_sync(0xffffffffu, p[j], src);
                    int key = src*4 + j;
                    float2 vv = *reinterpret_cast<const float2*>(&Vs[key*64 + d0v]);
                    acc.x += pv*vv.x; acc.y += pv*vv.y;
                }
            }
            *reinterpret_cast<float2*>(o + ((size_t)b*Mc + qi)*Cc + h*64 + d0v) = acc;
        }
    }
}

// ============ hx attention ============
#define SMEM_HX ((64*128 + 128*64 + 32*64 + 8*4*128)*4)
__global__ __launch_bounds__(256) void attn_hx_kernel(
    const float* __restrict__ q, const float* __restrict__ kv,
    float* __restrict__ o)
{
    extern __shared__ float sm[];
    float* Kt = sm;
    float* Vs = Kt + 64*128;
    float* sq = Vs + 128*64;
    float* ps = sq + 32*64;

    int tid = threadIdx.x;
    int warp = tid >> 5, lane = tid & 31;
    int bh = blockIdx.x, b = bh / Hc, h = bh % Hc;
    int q0 = blockIdx.y * 32;

    for (int idx = tid; idx < 32*16; idx += 256) {
        int qi = idx >> 4, j = idx & 15;
        float4 qv = *reinterpret_cast<const float4*>(q + ((size_t)b*Tc + q0 + qi)*Cc + h*64 + j*4);
        *reinterpret_cast<float4*>(&sq[qi*64 + j*4]) = qv;
    }

    float m[4], den[4];
    float2 acc[4];
    #pragma unroll
    for (int i=0;i<4;i++){ m[i] = -F_INF; den[i] = 0.f; acc[i] = make_float2(0.f,0.f); }
    int d0v = lane*2;
    float* psw = ps + warp*512;

    for (int c0 = 0; c0 < Mc; c0 += 128) {
        int nk = min(128, Mc - c0);
        __syncthreads();
        for (int idx = tid; idx < 128*16; idx += 256) {
            int t = idx >> 4, j = idx & 15;
            float4 kvv = make_float4(0.f,0.f,0.f,0.f), vv = kvv;
            if (t < nk) {
                size_t row = ((size_t)b*Mc + c0 + t)*KVS + h*64 + j*4;
                kvv = *reinterpret_cast<const float4*>(kv + row);
                vv  = *reinterpret_cast<const float4*>(kv + row + Cc);
            }
            Kt[(j*4+0)*128 + t] = kvv.x;
            Kt[(j*4+1)*128 + t] = kvv.y;
            Kt[(j*4+2)*128 + t] = kvv.z;
            Kt[(j*4+3)*128 + t] = kvv.w;
            *reinterpret_cast<float4*>(&Vs[t*64 + j*4]) = vv;
        }
        __syncthreads();

        float s[4][4];
        #pragma unroll
        for (int i=0;i<4;i++)
            #pragma unroll
            for (int j=0;j<4;j++) s[i][j] = 0.f;
        #pragma unroll 4
        for (int d0 = 0; d0 < 64; d0 += 4) {
            float4 kk4[4];
            #pragma unroll
            for (int dd = 0; dd < 4; dd++)
                kk4[dd] = *reinterpret_cast<const float4*>(&Kt[(d0+dd)*128 + lane*4]);
            #pragma unroll
            for (int i = 0; i < 4; i++) {
                float4 qd = *reinterpret_cast<const float4*>(&sq[(warp*4+i)*64 + d0]);
                s[i][0] += qd.x*kk4[0].x + qd.y*kk4[1].x + qd.z*kk4[2].x + qd.w*kk4[3].x;
                s[i][1] += qd.x*kk4[0].y + qd.y*kk4[1].y + qd.z*kk4[2].y + qd.w*kk4[3].y;
                s[i][2] += qd.x*kk4[0].z + qd.y*kk4[1].z + qd.z*kk4[2].z + qd.w*kk4[3].z;
                s[i][3] += qd.x*kk4[0].w + qd.y*kk4[1].w + qd.z*kk4[2].w + qd.w*kk4[3].w;
            }
        }
        float lm[4];
        #pragma unroll
        for (int i = 0; i < 4; i++) {
            float mm = -F_INF;
            #pragma unroll
            for (int j=0;j<4;j++) {
                s[i][j] = (lane*4 + j < nk) ? s[i][j]*0.125f : -F_INF;
                mm = fmaxf(mm, s[i][j]);
            }
            lm[i] = mm;
        }
        warpMax4(lm);
        float f[4], le[4];
        #pragma unroll
        for (int i = 0; i < 4; i++) {
            float newm = fmaxf(m[i], lm[i]);
            f[i] = __expf(m[i] - newm);
            m[i] = newm;
            float e0 = __expf(s[i][0]-newm), e1 = __expf(s[i][1]-newm);
            float e2 = __expf(s[i][2]-newm), e3 = __expf(s[i][3]-newm);
            le[i] = e0+e1+e2+e3;
            *reinterpret_cast<float4*>(&psw[i*128 + lane*4]) = make_float4(e0,e1,e2,e3);
        }
        warpSum4(le);
        #pragma unroll
        for (int i = 0; i < 4; i++) {
            den[i] = den[i]*f[i] + le[i];
            acc[i].x *= f[i]; acc[i].y *= f[i];
        }
        __syncwarp();
        #pragma unroll 4
        for (int kk = 0; kk < 128; kk++) {
            float2 vv = *reinterpret_cast<const float2*>(&Vs[kk*64 + d0v]);
            float p0 = psw[0*128 + kk], p1 = psw[1*128 + kk];
            float p2 = psw[2*128 + kk], p3 = psw[3*128 + kk];
            acc[0].x += p0*vv.x; acc[0].y += p0*vv.y;
            acc[1].x += p1*vv.x; acc[1].y += p1*vv.y;
            acc[2].x += p2*vv.x; acc[2].y += p2*vv.y;
            acc[3].x += p3*vv.x; acc[3].y += p3*vv.y;
        }
    }
    #pragma unroll
    for (int i=0;i<4;i++) {
        int qi = q0 + warp*4 + i;
        float invd = 1.f / den[i];
        float2 ov = make_float2(acc[i].x*invd, acc[i].y*invd);
        *reinterpret_cast<float2*>(o + ((size_t)b*Tc + qi)*Cc + h*64 + d0v) = ov;
    }
}

// ============ add + layernorm (float + half outputs) ============
__global__ __launch_bounds__(256) void add_ln_kernel(
    const float* __restrict__ x, const float* __restrict__ r,
    const float* __restrict__ g, const float* __restrict__ bb,
    float* __restrict__ out, __half* __restrict__ outh, int nrows)
{
    int warp = (blockIdx.x * blockDim.x + threadIdx.x) >> 5;
    int lane = threadIdx.x & 31;
    if (warp >= nrows) return;
    const float* xr = x + (size_t)warp * Cc;
    const float* rr = r + (size_t)warp * Cc;
    float vals[16];
    float s = 0.f;
    #pragma unroll
    for (int i=0;i<16;i++) { float vv = xr[lane + i*32] + rr[lane + i*32]; vals[i] = vv; s += vv; }
    #pragma unroll
    for (int o2=16;o2;o2>>=1) s += __shfl_xor_sync(0xffffffffu, s, o2);
    float mu = s * (1.f/512.f);
    float vs = 0.f;
    #pragma unroll
    for (int i=0;i<16;i++){ float d = vals[i]-mu; vs += d*d; }
    #pragma unroll
    for (int o2=16;o2;o2>>=1) vs += __shfl_xor_sync(0xffffffffu, vs, o2);
    float rstd = rsqrtf(vs*(1.f/512.f) + 1e-5f);
    float* outr = out + (size_t)warp * Cc;
    __half* outhr = outh + (size_t)warp * Cc;
    #pragma unroll
    for (int i=0;i<16;i++){
        int cc = lane + i*32;
        float ov = (vals[i]-mu)*rstd*g[cc] + bb[cc];
        outr[cc] = ov;
        outhr[cc] = __float2half(ov);
    }
}

// ============ misc elementwise ============
__global__ void repmean_kernel(const float* __restrict__ inp, const float* __restrict__ rep_w,
                               float* __restrict__ out)
{
    int b = blockIdx.x, c = threadIdx.x;
    const float* base = inp + (size_t)b*Tc*Cc + c;
    float rw = rep_w[c];
    float s = 0.f;
    for (int t=0;t<Tc;t++) s += fmaxf(rw * base[(size_t)t*Cc], 0.f);
    out[b*Cc + c] = s * (1.f/Tc);
}

__global__ void gate_kernel(const float* __restrict__ gates, const float* __restrict__ gi,
                            const float* __restrict__ mem_final, const float* __restrict__ mem0,
                            const float* __restrict__ ib, const float* __restrict__ fb,
                            float* __restrict__ nm, __half* __restrict__ nmh)
{
    size_t n = (size_t)Bc*Mc*Cc;
    size_t i = (size_t)blockIdx.x*blockDim.x + threadIdx.x;
    size_t st = (size_t)gridDim.x*blockDim.x;
    float ibv = ib[0], fbv = fb[0];
    for (; i < n; i += st) {
        int c = (int)(i % Cc);
        size_t bm = i / Cc;
        int b = (int)(bm / Mc);
        float gI = gates[bm*2*Cc + c]      + gi[b*2*Cc + c]      + ibv;
        float gF = gates[bm*2*Cc + Cc + c] + gi[b*2*Cc + Cc + c] + fbv;
        float igv = 1.f/(1.f + __expf(-gI));
        float fgv = 1.f/(1.f + __expf(-gF));
        float ov = igv * tanhf(mem_final[i]) + fgv * mem0[i];
        nm[i] = ov;
        nmh[i] = __float2half(ov);
    }
}

// ============ launch ============
extern "C" void kernel_launch(void* const* d_in, const int* in_sizes, int n_in,
                              void* d_out, int out_size)
{
    const float* ipts   = (const float*)d_in[0];
    const float* memory = (const float*)d_in[1];
    const float* Wq=(const float*)d_in[2],  *bq=(const float*)d_in[3];
    const float* Wk=(const float*)d_in[4],  *bk=(const float*)d_in[5];
    const float* Wv=(const float*)d_in[6],  *bv=(const float*)d_in[7];
    const float* Wm=(const float*)d_in[8],  *bm=(const float*)d_in[9];
    const float* g1=(const float*)d_in[10], *b1=(const float*)d_in[11];
    const float* g2=(const float*)d_in[12], *b2=(const float*)d_in[13];
    const float* Wp=(const float*)d_in[14], *bp=(const float*)d_in[15];
    const float* rep_w=(const float*)d_in[16];
    const float* Wig=(const float*)d_in[17], *big=(const float*)d_in[18];
    const float* Wmg=(const float*)d_in[19], *bmg=(const float*)d_in[20];
    const float* fb=(const float*)d_in[21], *ib=(const float*)d_in[22];

    float* out_nm = (float*)d_out;
    float* out_hx = out_nm + (size_t)Bc*Mc*Cc;

    float *inp,*mem,*qb,*kvs,*ao,*h2,*gt,*rm,*gi,*bkv;
    __half *ipts_h,*inp_h,*mem_h,*h1_h,*tm_h,*nm_h;
    __half *WqT,*WkvT,*WmT,*WpT,*WmgT;
    cudaGetSymbolAddress((void**)&inp, d_inp);
    cudaGetSymbolAddress((void**)&mem, d_mem);
    cudaGetSymbolAddress((void**)&qb,  d_qb);
    cudaGetSymbolAddress((void**)&kvs, d_kvs);
    cudaGetSymbolAddress((void**)&ao,  d_ao);
    cudaGetSymbolAddress((void**)&h2,  d_h2);
    cudaGetSymbolAddress((void**)&gt,  d_gt);
    cudaGetSymbolAddress((void**)&rm,  d_rm);
    cudaGetSymbolAddress((void**)&gi,  d_gi);
    cudaGetSymbolAddress((void**)&bkv, d_bkv);
    cudaGetSymbolAddress((void**)&ipts_h, d_ipts_h);
    cudaGetSymbolAddress((void**)&inp_h,  d_inp_h);
    cudaGetSymbolAddress((void**)&mem_h,  d_mem_h);
    cudaGetSymbolAddress((void**)&h1_h,   d_h1_h);
    cudaGetSymbolAddress((void**)&tm_h,   d_tm_h);
    cudaGetSymbolAddress((void**)&nm_h,   d_nm_h);
    cudaGetSymbolAddress((void**)&WqT, d_WqT);
    cudaGetSymbolAddress((void**)&WkvT, d_WkvT);
    cudaGetSymbolAddress((void**)&WmT, d_WmT);
    cudaGetSymbolAddress((void**)&WpT, d_WpT);
    cudaGetSymbolAddress((void**)&WmgT, d_WmgT);

    cudaFuncSetAttribute(attn_topk_kernel, cudaFuncAttributeMaxDynamicSharedMemorySize, SMEM_TOPK);
    cudaFuncSetAttribute(attn_hx_kernel,   cudaFuncAttributeMaxDynamicSharedMemorySize, SMEM_HX);
    cudaFuncSetAttribute(f16_gemm_kernel,  cudaFuncAttributeMaxDynamicSharedMemorySize, TG_SMEM);

    TPack tp;
    tp.in[0]=Wq;  tp.out[0]=WqT;           tp.C[0]=Cc;
    tp.in[1]=Wk;  tp.out[1]=WkvT;          tp.C[1]=Cc;
    tp.in[2]=Wv;  tp.out[2]=WkvT + Cc*Cc;  tp.C[2]=Cc;
    tp.in[3]=Wm;  tp.out[3]=WmT;           tp.C[3]=Cc;
    tp.in[4]=Wp;  tp.out[4]=WpT;           tp.C[4]=Cc;
    tp.in[5]=Wmg; tp.out[5]=WmgT;          tp.C[5]=2*Cc;
    tp.bk = bk; tp.bv = bv; tp.bkv = bkv;
    transpose_all_kernel<<<dim3(32,16,6), 256>>>(tp);
    convert_pre_kernel<<<2048, 256>>>(ipts, memory, ipts_h, mem_h, tm_h);
    cudaMemcpyAsync(mem, memory, sizeof(float)*(size_t)Bc*Mc*Cc, cudaMemcpyDeviceToDevice);

    auto tgemm = [&](const __half* A, const __half* WT, const float* bias,
                     float* of, __half* oh, int N, int NO, int relu){
        f16_gemm_kernel<<<dim3(NO/128, (N+127)/128), 256, TG_SMEM>>>(
            A, WT, bias, of, oh, N, Cc, NO, relu);
    };

    // inp = ipts @ Wp + bp (float + half); fused k|v from inp_h
    tgemm(ipts_h, WpT, bp, inp, inp_h, Bc*Tc, Cc, 0);
    tgemm(inp_h, WkvT, bkv, kvs, nullptr, Bc*Tc, KVS, 0);

    for (int blk = 0; blk < NBLK; blk++) {
        tgemm(mem_h, WqT, bq, qb, nullptr, Bc*Mc, Cc, 0);
        attn_topk_kernel<<<dim3(Bc*Hc, Q_BLOCKS), 256, SMEM_TOPK>>>(qb, kvs, ao);
        add_ln_kernel<<<(Bc*Mc + 7)/8, 256>>>(mem, ao, g1, b1, mem, mem_h, Bc*Mc);
        tgemm(mem_h, WmT, bm, nullptr, h1_h, Bc*Mc, Cc, 1);
        tgemm(h1_h,  WmT, bm, h2, nullptr, Bc*Mc, Cc, 1);
        add_ln_kernel<<<(Bc*Mc + 7)/8, 256>>>(mem, h2, g2, b2, mem, mem_h, Bc*Mc);
    }

    // gates
    repmean_kernel<<<Bc, Cc>>>(inp, rep_w, rm);
    gemm_kernel<<<dim3(2*Cc/64, 1), 256>>>(rm, Wig, big, gi, Bc, Cc, 2*Cc, 0);
    tgemm(tm_h, WmgT, bmg, gt, nullptr, Bc*Mc, 2*Cc, 0);
    gate_kernel<<<2048, 256>>>(gt, gi, mem, memory, ib, fb, out_nm, nm_h);

    // hx
    tgemm(inp_h, WqT, bq, qb, nullptr, Bc*Tc, Cc, 0);
    tgemm(nm_h, WkvT, bkv, gt, nullptr, Bc*Mc, KVS, 0);
    attn_hx_kernel<<<dim3(Bc*Hc, Tc/32), 256, SMEM_HX>>>(qb, gt, out_hx);
}